// round 2
// baseline (speedup 1.0000x reference)
#include <cuda_runtime.h>
#include <math.h>

#define Bn 2
#define Sn 2048
#define Dn 2048
#define Hn 16
#define DHn 128
#define DRn 64
#define DCKVn 512
#define DCQn 1536
#define Mn (Bn*Sn)   // 4096 rows for every GEMM

// ---------------- scratch (device globals; no allocation allowed) ----------------
__device__ float g_kvc [(size_t)Mn*DCKVn];
__device__ float g_qc  [(size_t)Mn*DCQn];
__device__ float g_kcnt[(size_t)Mn*Hn*DHn];
__device__ float g_v   [(size_t)Mn*Hn*DHn];
__device__ float g_qcnt[(size_t)Mn*Hn*DHn];
__device__ float g_kr  [(size_t)Mn*Hn*DRn];
__device__ float g_qr  [(size_t)Mn*Hn*DRn];
__device__ float g_attn[(size_t)Mn*Hn*DHn];

// ---------------- generic C[M,N] = A[M,K] @ W[N,K]^T + bias ----------------
__global__ __launch_bounds__(256) void gemm_bias_kernel(
    const float* __restrict__ A, const float* __restrict__ W,
    const float* __restrict__ bias, float* __restrict__ C,
    int M, int N, int K)
{
    __shared__ float As[8][132];
    __shared__ float Bs[8][132];
    const int tid = threadIdx.x;
    const int tx = tid & 15, ty = tid >> 4;
    const int m0 = blockIdx.y << 7, n0 = blockIdx.x << 7;
    const int lr = tid >> 1;              // 0..127 row within tile
    const int lk = (tid & 1) << 2;        // 0 or 4
    const float* Ap = A + (size_t)(m0 + lr) * K + lk;
    const float* Wp = W + (size_t)(n0 + lr) * K + lk;

    float acc[8][8];
#pragma unroll
    for (int i = 0; i < 8; i++)
#pragma unroll
        for (int j = 0; j < 8; j++) acc[i][j] = 0.f;

    for (int k0 = 0; k0 < K; k0 += 8) {
        float4 av = *(const float4*)(Ap + k0);
        float4 wv = *(const float4*)(Wp + k0);
        __syncthreads();
        As[lk+0][lr] = av.x; As[lk+1][lr] = av.y; As[lk+2][lr] = av.z; As[lk+3][lr] = av.w;
        Bs[lk+0][lr] = wv.x; Bs[lk+1][lr] = wv.y; Bs[lk+2][lr] = wv.z; Bs[lk+3][lr] = wv.w;
        __syncthreads();
#pragma unroll
        for (int kk = 0; kk < 8; kk++) {
            float a[8], b[8];
            *(float4*)(a  ) = *(const float4*)(&As[kk][ty*8]);
            *(float4*)(a+4) = *(const float4*)(&As[kk][ty*8+4]);
            *(float4*)(b  ) = *(const float4*)(&Bs[kk][tx*8]);
            *(float4*)(b+4) = *(const float4*)(&Bs[kk][tx*8+4]);
#pragma unroll
            for (int i = 0; i < 8; i++)
#pragma unroll
                for (int j = 0; j < 8; j++)
                    acc[i][j] = fmaf(a[i], b[j], acc[i][j]);
        }
    }

    float bv[8];
    *(float4*)(bv  ) = *(const float4*)(bias + n0 + tx*8);
    *(float4*)(bv+4) = *(const float4*)(bias + n0 + tx*8 + 4);
#pragma unroll
    for (int i = 0; i < 8; i++) {
        float* Cp = C + (size_t)(m0 + ty*8 + i) * N + n0 + tx*8;
        float4 o0 = make_float4(acc[i][0]+bv[0], acc[i][1]+bv[1], acc[i][2]+bv[2], acc[i][3]+bv[3]);
        float4 o1 = make_float4(acc[i][4]+bv[4], acc[i][5]+bv[5], acc[i][6]+bv[6], acc[i][7]+bv[7]);
        *(float4*)(Cp    ) = o0;
        *(float4*)(Cp + 4) = o1;
    }
}

// ---------------- rotate-half RoPE, in place on t: [B,S,H,DR] ----------------
__global__ void rope_kernel(float* __restrict__ t, int total)
{
    int idx = blockIdx.x * blockDim.x + threadIdx.x;
    if (idx >= total) return;
    int j   = idx & 31;            // 0..DR/2-1
    int rem = idx >> 5;            // (b*S+s)*H + h
    int bs  = rem >> 4;            // b*S+s   (H=16)
    int s   = bs & (Sn - 1);
    float inv_freq = 1.0f / powf(10000.0f, (float)(2 * j) / (float)DRn);
    float ang = (float)s * inv_freq;
    float sv, cv;
    sincosf(ang, &sv, &cv);
    float* p = t + (size_t)rem * DRn;
    float t1 = p[j], t2 = p[j + 32];
    p[j]      = t1 * cv - t2 * sv;
    p[j + 32] = t2 * cv + t1 * sv;
}

// ---------------- causal flash attention, fp32, GEMM-style microkernel ----------------
// grid (S/128, B*H). BM=128 queries, BN=64 keys per tile, 256 threads.
// Q staged once transposed [k][m]; K streamed in BK=8 chunks; P staged transposed [n][m].
#define AT_QS 132           // m-stride for Qs (128 + 4, keeps float4 alignment, derotates banks)
#define AT_KS 68            // row-stride for K chunk (64 + 4)
#define AT_PS 132           // m-stride for Ps
#define ATTN_SMEM ((192*AT_QS + 8*AT_KS + 64*128 + 64*AT_PS) * 4)

__global__ __launch_bounds__(256) void attn_kernel(
    const float* __restrict__ qcnt, const float* __restrict__ qr,
    const float* __restrict__ kcnt, const float* __restrict__ kr,
    const float* __restrict__ v, float* __restrict__ outp)
{
    extern __shared__ float sm[];
    float* Qs = sm;                     // [192][AT_QS] transposed Q
    float* Ks = Qs + 192 * AT_QS;       // [8][AT_KS] transposed K chunk
    float* Vs = Ks + 8 * AT_KS;         // [64][128]
    float* Ps = Vs + 64 * 128;          // [64][AT_PS] transposed P

    const int tid = threadIdx.x;
    const int tx = tid & 15, ty = tid >> 4;
    const int qb = blockIdx.x;
    const int b  = blockIdx.y >> 4;     // H = 16
    const int h  = blockIdx.y & 15;
    const int q0 = qb * 128;
    const float scale = rsqrtf((float)(DHn + DRn));

    // ---- stage Q transposed [k][m], prescaled (once) ----
    {
        const int lr = tid >> 1;        // 0..127 (query row)
        const int lk = (tid & 1) << 2;  // 0 or 4
        const float* qc_row = qcnt + (size_t)(b*Sn + q0 + lr) * (Hn*DHn) + h*DHn;
        const float* qr_row = qr   + (size_t)(b*Sn + q0 + lr) * (Hn*DRn) + h*DRn;
#pragma unroll
        for (int c0 = 0; c0 < 192; c0 += 8) {
            int k = c0 + lk;
            float4 qv = (k < 128) ? *(const float4*)(qc_row + k)
                                  : *(const float4*)(qr_row + (k - 128));
            Qs[(k+0)*AT_QS + lr] = qv.x * scale;
            Qs[(k+1)*AT_QS + lr] = qv.y * scale;
            Qs[(k+2)*AT_QS + lr] = qv.z * scale;
            Qs[(k+3)*AT_QS + lr] = qv.w * scale;
        }
    }

    float mrow[8], lrow[8], acc[8][8];
#pragma unroll
    for (int i = 0; i < 8; i++) {
        mrow[i] = -3.0e38f; lrow[i] = 0.f;
#pragma unroll
        for (int j = 0; j < 8; j++) acc[i][j] = 0.f;
    }

    const int klr = tid >> 1;           // 0..127 -> rows 0..63 for tid<128
    const int klk = (tid & 1) << 2;     // 0 or 4
    const int kb_end = 2*qb + 1;

    for (int kb = 0; kb <= kb_end; kb++) {
        const int k0r = kb * 64;
        __syncthreads();                 // prev iter's Ps/Vs readers done

        // stage V [64][128] (coalesced, no transpose)
        for (int idx = tid; idx < 64*32; idx += 256) {
            int r = idx >> 5, c4 = idx & 31;
            *(float4*)(Vs + r*128 + c4*4) =
                *(const float4*)(v + (size_t)(b*Sn + k0r + r)*(Hn*DHn) + h*DHn + c4*4);
        }

        float s[8][4];
#pragma unroll
        for (int i = 0; i < 8; i++)
#pragma unroll
            for (int j = 0; j < 4; j++) s[i][j] = 0.f;

        const float* kc_row = kcnt + (size_t)(b*Sn + k0r + (klr & 63))*(Hn*DHn) + h*DHn;
        const float* kr_row = kr   + (size_t)(b*Sn + k0r + (klr & 63))*(Hn*DRn) + h*DRn;

        // ---- QK^T: stream K in BK=8 chunks ----
        for (int c0 = 0; c0 < 192; c0 += 8) {
            float4 kv = make_float4(0.f, 0.f, 0.f, 0.f);
            if (tid < 128) {
                int k = c0 + klk;
                kv = (k < 128) ? *(const float4*)(kc_row + k)
                               : *(const float4*)(kr_row + (k - 128));
            }
            __syncthreads();             // prev chunk's readers done
            if (tid < 128) {
                Ks[(klk+0)*AT_KS + klr] = kv.x;
                Ks[(klk+1)*AT_KS + klr] = kv.y;
                Ks[(klk+2)*AT_KS + klr] = kv.z;
                Ks[(klk+3)*AT_KS + klr] = kv.w;
            }
            __syncthreads();
#pragma unroll
            for (int kk = 0; kk < 8; kk++) {
                float a[8], bq[4];
                *(float4*)(a  ) = *(const float4*)(&Qs[(c0+kk)*AT_QS + ty*8]);
                *(float4*)(a+4) = *(const float4*)(&Qs[(c0+kk)*AT_QS + ty*8 + 4]);
                *(float4*)(bq ) = *(const float4*)(&Ks[kk*AT_KS + tx*4]);
#pragma unroll
                for (int i = 0; i < 8; i++)
#pragma unroll
                    for (int j = 0; j < 4; j++)
                        s[i][j] = fmaf(a[i], bq[j], s[i][j]);
            }
        }

        // ---- causal mask (only last two tiles) ----
        if (k0r + 63 > q0) {
#pragma unroll
            for (int i = 0; i < 8; i++)
#pragma unroll
                for (int j = 0; j < 4; j++)
                    if (k0r + tx*4 + j > q0 + ty*8 + i) s[i][j] = -1e9f;
        }

        // ---- online softmax; write P transposed [n][m] ----
#pragma unroll
        for (int i = 0; i < 8; i++) {
            float rmax = fmaxf(fmaxf(s[i][0], s[i][1]), fmaxf(s[i][2], s[i][3]));
#pragma unroll
            for (int off = 8; off >= 1; off >>= 1)
                rmax = fmaxf(rmax, __shfl_xor_sync(0xffffffffu, rmax, off, 16));
            float mn = fmaxf(mrow[i], rmax);
            float alpha = __expf(mrow[i] - mn);
            float rs = 0.f;
#pragma unroll
            for (int j = 0; j < 4; j++) { s[i][j] = __expf(s[i][j] - mn); rs += s[i][j]; }
#pragma unroll
            for (int off = 8; off >= 1; off >>= 1)
                rs += __shfl_xor_sync(0xffffffffu, rs, off, 16);
            lrow[i] = lrow[i] * alpha + rs;
            mrow[i] = mn;
#pragma unroll
            for (int j = 0; j < 8; j++) acc[i][j] *= alpha;
#pragma unroll
            for (int j = 0; j < 4; j++)
                Ps[(tx*4 + j)*AT_PS + ty*8 + i] = s[i][j];
        }
        __syncthreads();

        // ---- PV: acc[128][128] += P^T-read [c][m] * V [c][dv] ----
#pragma unroll 2
        for (int c = 0; c < 64; c++) {
            float p[8], vv[8];
            *(float4*)(p  ) = *(const float4*)(&Ps[c*AT_PS + ty*8]);
            *(float4*)(p+4) = *(const float4*)(&Ps[c*AT_PS + ty*8 + 4]);
            *(float4*)(vv  ) = *(const float4*)(&Vs[c*128 + tx*8]);
            *(float4*)(vv+4) = *(const float4*)(&Vs[c*128 + tx*8 + 4]);
#pragma unroll
            for (int i = 0; i < 8; i++)
#pragma unroll
                for (int j = 0; j < 8; j++)
                    acc[i][j] = fmaf(p[i], vv[j], acc[i][j]);
        }
    }

    // ---- epilogue ----
#pragma unroll
    for (int i = 0; i < 8; i++) {
        float inv = 1.0f / lrow[i];
        float* op = outp + (size_t)(b*Sn + q0 + ty*8 + i)*(Hn*DHn) + h*DHn + tx*8;
        float4 o0 = make_float4(acc[i][0]*inv, acc[i][1]*inv, acc[i][2]*inv, acc[i][3]*inv);
        float4 o1 = make_float4(acc[i][4]*inv, acc[i][5]*inv, acc[i][6]*inv, acc[i][7]*inv);
        *(float4*)(op    ) = o0;
        *(float4*)(op + 4) = o1;
    }
}

// ---------------- launch ----------------
extern "C" void kernel_launch(void* const* d_in, const int* in_sizes, int n_in,
                              void* d_out, int out_size)
{
    const float* x   = (const float*)d_in[0];
    const float* Wkd = (const float*)d_in[1];
    const float* bkd = (const float*)d_in[2];
    const float* Wqd = (const float*)d_in[3];
    const float* bqd = (const float*)d_in[4];
    const float* Wku = (const float*)d_in[5];
    const float* bku = (const float*)d_in[6];
    const float* Wvu = (const float*)d_in[7];
    const float* bvu = (const float*)d_in[8];
    const float* Wqu = (const float*)d_in[9];
    const float* bqu = (const float*)d_in[10];
    const float* Wkr = (const float*)d_in[11];
    const float* bkr = (const float*)d_in[12];
    const float* Wqr = (const float*)d_in[13];
    const float* bqr = (const float*)d_in[14];
    const float* Wo  = (const float*)d_in[15];
    const float* bo  = (const float*)d_in[16];

    float *kvc, *qc, *kcnt, *vv, *qcnt, *kr, *qr, *attn;
    cudaGetSymbolAddress((void**)&kvc,  g_kvc);
    cudaGetSymbolAddress((void**)&qc,   g_qc);
    cudaGetSymbolAddress((void**)&kcnt, g_kcnt);
    cudaGetSymbolAddress((void**)&vv,   g_v);
    cudaGetSymbolAddress((void**)&qcnt, g_qcnt);
    cudaGetSymbolAddress((void**)&kr,   g_kr);
    cudaGetSymbolAddress((void**)&qr,   g_qr);
    cudaGetSymbolAddress((void**)&attn, g_attn);

    dim3 thr(256);
    // compress
    gemm_bias_kernel<<<dim3(DCKVn/128, Mn/128), thr>>>(x,  Wkd, bkd, kvc,  Mn, DCKVn, Dn);
    gemm_bias_kernel<<<dim3(DCQn /128, Mn/128), thr>>>(x,  Wqd, bqd, qc,   Mn, DCQn,  Dn);
    // up-project
    gemm_bias_kernel<<<dim3((Hn*DHn)/128, Mn/128), thr>>>(kvc, Wku, bku, kcnt, Mn, Hn*DHn, DCKVn);
    gemm_bias_kernel<<<dim3((Hn*DHn)/128, Mn/128), thr>>>(kvc, Wvu, bvu, vv,   Mn, Hn*DHn, DCKVn);
    gemm_bias_kernel<<<dim3((Hn*DHn)/128, Mn/128), thr>>>(qc,  Wqu, bqu, qcnt, Mn, Hn*DHn, DCQn);
    gemm_bias_kernel<<<dim3((Hn*DRn)/128, Mn/128), thr>>>(x,   Wkr, bkr, kr,   Mn, Hn*DRn, Dn);
    gemm_bias_kernel<<<dim3((Hn*DRn)/128, Mn/128), thr>>>(qc,  Wqr, bqr, qr,   Mn, Hn*DRn, DCQn);
    // rope (in place)
    int rope_total = Mn * Hn * (DRn / 2);
    rope_kernel<<<(rope_total + 255) / 256, 256>>>(kr, rope_total);
    rope_kernel<<<(rope_total + 255) / 256, 256>>>(qr, rope_total);
    // attention
    cudaFuncSetAttribute(attn_kernel, cudaFuncAttributeMaxDynamicSharedMemorySize, ATTN_SMEM);
    attn_kernel<<<dim3(Sn/128, Bn*Hn), thr, ATTN_SMEM>>>(qcnt, qr, kcnt, kr, vv, attn);
    // output projection
    gemm_bias_kernel<<<dim3(Dn/128, Mn/128), thr>>>(attn, Wo, bo, (float*)d_out, Mn, Dn, Dn);
}

// round 5
// speedup vs baseline: 1.8412x; 1.8412x over previous
#include <cuda_runtime.h>
#include <math.h>

#define Bn 2
#define Sn 2048
#define Dn 2048
#define Hn 16
#define DHn 128
#define DRn 64
#define DCKVn 512
#define DCQn 1536
#define Mn (Bn*Sn)   // 4096 rows for every GEMM

// ---------------- scratch (device globals; no allocation allowed) ----------------
__device__ float g_kvc [(size_t)Mn*DCKVn];
__device__ float g_qc  [(size_t)Mn*DCQn];
__device__ float g_kcnt[(size_t)Mn*Hn*DHn];
__device__ float g_v   [(size_t)Mn*Hn*DHn];
__device__ float g_qcnt[(size_t)Mn*Hn*DHn];
__device__ float g_kr  [(size_t)Mn*Hn*DRn];
__device__ float g_qr  [(size_t)Mn*Hn*DRn];
__device__ float g_attn[(size_t)Mn*Hn*DHn];

// ---------------- generic C[M,N] = A[M,K] @ W[N,K]^T + bias ----------------
__global__ __launch_bounds__(256) void gemm_bias_kernel(
    const float* __restrict__ A, const float* __restrict__ W,
    const float* __restrict__ bias, float* __restrict__ C,
    int M, int N, int K)
{
    __shared__ float As[8][132];
    __shared__ float Bs[8][132];
    const int tid = threadIdx.x;
    const int tx = tid & 15, ty = tid >> 4;
    const int m0 = blockIdx.y << 7, n0 = blockIdx.x << 7;
    const int lr = tid >> 1;              // 0..127 row within tile
    const int lk = (tid & 1) << 2;        // 0 or 4
    const float* Ap = A + (size_t)(m0 + lr) * K + lk;
    const float* Wp = W + (size_t)(n0 + lr) * K + lk;

    float acc[8][8];
#pragma unroll
    for (int i = 0; i < 8; i++)
#pragma unroll
        for (int j = 0; j < 8; j++) acc[i][j] = 0.f;

    for (int k0 = 0; k0 < K; k0 += 8) {
        float4 av = *(const float4*)(Ap + k0);
        float4 wv = *(const float4*)(Wp + k0);
        __syncthreads();
        As[lk+0][lr] = av.x; As[lk+1][lr] = av.y; As[lk+2][lr] = av.z; As[lk+3][lr] = av.w;
        Bs[lk+0][lr] = wv.x; Bs[lk+1][lr] = wv.y; Bs[lk+2][lr] = wv.z; Bs[lk+3][lr] = wv.w;
        __syncthreads();
#pragma unroll
        for (int kk = 0; kk < 8; kk++) {
            float a[8], b[8];
            *(float4*)(a  ) = *(const float4*)(&As[kk][ty*8]);
            *(float4*)(a+4) = *(const float4*)(&As[kk][ty*8+4]);
            *(float4*)(b  ) = *(const float4*)(&Bs[kk][tx*8]);
            *(float4*)(b+4) = *(const float4*)(&Bs[kk][tx*8+4]);
#pragma unroll
            for (int i = 0; i < 8; i++)
#pragma unroll
                for (int j = 0; j < 8; j++)
                    acc[i][j] = fmaf(a[i], b[j], acc[i][j]);
        }
    }

    float bv[8];
    *(float4*)(bv  ) = *(const float4*)(bias + n0 + tx*8);
    *(float4*)(bv+4) = *(const float4*)(bias + n0 + tx*8 + 4);
#pragma unroll
    for (int i = 0; i < 8; i++) {
        float* Cp = C + (size_t)(m0 + ty*8 + i) * N + n0 + tx*8;
        float4 o0 = make_float4(acc[i][0]+bv[0], acc[i][1]+bv[1], acc[i][2]+bv[2], acc[i][3]+bv[3]);
        float4 o1 = make_float4(acc[i][4]+bv[4], acc[i][5]+bv[5], acc[i][6]+bv[6], acc[i][7]+bv[7]);
        *(float4*)(Cp    ) = o0;
        *(float4*)(Cp + 4) = o1;
    }
}

// ---------------- rotate-half RoPE, in place on t: [B,S,H,DR] ----------------
__global__ void rope_kernel(float* __restrict__ t, int total)
{
    int idx = blockIdx.x * blockDim.x + threadIdx.x;
    if (idx >= total) return;
    int j   = idx & 31;            // 0..DR/2-1
    int rem = idx >> 5;            // (b*S+s)*H + h
    int bs  = rem >> 4;            // b*S+s   (H=16)
    int s   = bs & (Sn - 1);
    float inv_freq = 1.0f / powf(10000.0f, (float)(2 * j) / (float)DRn);
    float ang = (float)s * inv_freq;
    float sv, cv;
    sincosf(ang, &sv, &cv);
    float* p = t + (size_t)rem * DRn;
    float t1 = p[j], t2 = p[j + 32];
    p[j]      = t1 * cv - t2 * sv;
    p[j + 32] = t2 * cv + t1 * sv;
}

// ---------------- causal flash attention, fp32 ----------------
// grid (B*H, S/128). BM=128 queries, BN=64 keys, 256 threads, 8x4 / 8x8 microtiles.
// Full K tile staged transposed [192][68]; P buffer UNIONed onto K buffer.
// Only 4 __syncthreads per key-tile.
#define AT_QS 132           // m-stride for Qs (128 + 4)
#define AT_KS 68            // m-stride for Ks rows (64 + 4)
#define AT_PS 132           // m-stride for Ps
#define AT_QS_F (192*AT_QS) // 25344 floats
#define AT_KS_F (192*AT_KS) // 13056 floats (>= 64*AT_PS = 8448, so P fits in union)
#define ATTN_SMEM ((AT_QS_F + AT_KS_F + 64*128) * 4)

__global__ __launch_bounds__(256) void attn_kernel(
    const float* __restrict__ qcnt, const float* __restrict__ qr,
    const float* __restrict__ kcnt, const float* __restrict__ kr,
    const float* __restrict__ v, float* __restrict__ outp)
{
    extern __shared__ float sm[];
    float* Qs = sm;                     // [192][AT_QS] transposed Q
    float* Ks = Qs + AT_QS_F;           // [192][AT_KS] transposed K tile
    float* Ps = Ks;                     // [64][AT_PS]  (alias; K dead when P live)
    float* Vs = Ks + AT_KS_F;           // [64][128]

    const int tid = threadIdx.x;
    const int tx = tid & 15, ty = tid >> 4;
    const int b  = blockIdx.x >> 4;     // H = 16
    const int h  = blockIdx.x & 15;
    const int qb = (gridDim.y - 1) - blockIdx.y;   // heaviest q-blocks first
    const int q0 = qb * 128;
    const float scale = rsqrtf((float)(DHn + DRn));

    // ---- stage Q transposed [k][m], prescaled (once) ----
    {
        const int lr = tid >> 1;        // 0..127 (query row)
        const int lk = (tid & 1) << 2;  // 0 or 4
        const float* qc_row = qcnt + (size_t)(b*Sn + q0 + lr) * (Hn*DHn) + h*DHn;
        const float* qr_row = qr   + (size_t)(b*Sn + q0 + lr) * (Hn*DRn) + h*DRn;
#pragma unroll
        for (int c0 = 0; c0 < 192; c0 += 8) {
            int k = c0 + lk;
            float4 qv = (k < 128) ? *(const float4*)(qc_row + k)
                                  : *(const float4*)(qr_row + (k - 128));
            Qs[(k+0)*AT_QS + lr] = qv.x * scale;
            Qs[(k+1)*AT_QS + lr] = qv.y * scale;
            Qs[(k+2)*AT_QS + lr] = qv.z * scale;
            Qs[(k+3)*AT_QS + lr] = qv.w * scale;
        }
    }

    float mrow[8], lrow[8], acc[8][8];
#pragma unroll
    for (int i = 0; i < 8; i++) {
        mrow[i] = -3.0e38f; lrow[i] = 0.f;
#pragma unroll
        for (int j = 0; j < 8; j++) acc[i][j] = 0.f;
    }

    const int kb_end = 2*qb + 1;

    for (int kb = 0; kb <= kb_end; kb++) {
        const int k0r = kb * 64;
        __syncthreads();   // prev iter's Ps (=Ks) / Vs readers done; Qs stage done (kb=0)

        // ---- stage K transposed [k][n] ----
        for (int idx = tid; idx < 64*48; idx += 256) {
            int r = idx / 48, c4 = idx % 48, k = c4 * 4;
            float4 kv;
            if (k < 128)
                kv = *(const float4*)(kcnt + (size_t)(b*Sn + k0r + r)*(Hn*DHn) + h*DHn + k);
            else
                kv = *(const float4*)(kr   + (size_t)(b*Sn + k0r + r)*(Hn*DRn) + h*DRn + (k-128));
            Ks[(k+0)*AT_KS + r] = kv.x;
            Ks[(k+1)*AT_KS + r] = kv.y;
            Ks[(k+2)*AT_KS + r] = kv.z;
            Ks[(k+3)*AT_KS + r] = kv.w;
        }
        // ---- stage V [64][128] ----
        for (int idx = tid; idx < 64*32; idx += 256) {
            int r = idx >> 5, c4 = idx & 31;
            *(float4*)(Vs + r*128 + c4*4) =
                *(const float4*)(v + (size_t)(b*Sn + k0r + r)*(Hn*DHn) + h*DHn + c4*4);
        }
        __syncthreads();

        // ---- QK^T: 8x4 microtile, 3 LDS.128 per 32 FMA, no barriers ----
        float s[8][4];
#pragma unroll
        for (int i = 0; i < 8; i++)
#pragma unroll
            for (int j = 0; j < 4; j++) s[i][j] = 0.f;

#pragma unroll 4
        for (int k = 0; k < 192; k++) {
            float a[8], bq[4];
            *(float4*)(a  ) = *(const float4*)(&Qs[k*AT_QS + ty*8]);
            *(float4*)(a+4) = *(const float4*)(&Qs[k*AT_QS + ty*8 + 4]);
            *(float4*)(bq ) = *(const float4*)(&Ks[k*AT_KS + tx*4]);
#pragma unroll
            for (int i = 0; i < 8; i++)
#pragma unroll
                for (int j = 0; j < 4; j++)
                    s[i][j] = fmaf(a[i], bq[j], s[i][j]);
        }
        __syncthreads();   // all Ks reads done before Ps writes (alias)

        // ---- causal mask (only the last two tiles can cross the diagonal) ----
        if (k0r + 63 > q0) {
#pragma unroll
            for (int i = 0; i < 8; i++)
#pragma unroll
                for (int j = 0; j < 4; j++)
                    if (k0r + tx*4 + j > q0 + ty*8 + i) s[i][j] = -1e9f;
        }

        // ---- online softmax; write P transposed [n][m] ----
#pragma unroll
        for (int i = 0; i < 8; i++) {
            float rmax = fmaxf(fmaxf(s[i][0], s[i][1]), fmaxf(s[i][2], s[i][3]));
#pragma unroll
            for (int off = 8; off >= 1; off >>= 1)
                rmax = fmaxf(rmax, __shfl_xor_sync(0xffffffffu, rmax, off, 16));
            float mn = fmaxf(mrow[i], rmax);
            float alpha = __expf(mrow[i] - mn);
            float rs = 0.f;
#pragma unroll
            for (int j = 0; j < 4; j++) { s[i][j] = __expf(s[i][j] - mn); rs += s[i][j]; }
#pragma unroll
            for (int off = 8; off >= 1; off >>= 1)
                rs += __shfl_xor_sync(0xffffffffu, rs, off, 16);
            lrow[i] = lrow[i] * alpha + rs;
            mrow[i] = mn;
#pragma unroll
            for (int j = 0; j < 8; j++) acc[i][j] *= alpha;
#pragma unroll
            for (int j = 0; j < 4; j++)
                Ps[(tx*4 + j)*AT_PS + ty*8 + i] = s[i][j];
        }
        __syncthreads();

        // ---- PV: 8x8 microtile, 4 LDS.128 per 64 FMA ----
#pragma unroll 2
        for (int c = 0; c < 64; c++) {
            float p[8], vv[8];
            *(float4*)(p  ) = *(const float4*)(&Ps[c*AT_PS + ty*8]);
            *(float4*)(p+4) = *(const float4*)(&Ps[c*AT_PS + ty*8 + 4]);
            *(float4*)(vv  ) = *(const float4*)(&Vs[c*128 + tx*8]);
            *(float4*)(vv+4) = *(const float4*)(&Vs[c*128 + tx*8 + 4]);
#pragma unroll
            for (int i = 0; i < 8; i++)
#pragma unroll
                for (int j = 0; j < 8; j++)
                    acc[i][j] = fmaf(p[i], vv[j], acc[i][j]);
        }
    }

    // ---- epilogue ----
#pragma unroll
    for (int i = 0; i < 8; i++) {
        float inv = 1.0f / lrow[i];
        float* op = outp + (size_t)(b*Sn + q0 + ty*8 + i)*(Hn*DHn) + h*DHn + tx*8;
        float4 o0 = make_float4(acc[i][0]*inv, acc[i][1]*inv, acc[i][2]*inv, acc[i][3]*inv);
        float4 o1 = make_float4(acc[i][4]*inv, acc[i][5]*inv, acc[i][6]*inv, acc[i][7]*inv);
        *(float4*)(op    ) = o0;
        *(float4*)(op + 4) = o1;
    }
}

// ---------------- launch ----------------
extern "C" void kernel_launch(void* const* d_in, const int* in_sizes, int n_in,
                              void* d_out, int out_size)
{
    const float* x   = (const float*)d_in[0];
    const float* Wkd = (const float*)d_in[1];
    const float* bkd = (const float*)d_in[2];
    const float* Wqd = (const float*)d_in[3];
    const float* bqd = (const float*)d_in[4];
    const float* Wku = (const float*)d_in[5];
    const float* bku = (const float*)d_in[6];
    const float* Wvu = (const float*)d_in[7];
    const float* bvu = (const float*)d_in[8];
    const float* Wqu = (const float*)d_in[9];
    const float* bqu = (const float*)d_in[10];
    const float* Wkr = (const float*)d_in[11];
    const float* bkr = (const float*)d_in[12];
    const float* Wqr = (const float*)d_in[13];
    const float* bqr = (const float*)d_in[14];
    const float* Wo  = (const float*)d_in[15];
    const float* bo  = (const float*)d_in[16];

    float *kvc, *qc, *kcnt, *vv, *qcnt, *kr, *qr, *attn;
    cudaGetSymbolAddress((void**)&kvc,  g_kvc);
    cudaGetSymbolAddress((void**)&qc,   g_qc);
    cudaGetSymbolAddress((void**)&kcnt, g_kcnt);
    cudaGetSymbolAddress((void**)&vv,   g_v);
    cudaGetSymbolAddress((void**)&qcnt, g_qcnt);
    cudaGetSymbolAddress((void**)&kr,   g_kr);
    cudaGetSymbolAddress((void**)&qr,   g_qr);
    cudaGetSymbolAddress((void**)&attn, g_attn);

    dim3 thr(256);
    // compress
    gemm_bias_kernel<<<dim3(DCKVn/128, Mn/128), thr>>>(x,  Wkd, bkd, kvc,  Mn, DCKVn, Dn);
    gemm_bias_kernel<<<dim3(DCQn /128, Mn/128), thr>>>(x,  Wqd, bqd, qc,   Mn, DCQn,  Dn);
    // up-project
    gemm_bias_kernel<<<dim3((Hn*DHn)/128, Mn/128), thr>>>(kvc, Wku, bku, kcnt, Mn, Hn*DHn, DCKVn);
    gemm_bias_kernel<<<dim3((Hn*DHn)/128, Mn/128), thr>>>(kvc, Wvu, bvu, vv,   Mn, Hn*DHn, DCKVn);
    gemm_bias_kernel<<<dim3((Hn*DHn)/128, Mn/128), thr>>>(qc,  Wqu, bqu, qcnt, Mn, Hn*DHn, DCQn);
    gemm_bias_kernel<<<dim3((Hn*DRn)/128, Mn/128), thr>>>(x,   Wkr, bkr, kr,   Mn, Hn*DRn, Dn);
    gemm_bias_kernel<<<dim3((Hn*DRn)/128, Mn/128), thr>>>(qc,  Wqr, bqr, qr,   Mn, Hn*DRn, DCQn);
    // rope (in place)
    int rope_total = Mn * Hn * (DRn / 2);
    rope_kernel<<<(rope_total + 255) / 256, 256>>>(kr, rope_total);
    rope_kernel<<<(rope_total + 255) / 256, 256>>>(qr, rope_total);
    // attention
    cudaFuncSetAttribute(attn_kernel, cudaFuncAttributeMaxDynamicSharedMemorySize, ATTN_SMEM);
    attn_kernel<<<dim3(Bn*Hn, Sn/128), thr, ATTN_SMEM>>>(qcnt, qr, kcnt, kr, vv, attn);
    // output projection
    gemm_bias_kernel<<<dim3(Dn/128, Mn/128), thr>>>(attn, Wo, bo, (float*)d_out, Mn, Dn, Dn);
}

// round 12
// speedup vs baseline: 2.7876x; 1.5141x over previous
#include <cuda_runtime.h>
#include <cuda_bf16.h>
#include <math.h>
#include <stdint.h>

#define Bn 2
#define Sn 2048
#define Dn 2048
#define Hn 16
#define DHn 128
#define DRn 64
#define DCKVn 512
#define DCQn 1536
#define Mn (Bn*Sn)   // 4096 rows for every GEMM

// ---------------- scratch (device globals; no allocation allowed) ----------------
__device__ float g_kcnt[(size_t)Mn*Hn*DHn];
__device__ float g_v   [(size_t)Mn*Hn*DHn];
__device__ float g_qcnt[(size_t)Mn*Hn*DHn];
__device__ float g_kr  [(size_t)Mn*Hn*DRn];
__device__ float g_qr  [(size_t)Mn*Hn*DRn];
__device__ float g_attn[(size_t)Mn*Hn*DHn];
__device__ __nv_bfloat16 g_x_hi  [(size_t)Mn*Dn],      g_x_lo  [(size_t)Mn*Dn];
__device__ __nv_bfloat16 g_kvc_hi[(size_t)Mn*DCKVn],   g_kvc_lo[(size_t)Mn*DCKVn];
__device__ __nv_bfloat16 g_qc_hi [(size_t)Mn*DCQn],    g_qc_lo [(size_t)Mn*DCQn];
__device__ __nv_bfloat16 g_at_hi [(size_t)Mn*Hn*DHn],  g_at_lo [(size_t)Mn*Hn*DHn];
__device__ __nv_bfloat16 g_Wkd_hi[(size_t)DCKVn*Dn],     g_Wkd_lo[(size_t)DCKVn*Dn];
__device__ __nv_bfloat16 g_Wqd_hi[(size_t)DCQn*Dn],      g_Wqd_lo[(size_t)DCQn*Dn];
__device__ __nv_bfloat16 g_Wku_hi[(size_t)Hn*DHn*DCKVn], g_Wku_lo[(size_t)Hn*DHn*DCKVn];
__device__ __nv_bfloat16 g_Wvu_hi[(size_t)Hn*DHn*DCKVn], g_Wvu_lo[(size_t)Hn*DHn*DCKVn];
__device__ __nv_bfloat16 g_Wqu_hi[(size_t)Hn*DHn*DCQn],  g_Wqu_lo[(size_t)Hn*DHn*DCQn];
__device__ __nv_bfloat16 g_Wkr_hi[(size_t)Hn*DRn*Dn],    g_Wkr_lo[(size_t)Hn*DRn*Dn];
__device__ __nv_bfloat16 g_Wqr_hi[(size_t)Hn*DRn*DCQn],  g_Wqr_lo[(size_t)Hn*DRn*DCQn];
__device__ __nv_bfloat16 g_Wo_hi [(size_t)Dn*Hn*DHn],    g_Wo_lo [(size_t)Dn*Hn*DHn];

// ================= helpers =================
static __device__ __forceinline__ uint32_t smem_u32(const void* p) {
    uint32_t a;
    asm("{ .reg .u64 t; cvta.to.shared.u64 t, %1; cvt.u32.u64 %0, t; }" : "=r"(a) : "l"(p));
    return a;
}

#define LDSM4(r0,r1,r2,r3,addr) \
    asm volatile("ldmatrix.sync.aligned.m8n8.x4.shared.b16 {%0,%1,%2,%3}, [%4];" \
        : "=r"(r0),"=r"(r1),"=r"(r2),"=r"(r3) : "r"(addr))
#define LDSM2(r0,r1,addr) \
    asm volatile("ldmatrix.sync.aligned.m8n8.x2.shared.b16 {%0,%1}, [%2];" \
        : "=r"(r0),"=r"(r1) : "r"(addr))
#define MMA16816(d,a,b) \
    asm volatile("mma.sync.aligned.m16n8k16.row.col.f32.bf16.bf16.f32 " \
        "{%0,%1,%2,%3}, {%4,%5,%6,%7}, {%8,%9}, {%0,%1,%2,%3};" \
        : "+f"((d)[0]),"+f"((d)[1]),"+f"((d)[2]),"+f"((d)[3]) \
        : "r"((a)[0]),"r"((a)[1]),"r"((a)[2]),"r"((a)[3]), "r"((b)[0]),"r"((b)[1]))

// ---------------- fp32 -> bf16 hi/lo split (vectorized) ----------------
__global__ void split_kernel(const float* __restrict__ in, __nv_bfloat16* __restrict__ hi,
                             __nv_bfloat16* __restrict__ lo, int n4)
{
    int i = blockIdx.x * blockDim.x + threadIdx.x;
    if (i >= n4) return;
    float4 a = ((const float4*)in)[i];
    __nv_bfloat16 h0 = __float2bfloat16(a.x), h1 = __float2bfloat16(a.y);
    __nv_bfloat16 h2 = __float2bfloat16(a.z), h3 = __float2bfloat16(a.w);
    __nv_bfloat16 l0 = __float2bfloat16(a.x - __bfloat162float(h0));
    __nv_bfloat16 l1 = __float2bfloat16(a.y - __bfloat162float(h1));
    __nv_bfloat16 l2 = __float2bfloat16(a.z - __bfloat162float(h2));
    __nv_bfloat16 l3 = __float2bfloat16(a.w - __bfloat162float(h3));
    uint2 hv, lv;
    hv.x = (uint32_t)__bfloat16_as_ushort(h0) | ((uint32_t)__bfloat16_as_ushort(h1) << 16);
    hv.y = (uint32_t)__bfloat16_as_ushort(h2) | ((uint32_t)__bfloat16_as_ushort(h3) << 16);
    lv.x = (uint32_t)__bfloat16_as_ushort(l0) | ((uint32_t)__bfloat16_as_ushort(l1) << 16);
    lv.y = (uint32_t)__bfloat16_as_ushort(l2) | ((uint32_t)__bfloat16_as_ushort(l3) << 16);
    ((uint2*)hi)[i] = hv;
    ((uint2*)lo)[i] = lv;
}

// ---------------- mma.sync GEMM: C[M,N] = A@W^T + bias (bf16 split, fp32 accum) ----------------
// 128x128 CTA tile, 8 warps (2 M x 4 N), warp tile 64x32, m16n8k16 fragments.
// D = Ahi*Whi + Ahi*Wlo + Alo*Whi  (3 mma passes, one shared staging).
#define GM_STRIDE 72                          // bf16 elems per smem row (64 + 8 pad -> 144B stride)
#define GM_ARRB   (128*GM_STRIDE*2)           // 18432 bytes per array
#define GM_SMEM   (4*GM_ARRB)                 // 73728 bytes

__global__ __launch_bounds__(256) void gemm_mma_kernel(
    const __nv_bfloat16* __restrict__ Ahi, const __nv_bfloat16* __restrict__ Alo,
    const __nv_bfloat16* __restrict__ Whi, const __nv_bfloat16* __restrict__ Wlo,
    const float* __restrict__ bias,
    float* __restrict__ Cf,                                   // fp32 out (or null)
    __nv_bfloat16* __restrict__ Chi, __nv_bfloat16* __restrict__ Clo,   // split out
    int N, int K)
{
    extern __shared__ char smem[];
    __nv_bfloat16* ah = (__nv_bfloat16*)smem;
    __nv_bfloat16* al = ah + 128*GM_STRIDE;
    __nv_bfloat16* bh = al + 128*GM_STRIDE;
    __nv_bfloat16* bl = bh + 128*GM_STRIDE;
    const uint32_t sb = smem_u32(smem);

    const int tid  = threadIdx.x;
    const int lane = tid & 31, wid = tid >> 5;
    const int wm = wid & 1, wn = wid >> 1;       // 2 x 4 warp grid
    const int n0 = blockIdx.x << 7, m0 = blockIdx.y << 7;

    float acc[4][4][4];
#pragma unroll
    for (int mt = 0; mt < 4; mt++)
#pragma unroll
        for (int nt = 0; nt < 4; nt++)
#pragma unroll
            for (int q = 0; q < 4; q++) acc[mt][nt][q] = 0.f;

    // ldmatrix lane address components
    const int lrow = lane & 15;                  // A: row within 16
    const int lk8  = (lane >> 4) << 3;           // A: k offset 0/8
    const int brow = lane & 7;                   // B: row within 8
    const int bk8  = ((lane >> 3) & 1) << 3;     // B: k offset 0/8 (lanes 8-15)

    const uint32_t aBaseH = sb + (uint32_t)(wm*64 + lrow)*144 + (uint32_t)lk8*2;
    const uint32_t aBaseL = aBaseH + GM_ARRB;
    const uint32_t bBaseH = sb + 2u*GM_ARRB + (uint32_t)(wn*32 + brow)*144 + (uint32_t)bk8*2;
    const uint32_t bBaseL = bBaseH + GM_ARRB;

    for (int k0 = 0; k0 < K; k0 += 64) {
        __syncthreads();
        // stage Ahi/Alo/Whi/Wlo 128x64 tiles (row stride 72 elems, conflict-free for ldmatrix)
#pragma unroll
        for (int i = 0; i < 4; i++) {
            int seg = tid + (i << 8);            // 0..1023
            int r = seg >> 3, c = (seg & 7) << 3;
            size_t ga = (size_t)(m0 + r) * K + k0 + c;
            size_t gb = (size_t)(n0 + r) * K + k0 + c;
            *(uint4*)(ah + r*GM_STRIDE + c) = *(const uint4*)(Ahi + ga);
            *(uint4*)(al + r*GM_STRIDE + c) = *(const uint4*)(Alo + ga);
            *(uint4*)(bh + r*GM_STRIDE + c) = *(const uint4*)(Whi + gb);
            *(uint4*)(bl + r*GM_STRIDE + c) = *(const uint4*)(Wlo + gb);
        }
        __syncthreads();

#pragma unroll
        for (int ks = 0; ks < 4; ks++) {
            const uint32_t koff = (uint32_t)ks * 32;   // 16 bf16 = 32 bytes
            uint32_t bhf[4][2], blf[4][2];
#pragma unroll
            for (int nt = 0; nt < 4; nt++) {
                LDSM2(bhf[nt][0], bhf[nt][1], bBaseH + (uint32_t)nt*1152 + koff);
                LDSM2(blf[nt][0], blf[nt][1], bBaseL + (uint32_t)nt*1152 + koff);
            }
#pragma unroll
            for (int mt = 0; mt < 4; mt++) {
                uint32_t ahf[4], alf[4];
                LDSM4(ahf[0], ahf[1], ahf[2], ahf[3], aBaseH + (uint32_t)mt*2304 + koff);
                LDSM4(alf[0], alf[1], alf[2], alf[3], aBaseL + (uint32_t)mt*2304 + koff);
#pragma unroll
                for (int nt = 0; nt < 4; nt++) {
                    MMA16816(acc[mt][nt], ahf, bhf[nt]);
                    MMA16816(acc[mt][nt], ahf, blf[nt]);
                    MMA16816(acc[mt][nt], alf, bhf[nt]);
                }
            }
        }
    }

    // ---- epilogue ----
    const int g = lane >> 2, tg = lane & 3;
#pragma unroll
    for (int mt = 0; mt < 4; mt++) {
#pragma unroll
        for (int nt = 0; nt < 4; nt++) {
            int n   = n0 + wn*32 + nt*8 + tg*2;
            int mA  = m0 + wm*64 + mt*16 + g;
            int mB  = mA + 8;
            float b0v = bias[n], b1v = bias[n+1];
            float f0 = acc[mt][nt][0] + b0v, f1 = acc[mt][nt][1] + b1v;
            float f2 = acc[mt][nt][2] + b0v, f3 = acc[mt][nt][3] + b1v;
            if (Cf) {
                *(float2*)(Cf + (size_t)mA * N + n) = make_float2(f0, f1);
                *(float2*)(Cf + (size_t)mB * N + n) = make_float2(f2, f3);
            } else {
                __nv_bfloat16 h0 = __float2bfloat16(f0), h1 = __float2bfloat16(f1);
                __nv_bfloat16 h2 = __float2bfloat16(f2), h3 = __float2bfloat16(f3);
                __nv_bfloat16 l0 = __float2bfloat16(f0 - __bfloat162float(h0));
                __nv_bfloat16 l1 = __float2bfloat16(f1 - __bfloat162float(h1));
                __nv_bfloat16 l2 = __float2bfloat16(f2 - __bfloat162float(h2));
                __nv_bfloat16 l3 = __float2bfloat16(f3 - __bfloat162float(h3));
                uint32_t hv0 = (uint32_t)__bfloat16_as_ushort(h0) | ((uint32_t)__bfloat16_as_ushort(h1) << 16);
                uint32_t hv1 = (uint32_t)__bfloat16_as_ushort(h2) | ((uint32_t)__bfloat16_as_ushort(h3) << 16);
                uint32_t lv0 = (uint32_t)__bfloat16_as_ushort(l0) | ((uint32_t)__bfloat16_as_ushort(l1) << 16);
                uint32_t lv1 = (uint32_t)__bfloat16_as_ushort(l2) | ((uint32_t)__bfloat16_as_ushort(l3) << 16);
                *(uint32_t*)(Chi + (size_t)mA * N + n) = hv0;
                *(uint32_t*)(Chi + (size_t)mB * N + n) = hv1;
                *(uint32_t*)(Clo + (size_t)mA * N + n) = lv0;
                *(uint32_t*)(Clo + (size_t)mB * N + n) = lv1;
            }
        }
    }
}

// ---------------- rotate-half RoPE, in place on t: [B,S,H,DR] ----------------
__global__ void rope_kernel(float* __restrict__ t, int total)
{
    int idx = blockIdx.x * blockDim.x + threadIdx.x;
    if (idx >= total) return;
    int j   = idx & 31;
    int rem = idx >> 5;
    int bs  = rem >> 4;
    int s   = bs & (Sn - 1);
    float inv_freq = 1.0f / powf(10000.0f, (float)(2 * j) / (float)DRn);
    float ang = (float)s * inv_freq;
    float sv, cv;
    sincosf(ang, &sv, &cv);
    float* p = t + (size_t)rem * DRn;
    float t1 = p[j], t2 = p[j + 32];
    p[j]      = t1 * cv - t2 * sv;
    p[j + 32] = t2 * cv + t1 * sv;
}

// ---------------- causal flash attention, fp32 (unchanged from R5 best) ----------------
#define AT_QS 132
#define AT_KS 68
#define AT_PS 132
#define AT_QS_F (192*AT_QS)
#define AT_KS_F (192*AT_KS)
#define ATTN_SMEM ((AT_QS_F + AT_KS_F + 64*128) * 4)

__global__ __launch_bounds__(256) void attn_kernel(
    const float* __restrict__ qcnt, const float* __restrict__ qr,
    const float* __restrict__ kcnt, const float* __restrict__ kr,
    const float* __restrict__ v, float* __restrict__ outp)
{
    extern __shared__ float sm[];
    float* Qs = sm;
    float* Ks = Qs + AT_QS_F;
    float* Ps = Ks;
    float* Vs = Ks + AT_KS_F;

    const int tid = threadIdx.x;
    const int tx = tid & 15, ty = tid >> 4;
    const int b  = blockIdx.x >> 4;
    const int h  = blockIdx.x & 15;
    const int qb = (gridDim.y - 1) - blockIdx.y;
    const int q0 = qb * 128;
    const float scale = rsqrtf((float)(DHn + DRn));

    {
        const int lr = tid >> 1;
        const int lk = (tid & 1) << 2;
        const float* qc_row = qcnt + (size_t)(b*Sn + q0 + lr) * (Hn*DHn) + h*DHn;
        const float* qr_row = qr   + (size_t)(b*Sn + q0 + lr) * (Hn*DRn) + h*DRn;
#pragma unroll
        for (int c0 = 0; c0 < 192; c0 += 8) {
            int k = c0 + lk;
            float4 qv = (k < 128) ? *(const float4*)(qc_row + k)
                                  : *(const float4*)(qr_row + (k - 128));
            Qs[(k+0)*AT_QS + lr] = qv.x * scale;
            Qs[(k+1)*AT_QS + lr] = qv.y * scale;
            Qs[(k+2)*AT_QS + lr] = qv.z * scale;
            Qs[(k+3)*AT_QS + lr] = qv.w * scale;
        }
    }

    float mrow[8], lrow[8], acc[8][8];
#pragma unroll
    for (int i = 0; i < 8; i++) {
        mrow[i] = -3.0e38f; lrow[i] = 0.f;
#pragma unroll
        for (int j = 0; j < 8; j++) acc[i][j] = 0.f;
    }

    const int kb_end = 2*qb + 1;

    for (int kb = 0; kb <= kb_end; kb++) {
        const int k0r = kb * 64;
        __syncthreads();

        for (int idx = tid; idx < 64*48; idx += 256) {
            int r = idx / 48, c4 = idx % 48, k = c4 * 4;
            float4 kv;
            if (k < 128)
                kv = *(const float4*)(kcnt + (size_t)(b*Sn + k0r + r)*(Hn*DHn) + h*DHn + k);
            else
                kv = *(const float4*)(kr   + (size_t)(b*Sn + k0r + r)*(Hn*DRn) + h*DRn + (k-128));
            Ks[(k+0)*AT_KS + r] = kv.x;
            Ks[(k+1)*AT_KS + r] = kv.y;
            Ks[(k+2)*AT_KS + r] = kv.z;
            Ks[(k+3)*AT_KS + r] = kv.w;
        }
        for (int idx = tid; idx < 64*32; idx += 256) {
            int r = idx >> 5, c4 = idx & 31;
            *(float4*)(Vs + r*128 + c4*4) =
                *(const float4*)(v + (size_t)(b*Sn + k0r + r)*(Hn*DHn) + h*DHn + c4*4);
        }
        __syncthreads();

        float s[8][4];
#pragma unroll
        for (int i = 0; i < 8; i++)
#pragma unroll
            for (int j = 0; j < 4; j++) s[i][j] = 0.f;

#pragma unroll 4
        for (int k = 0; k < 192; k++) {
            float a[8], bq[4];
            *(float4*)(a  ) = *(const float4*)(&Qs[k*AT_QS + ty*8]);
            *(float4*)(a+4) = *(const float4*)(&Qs[k*AT_QS + ty*8 + 4]);
            *(float4*)(bq ) = *(const float4*)(&Ks[k*AT_KS + tx*4]);
#pragma unroll
            for (int i = 0; i < 8; i++)
#pragma unroll
                for (int j = 0; j < 4; j++)
                    s[i][j] = fmaf(a[i], bq[j], s[i][j]);
        }
        __syncthreads();

        if (k0r + 63 > q0) {
#pragma unroll
            for (int i = 0; i < 8; i++)
#pragma unroll
                for (int j = 0; j < 4; j++)
                    if (k0r + tx*4 + j > q0 + ty*8 + i) s[i][j] = -1e9f;
        }

#pragma unroll
        for (int i = 0; i < 8; i++) {
            float rmax = fmaxf(fmaxf(s[i][0], s[i][1]), fmaxf(s[i][2], s[i][3]));
#pragma unroll
            for (int off = 8; off >= 1; off >>= 1)
                rmax = fmaxf(rmax, __shfl_xor_sync(0xffffffffu, rmax, off, 16));
            float mn = fmaxf(mrow[i], rmax);
            float alpha = __expf(mrow[i] - mn);
            float rs = 0.f;
#pragma unroll
            for (int j = 0; j < 4; j++) { s[i][j] = __expf(s[i][j] - mn); rs += s[i][j]; }
#pragma unroll
            for (int off = 8; off >= 1; off >>= 1)
                rs += __shfl_xor_sync(0xffffffffu, rs, off, 16);
            lrow[i] = lrow[i] * alpha + rs;
            mrow[i] = mn;
#pragma unroll
            for (int j = 0; j < 8; j++) acc[i][j] *= alpha;
#pragma unroll
            for (int j = 0; j < 4; j++)
                Ps[(tx*4 + j)*AT_PS + ty*8 + i] = s[i][j];
        }
        __syncthreads();

#pragma unroll 2
        for (int c = 0; c < 64; c++) {
            float p[8], vv[8];
            *(float4*)(p  ) = *(const float4*)(&Ps[c*AT_PS + ty*8]);
            *(float4*)(p+4) = *(const float4*)(&Ps[c*AT_PS + ty*8 + 4]);
            *(float4*)(vv  ) = *(const float4*)(&Vs[c*128 + tx*8]);
            *(float4*)(vv+4) = *(const float4*)(&Vs[c*128 + tx*8 + 4]);
#pragma unroll
            for (int i = 0; i < 8; i++)
#pragma unroll
                for (int j = 0; j < 8; j++)
                    acc[i][j] = fmaf(p[i], vv[j], acc[i][j]);
        }
    }

#pragma unroll
    for (int i = 0; i < 8; i++) {
        float inv = 1.0f / lrow[i];
        float* op = outp + (size_t)(b*Sn + q0 + ty*8 + i)*(Hn*DHn) + h*DHn + tx*8;
        float4 o0 = make_float4(acc[i][0]*inv, acc[i][1]*inv, acc[i][2]*inv, acc[i][3]*inv);
        float4 o1 = make_float4(acc[i][4]*inv, acc[i][5]*inv, acc[i][6]*inv, acc[i][7]*inv);
        *(float4*)(op    ) = o0;
        *(float4*)(op + 4) = o1;
    }
}

// ---------------- launch ----------------
static void run_split(const float* in, __nv_bfloat16* hi, __nv_bfloat16* lo, size_t n) {
    int n4 = (int)(n >> 2);
    split_kernel<<<(n4 + 255) / 256, 256>>>(in, hi, lo, n4);
}

extern "C" void kernel_launch(void* const* d_in, const int* in_sizes, int n_in,
                              void* d_out, int out_size)
{
    const float* x   = (const float*)d_in[0];
    const float* Wkd = (const float*)d_in[1];
    const float* bkd = (const float*)d_in[2];
    const float* Wqd = (const float*)d_in[3];
    const float* bqd = (const float*)d_in[4];
    const float* Wku = (const float*)d_in[5];
    const float* bku = (const float*)d_in[6];
    const float* Wvu = (const float*)d_in[7];
    const float* bvu = (const float*)d_in[8];
    const float* Wqu = (const float*)d_in[9];
    const float* bqu = (const float*)d_in[10];
    const float* Wkr = (const float*)d_in[11];
    const float* bkr = (const float*)d_in[12];
    const float* Wqr = (const float*)d_in[13];
    const float* bqr = (const float*)d_in[14];
    const float* Wo  = (const float*)d_in[15];
    const float* bo  = (const float*)d_in[16];

    float *kcnt, *vv, *qcnt, *kr, *qr, *attn;
    cudaGetSymbolAddress((void**)&kcnt, g_kcnt);
    cudaGetSymbolAddress((void**)&vv,   g_v);
    cudaGetSymbolAddress((void**)&qcnt, g_qcnt);
    cudaGetSymbolAddress((void**)&kr,   g_kr);
    cudaGetSymbolAddress((void**)&qr,   g_qr);
    cudaGetSymbolAddress((void**)&attn, g_attn);

    __nv_bfloat16 *x_hi, *x_lo, *kvc_hi, *kvc_lo, *qc_hi, *qc_lo, *at_hi, *at_lo;
    cudaGetSymbolAddress((void**)&x_hi,   g_x_hi);   cudaGetSymbolAddress((void**)&x_lo,   g_x_lo);
    cudaGetSymbolAddress((void**)&kvc_hi, g_kvc_hi); cudaGetSymbolAddress((void**)&kvc_lo, g_kvc_lo);
    cudaGetSymbolAddress((void**)&qc_hi,  g_qc_hi);  cudaGetSymbolAddress((void**)&qc_lo,  g_qc_lo);
    cudaGetSymbolAddress((void**)&at_hi,  g_at_hi);  cudaGetSymbolAddress((void**)&at_lo,  g_at_lo);

    __nv_bfloat16 *Wkd_hi,*Wkd_lo,*Wqd_hi,*Wqd_lo,*Wku_hi,*Wku_lo,*Wvu_hi,*Wvu_lo;
    __nv_bfloat16 *Wqu_hi,*Wqu_lo,*Wkr_hi,*Wkr_lo,*Wqr_hi,*Wqr_lo,*Wo_hi,*Wo_lo;
    cudaGetSymbolAddress((void**)&Wkd_hi, g_Wkd_hi); cudaGetSymbolAddress((void**)&Wkd_lo, g_Wkd_lo);
    cudaGetSymbolAddress((void**)&Wqd_hi, g_Wqd_hi); cudaGetSymbolAddress((void**)&Wqd_lo, g_Wqd_lo);
    cudaGetSymbolAddress((void**)&Wku_hi, g_Wku_hi); cudaGetSymbolAddress((void**)&Wku_lo, g_Wku_lo);
    cudaGetSymbolAddress((void**)&Wvu_hi, g_Wvu_hi); cudaGetSymbolAddress((void**)&Wvu_lo, g_Wvu_lo);
    cudaGetSymbolAddress((void**)&Wqu_hi, g_Wqu_hi); cudaGetSymbolAddress((void**)&Wqu_lo, g_Wqu_lo);
    cudaGetSymbolAddress((void**)&Wkr_hi, g_Wkr_hi); cudaGetSymbolAddress((void**)&Wkr_lo, g_Wkr_lo);
    cudaGetSymbolAddress((void**)&Wqr_hi, g_Wqr_hi); cudaGetSymbolAddress((void**)&Wqr_lo, g_Wqr_lo);
    cudaGetSymbolAddress((void**)&Wo_hi,  g_Wo_hi);  cudaGetSymbolAddress((void**)&Wo_lo,  g_Wo_lo);

    // ---- split fp32 -> bf16 hi/lo ----
    run_split(x,   x_hi,   x_lo,   (size_t)Mn*Dn);
    run_split(Wkd, Wkd_hi, Wkd_lo, (size_t)DCKVn*Dn);
    run_split(Wqd, Wqd_hi, Wqd_lo, (size_t)DCQn*Dn);
    run_split(Wku, Wku_hi, Wku_lo, (size_t)Hn*DHn*DCKVn);
    run_split(Wvu, Wvu_hi, Wvu_lo, (size_t)Hn*DHn*DCKVn);
    run_split(Wqu, Wqu_hi, Wqu_lo, (size_t)Hn*DHn*DCQn);
    run_split(Wkr, Wkr_hi, Wkr_lo, (size_t)Hn*DRn*Dn);
    run_split(Wqr, Wqr_hi, Wqr_lo, (size_t)Hn*DRn*DCQn);
    run_split(Wo,  Wo_hi,  Wo_lo,  (size_t)Dn*Hn*DHn);

    cudaFuncSetAttribute(gemm_mma_kernel, cudaFuncAttributeMaxDynamicSharedMemorySize, GM_SMEM);
    dim3 thr(256);

    // ---- compress (split bf16 outputs) ----
    gemm_mma_kernel<<<dim3(DCKVn/128, Mn/128), thr, GM_SMEM>>>(
        x_hi, x_lo, Wkd_hi, Wkd_lo, bkd, nullptr, kvc_hi, kvc_lo, DCKVn, Dn);
    gemm_mma_kernel<<<dim3(DCQn/128, Mn/128), thr, GM_SMEM>>>(
        x_hi, x_lo, Wqd_hi, Wqd_lo, bqd, nullptr, qc_hi, qc_lo, DCQn, Dn);
    // ---- up-project (fp32 outputs) ----
    gemm_mma_kernel<<<dim3((Hn*DHn)/128, Mn/128), thr, GM_SMEM>>>(
        kvc_hi, kvc_lo, Wku_hi, Wku_lo, bku, kcnt, nullptr, nullptr, Hn*DHn, DCKVn);
    gemm_mma_kernel<<<dim3((Hn*DHn)/128, Mn/128), thr, GM_SMEM>>>(
        kvc_hi, kvc_lo, Wvu_hi, Wvu_lo, bvu, vv, nullptr, nullptr, Hn*DHn, DCKVn);
    gemm_mma_kernel<<<dim3((Hn*DHn)/128, Mn/128), thr, GM_SMEM>>>(
        qc_hi, qc_lo, Wqu_hi, Wqu_lo, bqu, qcnt, nullptr, nullptr, Hn*DHn, DCQn);
    gemm_mma_kernel<<<dim3((Hn*DRn)/128, Mn/128), thr, GM_SMEM>>>(
        x_hi, x_lo, Wkr_hi, Wkr_lo, bkr, kr, nullptr, nullptr, Hn*DRn, Dn);
    gemm_mma_kernel<<<dim3((Hn*DRn)/128, Mn/128), thr, GM_SMEM>>>(
        qc_hi, qc_lo, Wqr_hi, Wqr_lo, bqr, qr, nullptr, nullptr, Hn*DRn, DCQn);

    // ---- rope (in place) ----
    int rope_total = Mn * Hn * (DRn / 2);
    rope_kernel<<<(rope_total + 255) / 256, 256>>>(kr, rope_total);
    rope_kernel<<<(rope_total + 255) / 256, 256>>>(qr, rope_total);

    // ---- attention ----
    cudaFuncSetAttribute(attn_kernel, cudaFuncAttributeMaxDynamicSharedMemorySize, ATTN_SMEM);
    attn_kernel<<<dim3(Bn*Hn, Sn/128), thr, ATTN_SMEM>>>(qcnt, qr, kcnt, kr, vv, attn);

    // ---- output projection ----
    run_split(attn, at_hi, at_lo, (size_t)Mn*Hn*DHn);
    gemm_mma_kernel<<<dim3(Dn/128, Mn/128), thr, GM_SMEM>>>(
        at_hi, at_lo, Wo_hi, Wo_lo, bo, (float*)d_out, nullptr, nullptr, Dn, Hn*DHn);
}

// round 14
// speedup vs baseline: 3.4587x; 1.2407x over previous
#include <cuda_runtime.h>
#include <cuda_bf16.h>
#include <math.h>
#include <stdint.h>

#define Bn 2
#define Sn 2048
#define Dn 2048
#define Hn 16
#define DHn 128
#define DRn 64
#define DCKVn 512
#define DCQn 1536
#define Mn (Bn*Sn)

// ---------------- scratch (device globals; no allocation allowed) ----------------
__device__ float g_kr  [(size_t)Mn*Hn*DRn];
__device__ float g_qr  [(size_t)Mn*Hn*DRn];
__device__ float g_attn[(size_t)Mn*Hn*DHn];
__device__ __nv_bfloat16 g_x_hi  [(size_t)Mn*Dn],      g_x_lo  [(size_t)Mn*Dn];
__device__ __nv_bfloat16 g_kvc_hi[(size_t)Mn*DCKVn],   g_kvc_lo[(size_t)Mn*DCKVn];
__device__ __nv_bfloat16 g_qc_hi [(size_t)Mn*DCQn],    g_qc_lo [(size_t)Mn*DCQn];
__device__ __nv_bfloat16 g_at_hi [(size_t)Mn*Hn*DHn],  g_at_lo [(size_t)Mn*Hn*DHn];
// split attention operands
__device__ __nv_bfloat16 g_qu_hi [(size_t)Mn*Hn*DHn],  g_qu_lo [(size_t)Mn*Hn*DHn];
__device__ __nv_bfloat16 g_kc_hi [(size_t)Mn*Hn*DHn],  g_kc_lo [(size_t)Mn*Hn*DHn];
__device__ __nv_bfloat16 g_v_hi  [(size_t)Mn*Hn*DHn],  g_v_lo  [(size_t)Mn*Hn*DHn];
__device__ __nv_bfloat16 g_krs_hi[(size_t)Mn*Hn*DRn],  g_krs_lo[(size_t)Mn*Hn*DRn];
__device__ __nv_bfloat16 g_qrs_hi[(size_t)Mn*Hn*DRn],  g_qrs_lo[(size_t)Mn*Hn*DRn];
// split weights
__device__ __nv_bfloat16 g_Wkd_hi[(size_t)DCKVn*Dn],     g_Wkd_lo[(size_t)DCKVn*Dn];
__device__ __nv_bfloat16 g_Wqd_hi[(size_t)DCQn*Dn],      g_Wqd_lo[(size_t)DCQn*Dn];
__device__ __nv_bfloat16 g_Wku_hi[(size_t)Hn*DHn*DCKVn], g_Wku_lo[(size_t)Hn*DHn*DCKVn];
__device__ __nv_bfloat16 g_Wvu_hi[(size_t)Hn*DHn*DCKVn], g_Wvu_lo[(size_t)Hn*DHn*DCKVn];
__device__ __nv_bfloat16 g_Wqu_hi[(size_t)Hn*DHn*DCQn],  g_Wqu_lo[(size_t)Hn*DHn*DCQn];
__device__ __nv_bfloat16 g_Wkr_hi[(size_t)Hn*DRn*Dn],    g_Wkr_lo[(size_t)Hn*DRn*Dn];
__device__ __nv_bfloat16 g_Wqr_hi[(size_t)Hn*DRn*DCQn],  g_Wqr_lo[(size_t)Hn*DRn*DCQn];
__device__ __nv_bfloat16 g_Wo_hi [(size_t)Dn*Hn*DHn],    g_Wo_lo [(size_t)Dn*Hn*DHn];

// ================= helpers =================
static __device__ __forceinline__ uint32_t smem_u32(const void* p) {
    uint32_t a;
    asm("{ .reg .u64 t; cvta.to.shared.u64 t, %1; cvt.u32.u64 %0, t; }" : "=r"(a) : "l"(p));
    return a;
}
#define LDSM4(r0,r1,r2,r3,addr) \
    asm volatile("ldmatrix.sync.aligned.m8n8.x4.shared.b16 {%0,%1,%2,%3}, [%4];" \
        : "=r"(r0),"=r"(r1),"=r"(r2),"=r"(r3) : "r"(addr))
#define LDSM4T(r0,r1,r2,r3,addr) \
    asm volatile("ldmatrix.sync.aligned.m8n8.x4.trans.shared.b16 {%0,%1,%2,%3}, [%4];" \
        : "=r"(r0),"=r"(r1),"=r"(r2),"=r"(r3) : "r"(addr))
#define LDSM2(r0,r1,addr) \
    asm volatile("ldmatrix.sync.aligned.m8n8.x2.shared.b16 {%0,%1}, [%2];" \
        : "=r"(r0),"=r"(r1) : "r"(addr))
#define MMA16816(d,a,b) \
    asm volatile("mma.sync.aligned.m16n8k16.row.col.f32.bf16.bf16.f32 " \
        "{%0,%1,%2,%3}, {%4,%5,%6,%7}, {%8,%9}, {%0,%1,%2,%3};" \
        : "+f"((d)[0]),"+f"((d)[1]),"+f"((d)[2]),"+f"((d)[3]) \
        : "r"((a)[0]),"r"((a)[1]),"r"((a)[2]),"r"((a)[3]), "r"((b)[0]),"r"((b)[1]))

static __device__ __forceinline__ uint32_t pk2hi(float a, float b, float& ra, float& rb) {
    __nv_bfloat16 h0 = __float2bfloat16(a), h1 = __float2bfloat16(b);
    ra = a - __bfloat162float(h0);
    rb = b - __bfloat162float(h1);
    return (uint32_t)__bfloat16_as_ushort(h0) | ((uint32_t)__bfloat16_as_ushort(h1) << 16);
}
static __device__ __forceinline__ uint32_t pk2(float a, float b) {
    __nv_bfloat16 h0 = __float2bfloat16(a), h1 = __float2bfloat16(b);
    return (uint32_t)__bfloat16_as_ushort(h0) | ((uint32_t)__bfloat16_as_ushort(h1) << 16);
}

// ---------------- fp32 -> bf16 hi/lo split ----------------
__global__ void split_kernel(const float* __restrict__ in, __nv_bfloat16* __restrict__ hi,
                             __nv_bfloat16* __restrict__ lo, int n4)
{
    int i = blockIdx.x * blockDim.x + threadIdx.x;
    if (i >= n4) return;
    float4 a = ((const float4*)in)[i];
    float r0, r1, r2, r3;
    uint2 hv, lv;
    hv.x = pk2hi(a.x, a.y, r0, r1);
    hv.y = pk2hi(a.z, a.w, r2, r3);
    lv.x = pk2(r0, r1);
    lv.y = pk2(r2, r3);
    ((uint2*)hi)[i] = hv;
    ((uint2*)lo)[i] = lv;
}

// ---------------- mma.sync GEMM (unchanged from R12) ----------------
#define GM_STRIDE 72
#define GM_ARRB   (128*GM_STRIDE*2)
#define GM_SMEM   (4*GM_ARRB)

__global__ __launch_bounds__(256) void gemm_mma_kernel(
    const __nv_bfloat16* __restrict__ Ahi, const __nv_bfloat16* __restrict__ Alo,
    const __nv_bfloat16* __restrict__ Whi, const __nv_bfloat16* __restrict__ Wlo,
    const float* __restrict__ bias,
    float* __restrict__ Cf,
    __nv_bfloat16* __restrict__ Chi, __nv_bfloat16* __restrict__ Clo,
    int N, int K)
{
    extern __shared__ char smem[];
    __nv_bfloat16* ah = (__nv_bfloat16*)smem;
    __nv_bfloat16* al = ah + 128*GM_STRIDE;
    __nv_bfloat16* bh = al + 128*GM_STRIDE;
    __nv_bfloat16* bl = bh + 128*GM_STRIDE;
    const uint32_t sb = smem_u32(smem);

    const int tid  = threadIdx.x;
    const int lane = tid & 31, wid = tid >> 5;
    const int wm = wid & 1, wn = wid >> 1;
    const int n0 = blockIdx.x << 7, m0 = blockIdx.y << 7;

    float acc[4][4][4];
#pragma unroll
    for (int mt = 0; mt < 4; mt++)
#pragma unroll
        for (int nt = 0; nt < 4; nt++)
#pragma unroll
            for (int q = 0; q < 4; q++) acc[mt][nt][q] = 0.f;

    const int lrow = lane & 15;
    const int lk8  = (lane >> 4) << 3;
    const int brow = lane & 7;
    const int bk8  = ((lane >> 3) & 1) << 3;

    const uint32_t aBaseH = sb + (uint32_t)(wm*64 + lrow)*144 + (uint32_t)lk8*2;
    const uint32_t aBaseL = aBaseH + GM_ARRB;
    const uint32_t bBaseH = sb + 2u*GM_ARRB + (uint32_t)(wn*32 + brow)*144 + (uint32_t)bk8*2;
    const uint32_t bBaseL = bBaseH + GM_ARRB;

    for (int k0 = 0; k0 < K; k0 += 64) {
        __syncthreads();
#pragma unroll
        for (int i = 0; i < 4; i++) {
            int seg = tid + (i << 8);
            int r = seg >> 3, c = (seg & 7) << 3;
            size_t ga = (size_t)(m0 + r) * K + k0 + c;
            size_t gb = (size_t)(n0 + r) * K + k0 + c;
            *(uint4*)(ah + r*GM_STRIDE + c) = *(const uint4*)(Ahi + ga);
            *(uint4*)(al + r*GM_STRIDE + c) = *(const uint4*)(Alo + ga);
            *(uint4*)(bh + r*GM_STRIDE + c) = *(const uint4*)(Whi + gb);
            *(uint4*)(bl + r*GM_STRIDE + c) = *(const uint4*)(Wlo + gb);
        }
        __syncthreads();

#pragma unroll
        for (int ks = 0; ks < 4; ks++) {
            const uint32_t koff = (uint32_t)ks * 32;
            uint32_t bhf[4][2], blf[4][2];
#pragma unroll
            for (int nt = 0; nt < 4; nt++) {
                LDSM2(bhf[nt][0], bhf[nt][1], bBaseH + (uint32_t)nt*1152 + koff);
                LDSM2(blf[nt][0], blf[nt][1], bBaseL + (uint32_t)nt*1152 + koff);
            }
#pragma unroll
            for (int mt = 0; mt < 4; mt++) {
                uint32_t ahf[4], alf[4];
                LDSM4(ahf[0], ahf[1], ahf[2], ahf[3], aBaseH + (uint32_t)mt*2304 + koff);
                LDSM4(alf[0], alf[1], alf[2], alf[3], aBaseL + (uint32_t)mt*2304 + koff);
#pragma unroll
                for (int nt = 0; nt < 4; nt++) {
                    MMA16816(acc[mt][nt], ahf, bhf[nt]);
                    MMA16816(acc[mt][nt], ahf, blf[nt]);
                    MMA16816(acc[mt][nt], alf, bhf[nt]);
                }
            }
        }
    }

    const int g = lane >> 2, tg = lane & 3;
#pragma unroll
    for (int mt = 0; mt < 4; mt++) {
#pragma unroll
        for (int nt = 0; nt < 4; nt++) {
            int n   = n0 + wn*32 + nt*8 + tg*2;
            int mA  = m0 + wm*64 + mt*16 + g;
            int mB  = mA + 8;
            float b0v = bias[n], b1v = bias[n+1];
            float f0 = acc[mt][nt][0] + b0v, f1 = acc[mt][nt][1] + b1v;
            float f2 = acc[mt][nt][2] + b0v, f3 = acc[mt][nt][3] + b1v;
            if (Cf) {
                *(float2*)(Cf + (size_t)mA * N + n) = make_float2(f0, f1);
                *(float2*)(Cf + (size_t)mB * N + n) = make_float2(f2, f3);
            } else {
                float r0, r1, r2, r3;
                uint32_t hv0 = pk2hi(f0, f1, r0, r1);
                uint32_t hv1 = pk2hi(f2, f3, r2, r3);
                *(uint32_t*)(Chi + (size_t)mA * N + n) = hv0;
                *(uint32_t*)(Chi + (size_t)mB * N + n) = hv1;
                *(uint32_t*)(Clo + (size_t)mA * N + n) = pk2(r0, r1);
                *(uint32_t*)(Clo + (size_t)mB * N + n) = pk2(r2, r3);
            }
        }
    }
}

// ---------------- rotate-half RoPE, in place ----------------
__global__ void rope_kernel(float* __restrict__ t, int total)
{
    int idx = blockIdx.x * blockDim.x + threadIdx.x;
    if (idx >= total) return;
    int j   = idx & 31;
    int rem = idx >> 5;
    int bs  = rem >> 4;
    int s   = bs & (Sn - 1);
    float inv_freq = 1.0f / powf(10000.0f, (float)(2 * j) / (float)DRn);
    float ang = (float)s * inv_freq;
    float sv, cv;
    sincosf(ang, &sv, &cv);
    float* p = t + (size_t)rem * DRn;
    float t1 = p[j], t2 = p[j + 32];
    p[j]      = t1 * cv - t2 * sv;
    p[j + 32] = t2 * cv + t1 * sv;
}

// ---------------- tensor-core causal flash attention (bf16 split, fp32 softmax) ----------------
// grid (B*H, S/128). 256 threads, 8 warps; warp w owns rows w*16..w*16+15 x all keys.
// Q persistent in smem [128][200] hi/lo; K [64][200] hi/lo; V [64][136] hi/lo per tile.
#define SQH 0
#define SQL 51200
#define SKH 102400
#define SKL 128000
#define SVH 153600
#define SVL 171008
#define ATTN_SMEM 188416

__global__ __launch_bounds__(256) void attn_mma_kernel(
    const __nv_bfloat16* __restrict__ quh, const __nv_bfloat16* __restrict__ qul,
    const __nv_bfloat16* __restrict__ qrh, const __nv_bfloat16* __restrict__ qrl,
    const __nv_bfloat16* __restrict__ kch, const __nv_bfloat16* __restrict__ kcl,
    const __nv_bfloat16* __restrict__ krh, const __nv_bfloat16* __restrict__ krl,
    const __nv_bfloat16* __restrict__ vhi, const __nv_bfloat16* __restrict__ vlo,
    float* __restrict__ outp)
{
    extern __shared__ char smraw[];
    __nv_bfloat16* Qh = (__nv_bfloat16*)(smraw + SQH);
    __nv_bfloat16* Ql = (__nv_bfloat16*)(smraw + SQL);
    __nv_bfloat16* Kh = (__nv_bfloat16*)(smraw + SKH);
    __nv_bfloat16* Kl = (__nv_bfloat16*)(smraw + SKL);
    __nv_bfloat16* Vh = (__nv_bfloat16*)(smraw + SVH);
    __nv_bfloat16* Vl = (__nv_bfloat16*)(smraw + SVL);
    const uint32_t sb = smem_u32(smraw);

    const int tid  = threadIdx.x;
    const int lane = tid & 31, w = tid >> 5;
    const int b  = blockIdx.x >> 4;
    const int h  = blockIdx.x & 15;
    const int qb = (gridDim.y - 1) - blockIdx.y;
    const int q0 = qb * 128;
    const float scale = rsqrtf((float)(DHn + DRn));
    const int g = lane >> 2, tg = lane & 3;

    // ---- stage Q [128][192] hi/lo ----
    for (int i = tid; i < 3072; i += 256) {
        int r = i / 24, c = i % 24;
        size_t m = (size_t)(b*Sn + q0 + r);
        uint4 h4, l4;
        if (c < 16) {
            size_t off = m*(Hn*DHn) + h*DHn + c*8;
            h4 = *(const uint4*)(quh + off); l4 = *(const uint4*)(qul + off);
        } else {
            size_t off = m*(Hn*DRn) + h*DRn + (c-16)*8;
            h4 = *(const uint4*)(qrh + off); l4 = *(const uint4*)(qrl + off);
        }
        *(uint4*)(Qh + r*200 + c*8) = h4;
        *(uint4*)(Ql + r*200 + c*8) = l4;
    }

    float o[16][4];
#pragma unroll
    for (int nf = 0; nf < 16; nf++)
#pragma unroll
        for (int q = 0; q < 4; q++) o[nf][q] = 0.f;
    float mst0 = -1e30f, mst1 = -1e30f, lst0 = 0.f, lst1 = 0.f;

    // ldmatrix addresses
    const uint32_t aQhB = sb + SQH + (uint32_t)(w*16 + (lane & 15))*400 + (uint32_t)((lane >> 4) & 1)*16;
    const uint32_t aQlB = aQhB + (SQL - SQH);
    const uint32_t bKhB = sb + SKH + (uint32_t)((lane & 7) + ((lane & 16) >> 1))*400 + (uint32_t)(lane & 8)*2;
    const uint32_t bKlB = bKhB + (SKL - SKH);
    const uint32_t vBH  = sb + SVH + (uint32_t)(lane & 15)*272 + (uint32_t)((lane >> 4) << 4);
    const uint32_t vBL  = vBH + (SVL - SVH);

    const int kb_end = 2*qb + 1;
    for (int kb = 0; kb <= kb_end; kb++) {
        const int k0 = kb * 64;
        __syncthreads();
        // ---- stage K [64][192] hi/lo ----
        for (int i = tid; i < 1536; i += 256) {
            int r = i / 24, c = i % 24;
            size_t m = (size_t)(b*Sn + k0 + r);
            uint4 h4, l4;
            if (c < 16) {
                size_t off = m*(Hn*DHn) + h*DHn + c*8;
                h4 = *(const uint4*)(kch + off); l4 = *(const uint4*)(kcl + off);
            } else {
                size_t off = m*(Hn*DRn) + h*DRn + (c-16)*8;
                h4 = *(const uint4*)(krh + off); l4 = *(const uint4*)(krl + off);
            }
            *(uint4*)(Kh + r*200 + c*8) = h4;
            *(uint4*)(Kl + r*200 + c*8) = l4;
        }
        // ---- stage V [64][128] hi/lo ----
        for (int i = tid; i < 1024; i += 256) {
            int r = i >> 4, c = i & 15;
            size_t off = (size_t)(b*Sn + k0 + r)*(Hn*DHn) + h*DHn + c*8;
            *(uint4*)(Vh + r*136 + c*8) = *(const uint4*)(vhi + off);
            *(uint4*)(Vl + r*136 + c*8) = *(const uint4*)(vlo + off);
        }
        __syncthreads();

        // ---- S = Q K^T (3-pass split) ----
        float s[8][4];
#pragma unroll
        for (int nt = 0; nt < 8; nt++)
#pragma unroll
            for (int q = 0; q < 4; q++) s[nt][q] = 0.f;

        for (int kc = 0; kc < 12; kc++) {
            uint32_t qh4[4], ql4[4];
            LDSM4(qh4[0], qh4[1], qh4[2], qh4[3], aQhB + (uint32_t)kc*32);
            LDSM4(ql4[0], ql4[1], ql4[2], ql4[3], aQlB + (uint32_t)kc*32);
#pragma unroll
            for (int np = 0; np < 4; np++) {
                uint32_t kh4[4], kl4[4];
                LDSM4(kh4[0], kh4[1], kh4[2], kh4[3], bKhB + (uint32_t)np*6400 + (uint32_t)kc*32);
                LDSM4(kl4[0], kl4[1], kl4[2], kl4[3], bKlB + (uint32_t)np*6400 + (uint32_t)kc*32);
                uint32_t bh0[2] = {kh4[0], kh4[1]}, bh1[2] = {kh4[2], kh4[3]};
                uint32_t bl0[2] = {kl4[0], kl4[1]}, bl1[2] = {kl4[2], kl4[3]};
                MMA16816(s[2*np],   qh4, bh0); MMA16816(s[2*np],   qh4, bl0); MMA16816(s[2*np],   ql4, bh0);
                MMA16816(s[2*np+1], qh4, bh1); MMA16816(s[2*np+1], qh4, bl1); MMA16816(s[2*np+1], ql4, bh1);
            }
        }

        // scale + causal mask
#pragma unroll
        for (int nt = 0; nt < 8; nt++)
#pragma unroll
            for (int q = 0; q < 4; q++) s[nt][q] *= scale;
        if (k0 + 63 > q0) {
            int rg = q0 + w*16 + g;
#pragma unroll
            for (int nt = 0; nt < 8; nt++)
#pragma unroll
                for (int q = 0; q < 2; q++) {
                    int col = k0 + nt*8 + tg*2 + q;
                    if (col > rg)     s[nt][q]     = -1e9f;
                    if (col > rg + 8) s[nt][q + 2] = -1e9f;
                }
        }

        // ---- online softmax (rows g and g+8) ----
        float mg = -1e30f, mh = -1e30f;
#pragma unroll
        for (int nt = 0; nt < 8; nt++) {
            mg = fmaxf(mg, fmaxf(s[nt][0], s[nt][1]));
            mh = fmaxf(mh, fmaxf(s[nt][2], s[nt][3]));
        }
        mg = fmaxf(mg, __shfl_xor_sync(0xffffffffu, mg, 1));
        mg = fmaxf(mg, __shfl_xor_sync(0xffffffffu, mg, 2));
        mh = fmaxf(mh, __shfl_xor_sync(0xffffffffu, mh, 1));
        mh = fmaxf(mh, __shfl_xor_sync(0xffffffffu, mh, 2));
        float mng = fmaxf(mst0, mg), mnh = fmaxf(mst1, mh);
        float alg = __expf(mst0 - mng), alh = __expf(mst1 - mnh);
        float rsg = 0.f, rsh = 0.f;
#pragma unroll
        for (int nt = 0; nt < 8; nt++) {
            s[nt][0] = __expf(s[nt][0] - mng); rsg += s[nt][0];
            s[nt][1] = __expf(s[nt][1] - mng); rsg += s[nt][1];
            s[nt][2] = __expf(s[nt][2] - mnh); rsh += s[nt][2];
            s[nt][3] = __expf(s[nt][3] - mnh); rsh += s[nt][3];
        }
        rsg += __shfl_xor_sync(0xffffffffu, rsg, 1);
        rsg += __shfl_xor_sync(0xffffffffu, rsg, 2);
        rsh += __shfl_xor_sync(0xffffffffu, rsh, 1);
        rsh += __shfl_xor_sync(0xffffffffu, rsh, 2);
        lst0 = lst0 * alg + rsg; mst0 = mng;
        lst1 = lst1 * alh + rsh; mst1 = mnh;
#pragma unroll
        for (int nf = 0; nf < 16; nf++) {
            o[nf][0] *= alg; o[nf][1] *= alg;
            o[nf][2] *= alh; o[nf][3] *= alh;
        }

        // ---- pack P into A-frags (hi/lo) ----
        uint32_t pah[4][4], pal[4][4];
#pragma unroll
        for (int kcp = 0; kcp < 4; kcp++) {
            float r0, r1, r2, r3, r4, r5, r6, r7;
            pah[kcp][0] = pk2hi(s[2*kcp][0],   s[2*kcp][1],   r0, r1);
            pah[kcp][1] = pk2hi(s[2*kcp][2],   s[2*kcp][3],   r2, r3);
            pah[kcp][2] = pk2hi(s[2*kcp+1][0], s[2*kcp+1][1], r4, r5);
            pah[kcp][3] = pk2hi(s[2*kcp+1][2], s[2*kcp+1][3], r6, r7);
            pal[kcp][0] = pk2(r0, r1);
            pal[kcp][1] = pk2(r2, r3);
            pal[kcp][2] = pk2(r4, r5);
            pal[kcp][3] = pk2(r6, r7);
        }

        // ---- O += P V (3-pass split) ----
#pragma unroll
        for (int kcp = 0; kcp < 4; kcp++) {
            uint32_t koff = (uint32_t)kcp * 4352;     // 16 keys * 272 B
#pragma unroll
            for (int nq = 0; nq < 8; nq++) {
                uint32_t vh4[4], vl4[4];
                LDSM4T(vh4[0], vh4[1], vh4[2], vh4[3], vBH + koff + (uint32_t)nq*32);
                LDSM4T(vl4[0], vl4[1], vl4[2], vl4[3], vBL + koff + (uint32_t)nq*32);
                uint32_t bh0[2] = {vh4[0], vh4[1]}, bh1[2] = {vh4[2], vh4[3]};
                uint32_t bl0[2] = {vl4[0], vl4[1]}, bl1[2] = {vl4[2], vl4[3]};
                MMA16816(o[2*nq],   pah[kcp], bh0); MMA16816(o[2*nq],   pah[kcp], bl0); MMA16816(o[2*nq],   pal[kcp], bh0);
                MMA16816(o[2*nq+1], pah[kcp], bh1); MMA16816(o[2*nq+1], pah[kcp], bl1); MMA16816(o[2*nq+1], pal[kcp], bh1);
            }
        }
    }

    // ---- epilogue ----
    float ig = 1.f / lst0, ih = 1.f / lst1;
    int rgl = q0 + w*16 + g;
    float* baseg = outp + (size_t)(b*Sn + rgl    )*(Hn*DHn) + h*DHn + tg*2;
    float* baseh = outp + (size_t)(b*Sn + rgl + 8)*(Hn*DHn) + h*DHn + tg*2;
#pragma unroll
    for (int nf = 0; nf < 16; nf++) {
        *(float2*)(baseg + nf*8) = make_float2(o[nf][0]*ig, o[nf][1]*ig);
        *(float2*)(baseh + nf*8) = make_float2(o[nf][2]*ih, o[nf][3]*ih);
    }
}

// ---------------- launch ----------------
static void run_split(const float* in, __nv_bfloat16* hi, __nv_bfloat16* lo, size_t n) {
    int n4 = (int)(n >> 2);
    split_kernel<<<(n4 + 255) / 256, 256>>>(in, hi, lo, n4);
}

extern "C" void kernel_launch(void* const* d_in, const int* in_sizes, int n_in,
                              void* d_out, int out_size)
{
    const float* x   = (const float*)d_in[0];
    const float* Wkd = (const float*)d_in[1];
    const float* bkd = (const float*)d_in[2];
    const float* Wqd = (const float*)d_in[3];
    const float* bqd = (const float*)d_in[4];
    const float* Wku = (const float*)d_in[5];
    const float* bku = (const float*)d_in[6];
    const float* Wvu = (const float*)d_in[7];
    const float* bvu = (const float*)d_in[8];
    const float* Wqu = (const float*)d_in[9];
    const float* bqu = (const float*)d_in[10];
    const float* Wkr = (const float*)d_in[11];
    const float* bkr = (const float*)d_in[12];
    const float* Wqr = (const float*)d_in[13];
    const float* bqr = (const float*)d_in[14];
    const float* Wo  = (const float*)d_in[15];
    const float* bo  = (const float*)d_in[16];

    float *kr, *qr, *attn;
    cudaGetSymbolAddress((void**)&kr,   g_kr);
    cudaGetSymbolAddress((void**)&qr,   g_qr);
    cudaGetSymbolAddress((void**)&attn, g_attn);

    __nv_bfloat16 *x_hi, *x_lo, *kvc_hi, *kvc_lo, *qc_hi, *qc_lo, *at_hi, *at_lo;
    __nv_bfloat16 *qu_hi, *qu_lo, *kc_hi, *kc_lo, *v_hi, *v_lo, *krs_hi, *krs_lo, *qrs_hi, *qrs_lo;
    cudaGetSymbolAddress((void**)&x_hi,   g_x_hi);   cudaGetSymbolAddress((void**)&x_lo,   g_x_lo);
    cudaGetSymbolAddress((void**)&kvc_hi, g_kvc_hi); cudaGetSymbolAddress((void**)&kvc_lo, g_kvc_lo);
    cudaGetSymbolAddress((void**)&qc_hi,  g_qc_hi);  cudaGetSymbolAddress((void**)&qc_lo,  g_qc_lo);
    cudaGetSymbolAddress((void**)&at_hi,  g_at_hi);  cudaGetSymbolAddress((void**)&at_lo,  g_at_lo);
    cudaGetSymbolAddress((void**)&qu_hi,  g_qu_hi);  cudaGetSymbolAddress((void**)&qu_lo,  g_qu_lo);
    cudaGetSymbolAddress((void**)&kc_hi,  g_kc_hi);  cudaGetSymbolAddress((void**)&kc_lo,  g_kc_lo);
    cudaGetSymbolAddress((void**)&v_hi,   g_v_hi);   cudaGetSymbolAddress((void**)&v_lo,   g_v_lo);
    cudaGetSymbolAddress((void**)&krs_hi, g_krs_hi); cudaGetSymbolAddress((void**)&krs_lo, g_krs_lo);
    cudaGetSymbolAddress((void**)&qrs_hi, g_qrs_hi); cudaGetSymbolAddress((void**)&qrs_lo, g_qrs_lo);

    __nv_bfloat16 *Wkd_hi,*Wkd_lo,*Wqd_hi,*Wqd_lo,*Wku_hi,*Wku_lo,*Wvu_hi,*Wvu_lo;
    __nv_bfloat16 *Wqu_hi,*Wqu_lo,*Wkr_hi,*Wkr_lo,*Wqr_hi,*Wqr_lo,*Wo_hi,*Wo_lo;
    cudaGetSymbolAddress((void**)&Wkd_hi, g_Wkd_hi); cudaGetSymbolAddress((void**)&Wkd_lo, g_Wkd_lo);
    cudaGetSymbolAddress((void**)&Wqd_hi, g_Wqd_hi); cudaGetSymbolAddress((void**)&Wqd_lo, g_Wqd_lo);
    cudaGetSymbolAddress((void**)&Wku_hi, g_Wku_hi); cudaGetSymbolAddress((void**)&Wku_lo, g_Wku_lo);
    cudaGetSymbolAddress((void**)&Wvu_hi, g_Wvu_hi); cudaGetSymbolAddress((void**)&Wvu_lo, g_Wvu_lo);
    cudaGetSymbolAddress((void**)&Wqu_hi, g_Wqu_hi); cudaGetSymbolAddress((void**)&Wqu_lo, g_Wqu_lo);
    cudaGetSymbolAddress((void**)&Wkr_hi, g_Wkr_hi); cudaGetSymbolAddress((void**)&Wkr_lo, g_Wkr_lo);
    cudaGetSymbolAddress((void**)&Wqr_hi, g_Wqr_hi); cudaGetSymbolAddress((void**)&Wqr_lo, g_Wqr_lo);
    cudaGetSymbolAddress((void**)&Wo_hi,  g_Wo_hi);  cudaGetSymbolAddress((void**)&Wo_lo,  g_Wo_lo);

    // ---- split inputs ----
    run_split(x,   x_hi,   x_lo,   (size_t)Mn*Dn);
    run_split(Wkd, Wkd_hi, Wkd_lo, (size_t)DCKVn*Dn);
    run_split(Wqd, Wqd_hi, Wqd_lo, (size_t)DCQn*Dn);
    run_split(Wku, Wku_hi, Wku_lo, (size_t)Hn*DHn*DCKVn);
    run_split(Wvu, Wvu_hi, Wvu_lo, (size_t)Hn*DHn*DCKVn);
    run_split(Wqu, Wqu_hi, Wqu_lo, (size_t)Hn*DHn*DCQn);
    run_split(Wkr, Wkr_hi, Wkr_lo, (size_t)Hn*DRn*Dn);
    run_split(Wqr, Wqr_hi, Wqr_lo, (size_t)Hn*DRn*DCQn);
    run_split(Wo,  Wo_hi,  Wo_lo,  (size_t)Dn*Hn*DHn);

    cudaFuncSetAttribute(gemm_mma_kernel, cudaFuncAttributeMaxDynamicSharedMemorySize, GM_SMEM);
    dim3 thr(256);

    // ---- compress ----
    gemm_mma_kernel<<<dim3(DCKVn/128, Mn/128), thr, GM_SMEM>>>(
        x_hi, x_lo, Wkd_hi, Wkd_lo, bkd, nullptr, kvc_hi, kvc_lo, DCKVn, Dn);
    gemm_mma_kernel<<<dim3(DCQn/128, Mn/128), thr, GM_SMEM>>>(
        x_hi, x_lo, Wqd_hi, Wqd_lo, bqd, nullptr, qc_hi, qc_lo, DCQn, Dn);
    // ---- up-project: content/value as split bf16, rope parts fp32 (rope first) ----
    gemm_mma_kernel<<<dim3((Hn*DHn)/128, Mn/128), thr, GM_SMEM>>>(
        kvc_hi, kvc_lo, Wku_hi, Wku_lo, bku, nullptr, kc_hi, kc_lo, Hn*DHn, DCKVn);
    gemm_mma_kernel<<<dim3((Hn*DHn)/128, Mn/128), thr, GM_SMEM>>>(
        kvc_hi, kvc_lo, Wvu_hi, Wvu_lo, bvu, nullptr, v_hi, v_lo, Hn*DHn, DCKVn);
    gemm_mma_kernel<<<dim3((Hn*DHn)/128, Mn/128), thr, GM_SMEM>>>(
        qc_hi, qc_lo, Wqu_hi, Wqu_lo, bqu, nullptr, qu_hi, qu_lo, Hn*DHn, DCQn);
    gemm_mma_kernel<<<dim3((Hn*DRn)/128, Mn/128), thr, GM_SMEM>>>(
        x_hi, x_lo, Wkr_hi, Wkr_lo, bkr, kr, nullptr, nullptr, Hn*DRn, Dn);
    gemm_mma_kernel<<<dim3((Hn*DRn)/128, Mn/128), thr, GM_SMEM>>>(
        qc_hi, qc_lo, Wqr_hi, Wqr_lo, bqr, qr, nullptr, nullptr, Hn*DRn, DCQn);

    // ---- rope (fp32, in place) then split ----
    int rope_total = Mn * Hn * (DRn / 2);
    rope_kernel<<<(rope_total + 255) / 256, 256>>>(kr, rope_total);
    rope_kernel<<<(rope_total + 255) / 256, 256>>>(qr, rope_total);
    run_split(kr, krs_hi, krs_lo, (size_t)Mn*Hn*DRn);
    run_split(qr, qrs_hi, qrs_lo, (size_t)Mn*Hn*DRn);

    // ---- attention (tensor cores) ----
    cudaFuncSetAttribute(attn_mma_kernel, cudaFuncAttributeMaxDynamicSharedMemorySize, ATTN_SMEM);
    attn_mma_kernel<<<dim3(Bn*Hn, Sn/128), thr, ATTN_SMEM>>>(
        qu_hi, qu_lo, qrs_hi, qrs_lo, kc_hi, kc_lo, krs_hi, krs_lo, v_hi, v_lo, attn);

    // ---- output projection ----
    run_split(attn, at_hi, at_lo, (size_t)Mn*Hn*DHn);
    gemm_mma_kernel<<<dim3(Dn/128, Mn/128), thr, GM_SMEM>>>(
        at_hi, at_lo, Wo_hi, Wo_lo, bo, (float*)d_out, nullptr, nullptr, Dn, Hn*DHn);
}

// round 15
// speedup vs baseline: 5.1961x; 1.5023x over previous
#include <cuda_runtime.h>
#include <cuda_bf16.h>
#include <math.h>
#include <stdint.h>

#define Bn 2
#define Sn 2048
#define Dn 2048
#define Hn 16
#define DHn 128
#define DRn 64
#define DCKVn 512
#define DCQn 1536
#define Mn (Bn*Sn)

// ---------------- scratch (device globals; no allocation allowed) ----------------
__device__ float g_kr  [(size_t)Mn*Hn*DRn];
__device__ float g_qr  [(size_t)Mn*Hn*DRn];
__device__ __nv_bfloat16 g_x_hi  [(size_t)Mn*Dn],      g_x_lo  [(size_t)Mn*Dn];
__device__ __nv_bfloat16 g_kvc_hi[(size_t)Mn*DCKVn],   g_kvc_lo[(size_t)Mn*DCKVn];
__device__ __nv_bfloat16 g_qc_hi [(size_t)Mn*DCQn],    g_qc_lo [(size_t)Mn*DCQn];
__device__ __nv_bfloat16 g_at_hi [(size_t)Mn*Hn*DHn],  g_at_lo [(size_t)Mn*Hn*DHn];
__device__ __nv_bfloat16 g_qu_hi [(size_t)Mn*Hn*DHn],  g_qu_lo [(size_t)Mn*Hn*DHn];
__device__ __nv_bfloat16 g_kc_hi [(size_t)Mn*Hn*DHn],  g_kc_lo [(size_t)Mn*Hn*DHn];
__device__ __nv_bfloat16 g_v_hi  [(size_t)Mn*Hn*DHn],  g_v_lo  [(size_t)Mn*Hn*DHn];
__device__ __nv_bfloat16 g_krs_hi[(size_t)Mn*Hn*DRn],  g_krs_lo[(size_t)Mn*Hn*DRn];
__device__ __nv_bfloat16 g_qrs_hi[(size_t)Mn*Hn*DRn],  g_qrs_lo[(size_t)Mn*Hn*DRn];
__device__ __nv_bfloat16 g_Wkd_hi[(size_t)DCKVn*Dn],     g_Wkd_lo[(size_t)DCKVn*Dn];
__device__ __nv_bfloat16 g_Wqd_hi[(size_t)DCQn*Dn],      g_Wqd_lo[(size_t)DCQn*Dn];
__device__ __nv_bfloat16 g_Wku_hi[(size_t)Hn*DHn*DCKVn], g_Wku_lo[(size_t)Hn*DHn*DCKVn];
__device__ __nv_bfloat16 g_Wvu_hi[(size_t)Hn*DHn*DCKVn], g_Wvu_lo[(size_t)Hn*DHn*DCKVn];
__device__ __nv_bfloat16 g_Wqu_hi[(size_t)Hn*DHn*DCQn],  g_Wqu_lo[(size_t)Hn*DHn*DCQn];
__device__ __nv_bfloat16 g_Wkr_hi[(size_t)Hn*DRn*Dn],    g_Wkr_lo[(size_t)Hn*DRn*Dn];
__device__ __nv_bfloat16 g_Wqr_hi[(size_t)Hn*DRn*DCQn],  g_Wqr_lo[(size_t)Hn*DRn*DCQn];
__device__ __nv_bfloat16 g_Wo_hi [(size_t)Dn*Hn*DHn],    g_Wo_lo [(size_t)Dn*Hn*DHn];

// ================= helpers =================
static __device__ __forceinline__ uint32_t smem_u32(const void* p) {
    uint32_t a;
    asm("{ .reg .u64 t; cvta.to.shared.u64 t, %1; cvt.u32.u64 %0, t; }" : "=r"(a) : "l"(p));
    return a;
}
#define LDSM4(r0,r1,r2,r3,addr) \
    asm volatile("ldmatrix.sync.aligned.m8n8.x4.shared.b16 {%0,%1,%2,%3}, [%4];" \
        : "=r"(r0),"=r"(r1),"=r"(r2),"=r"(r3) : "r"(addr))
#define LDSM4T(r0,r1,r2,r3,addr) \
    asm volatile("ldmatrix.sync.aligned.m8n8.x4.trans.shared.b16 {%0,%1,%2,%3}, [%4];" \
        : "=r"(r0),"=r"(r1),"=r"(r2),"=r"(r3) : "r"(addr))
#define LDSM2(r0,r1,addr) \
    asm volatile("ldmatrix.sync.aligned.m8n8.x2.shared.b16 {%0,%1}, [%2];" \
        : "=r"(r0),"=r"(r1) : "r"(addr))
#define MMA16816(d,a,b) \
    asm volatile("mma.sync.aligned.m16n8k16.row.col.f32.bf16.bf16.f32 " \
        "{%0,%1,%2,%3}, {%4,%5,%6,%7}, {%8,%9}, {%0,%1,%2,%3};" \
        : "+f"((d)[0]),"+f"((d)[1]),"+f"((d)[2]),"+f"((d)[3]) \
        : "r"((a)[0]),"r"((a)[1]),"r"((a)[2]),"r"((a)[3]), "r"((b)[0]),"r"((b)[1]))
#define CP16(dst, src) \
    asm volatile("cp.async.cg.shared.global [%0], [%1], 16;" :: "r"(dst), "l"(src))
#define CP_COMMIT() asm volatile("cp.async.commit_group;" ::: "memory")
#define CP_WAIT0()  asm volatile("cp.async.wait_group 0;" ::: "memory")
#define CP_WAIT1()  asm volatile("cp.async.wait_group 1;" ::: "memory")

static __device__ __forceinline__ uint32_t pk2hi(float a, float b, float& ra, float& rb) {
    __nv_bfloat16 h0 = __float2bfloat16(a), h1 = __float2bfloat16(b);
    ra = a - __bfloat162float(h0);
    rb = b - __bfloat162float(h1);
    return (uint32_t)__bfloat16_as_ushort(h0) | ((uint32_t)__bfloat16_as_ushort(h1) << 16);
}
static __device__ __forceinline__ uint32_t pk2(float a, float b) {
    __nv_bfloat16 h0 = __float2bfloat16(a), h1 = __float2bfloat16(b);
    return (uint32_t)__bfloat16_as_ushort(h0) | ((uint32_t)__bfloat16_as_ushort(h1) << 16);
}

// ---------------- fp32 -> bf16 hi/lo split ----------------
__global__ void split_kernel(const float* __restrict__ in, __nv_bfloat16* __restrict__ hi,
                             __nv_bfloat16* __restrict__ lo, int n4)
{
    int i = blockIdx.x * blockDim.x + threadIdx.x;
    if (i >= n4) return;
    float4 a = ((const float4*)in)[i];
    float r0, r1, r2, r3;
    uint2 hv, lv;
    hv.x = pk2hi(a.x, a.y, r0, r1);
    hv.y = pk2hi(a.z, a.w, r2, r3);
    lv.x = pk2(r0, r1);
    lv.y = pk2(r2, r3);
    ((uint2*)hi)[i] = hv;
    ((uint2*)lo)[i] = lv;
}

// ---------------- mma.sync GEMM with 2-stage cp.async pipeline ----------------
#define GM_STRIDE 72
#define GM_ARRB   (128*GM_STRIDE*2)           // 18432 B per array
#define GM_STAGE  (4*GM_ARRB)                 // 73728 B per stage
#define GM_SMEM   (2*GM_STAGE)                // 147456 B

__global__ __launch_bounds__(256) void gemm_mma_kernel(
    const __nv_bfloat16* __restrict__ Ahi, const __nv_bfloat16* __restrict__ Alo,
    const __nv_bfloat16* __restrict__ Whi, const __nv_bfloat16* __restrict__ Wlo,
    const float* __restrict__ bias,
    float* __restrict__ Cf,
    __nv_bfloat16* __restrict__ Chi, __nv_bfloat16* __restrict__ Clo,
    int N, int K)
{
    extern __shared__ char smem[];
    const uint32_t sb = smem_u32(smem);

    const int tid  = threadIdx.x;
    const int lane = tid & 31, wid = tid >> 5;
    const int wm = wid & 1, wn = wid >> 1;
    const int n0 = blockIdx.x << 7, m0 = blockIdx.y << 7;

    float acc[4][4][4];
#pragma unroll
    for (int mt = 0; mt < 4; mt++)
#pragma unroll
        for (int nt = 0; nt < 4; nt++)
#pragma unroll
            for (int q = 0; q < 4; q++) acc[mt][nt][q] = 0.f;

    // staging lane mapping
    const int sr = tid >> 3, sc = (tid & 7) << 3;     // 32 rows per pass, 4 passes
    // ldmatrix lane mapping
    const int lrow = lane & 15;
    const int lk8  = (lane >> 4) << 3;
    const int brow = lane & 7;
    const int bk8  = ((lane >> 3) & 1) << 3;

    const uint32_t aOffH = (uint32_t)(wm*64 + lrow)*144 + (uint32_t)lk8*2;
    const uint32_t bOffH = 2u*GM_ARRB + (uint32_t)(wn*32 + brow)*144 + (uint32_t)bk8*2;

    const int nch = K >> 6;

    // ---- prologue: stage chunk 0 into stage 0 ----
#pragma unroll
    for (int i = 0; i < 4; i++) {
        int r = sr + i*32;
        uint32_t d = sb + (uint32_t)(r*GM_STRIDE + sc)*2;
        size_t ga = (size_t)(m0 + r) * K + sc;
        size_t gb = (size_t)(n0 + r) * K + sc;
        CP16(d,              Ahi + ga);
        CP16(d + GM_ARRB,    Alo + ga);
        CP16(d + 2u*GM_ARRB, Whi + gb);
        CP16(d + 3u*GM_ARRB, Wlo + gb);
    }
    CP_COMMIT();

    for (int ch = 0; ch < nch; ch++) {
        const int s = ch & 1;
        // issue next chunk into other stage (that buffer's readers finished at prev loop-end barrier)
        if (ch + 1 < nch) {
            const int k1 = (ch + 1) << 6;
            const uint32_t st = sb + (uint32_t)(1 - s)*GM_STAGE;
#pragma unroll
            for (int i = 0; i < 4; i++) {
                int r = sr + i*32;
                uint32_t d = st + (uint32_t)(r*GM_STRIDE + sc)*2;
                size_t ga = (size_t)(m0 + r) * K + k1 + sc;
                size_t gb = (size_t)(n0 + r) * K + k1 + sc;
                CP16(d,              Ahi + ga);
                CP16(d + GM_ARRB,    Alo + ga);
                CP16(d + 2u*GM_ARRB, Whi + gb);
                CP16(d + 3u*GM_ARRB, Wlo + gb);
            }
            CP_COMMIT();
            CP_WAIT1();     // chunk ch complete; ch+1 still in flight
        } else {
            CP_WAIT0();
        }
        __syncthreads();

        const uint32_t aBaseH = sb + (uint32_t)s*GM_STAGE + aOffH;
        const uint32_t aBaseL = aBaseH + GM_ARRB;
        const uint32_t bBaseH = sb + (uint32_t)s*GM_STAGE + bOffH;
        const uint32_t bBaseL = bBaseH + GM_ARRB;

#pragma unroll
        for (int ks = 0; ks < 4; ks++) {
            const uint32_t koff = (uint32_t)ks * 32;
            uint32_t bhf[4][2], blf[4][2];
#pragma unroll
            for (int nt = 0; nt < 4; nt++) {
                LDSM2(bhf[nt][0], bhf[nt][1], bBaseH + (uint32_t)nt*1152 + koff);
                LDSM2(blf[nt][0], blf[nt][1], bBaseL + (uint32_t)nt*1152 + koff);
            }
#pragma unroll
            for (int mt = 0; mt < 4; mt++) {
                uint32_t ahf[4], alf[4];
                LDSM4(ahf[0], ahf[1], ahf[2], ahf[3], aBaseH + (uint32_t)mt*2304 + koff);
                LDSM4(alf[0], alf[1], alf[2], alf[3], aBaseL + (uint32_t)mt*2304 + koff);
#pragma unroll
                for (int nt = 0; nt < 4; nt++) {
                    MMA16816(acc[mt][nt], ahf, bhf[nt]);
                    MMA16816(acc[mt][nt], ahf, blf[nt]);
                    MMA16816(acc[mt][nt], alf, bhf[nt]);
                }
            }
        }
        __syncthreads();   // stage s reads done before it is refilled in iter ch+2
    }

    const int g = lane >> 2, tg = lane & 3;
#pragma unroll
    for (int mt = 0; mt < 4; mt++) {
#pragma unroll
        for (int nt = 0; nt < 4; nt++) {
            int n   = n0 + wn*32 + nt*8 + tg*2;
            int mA  = m0 + wm*64 + mt*16 + g;
            int mB  = mA + 8;
            float b0v = bias[n], b1v = bias[n+1];
            float f0 = acc[mt][nt][0] + b0v, f1 = acc[mt][nt][1] + b1v;
            float f2 = acc[mt][nt][2] + b0v, f3 = acc[mt][nt][3] + b1v;
            if (Cf) {
                *(float2*)(Cf + (size_t)mA * N + n) = make_float2(f0, f1);
                *(float2*)(Cf + (size_t)mB * N + n) = make_float2(f2, f3);
            } else {
                float r0, r1, r2, r3;
                uint32_t hv0 = pk2hi(f0, f1, r0, r1);
                uint32_t hv1 = pk2hi(f2, f3, r2, r3);
                *(uint32_t*)(Chi + (size_t)mA * N + n) = hv0;
                *(uint32_t*)(Chi + (size_t)mB * N + n) = hv1;
                *(uint32_t*)(Clo + (size_t)mA * N + n) = pk2(r0, r1);
                *(uint32_t*)(Clo + (size_t)mB * N + n) = pk2(r2, r3);
            }
        }
    }
}

// ---------------- RoPE fused with hi/lo split: fp32 in -> bf16 hi/lo out ----------------
__global__ void rope_split_kernel(const float* __restrict__ t,
                                  __nv_bfloat16* __restrict__ hi,
                                  __nv_bfloat16* __restrict__ lo, int total)
{
    int idx = blockIdx.x * blockDim.x + threadIdx.x;
    if (idx >= total) return;
    int j   = idx & 31;
    int rem = idx >> 5;
    int bs  = rem >> 4;
    int s   = bs & (Sn - 1);
    float inv_freq = 1.0f / powf(10000.0f, (float)(2 * j) / (float)DRn);
    float ang = (float)s * inv_freq;
    float sv, cv;
    sincosf(ang, &sv, &cv);
    const float* p = t + (size_t)rem * DRn;
    float t1 = p[j], t2 = p[j + 32];
    float o1 = t1 * cv - t2 * sv;
    float o2 = t2 * cv + t1 * sv;
    __nv_bfloat16 h1 = __float2bfloat16(o1), h2 = __float2bfloat16(o2);
    __nv_bfloat16 l1 = __float2bfloat16(o1 - __bfloat162float(h1));
    __nv_bfloat16 l2 = __float2bfloat16(o2 - __bfloat162float(h2));
    size_t base = (size_t)rem * DRn;
    hi[base + j] = h1; hi[base + j + 32] = h2;
    lo[base + j] = l1; lo[base + j + 32] = l2;
}

// ---------------- tensor-core causal flash attention (bf16 split, fp32 softmax) ----------------
#define SQH 0
#define SQL 51200
#define SKH 102400
#define SKL 128000
#define SVH 153600
#define SVL 171008
#define ATTN_SMEM 188416

__global__ __launch_bounds__(256) void attn_mma_kernel(
    const __nv_bfloat16* __restrict__ quh, const __nv_bfloat16* __restrict__ qul,
    const __nv_bfloat16* __restrict__ qrh, const __nv_bfloat16* __restrict__ qrl,
    const __nv_bfloat16* __restrict__ kch, const __nv_bfloat16* __restrict__ kcl,
    const __nv_bfloat16* __restrict__ krh, const __nv_bfloat16* __restrict__ krl,
    const __nv_bfloat16* __restrict__ vhi, const __nv_bfloat16* __restrict__ vlo,
    __nv_bfloat16* __restrict__ ohi, __nv_bfloat16* __restrict__ olo)
{
    extern __shared__ char smraw[];
    const uint32_t sb = smem_u32(smraw);

    const int tid  = threadIdx.x;
    const int lane = tid & 31, w = tid >> 5;
    const int b  = blockIdx.x >> 4;
    const int h  = blockIdx.x & 15;
    const int qb = (gridDim.y - 1) - blockIdx.y;
    const int q0 = qb * 128;
    const float scale = rsqrtf((float)(DHn + DRn));
    const int g = lane >> 2, tg = lane & 3;

    // ---- stage Q [128][192] hi/lo (cp.async) ----
    for (int i = tid; i < 3072; i += 256) {
        int r = i / 24, c = i % 24;
        size_t m = (size_t)(b*Sn + q0 + r);
        const __nv_bfloat16 *ph, *pl;
        if (c < 16) { size_t off = m*(Hn*DHn) + h*DHn + c*8;       ph = quh + off; pl = qul + off; }
        else        { size_t off = m*(Hn*DRn) + h*DRn + (c-16)*8;  ph = qrh + off; pl = qrl + off; }
        uint32_t d = (uint32_t)(r*200 + c*8)*2;
        CP16(sb + SQH + d, ph);
        CP16(sb + SQL + d, pl);
    }
    CP_COMMIT();

    float o[16][4];
#pragma unroll
    for (int nf = 0; nf < 16; nf++)
#pragma unroll
        for (int q = 0; q < 4; q++) o[nf][q] = 0.f;
    float mst0 = -1e30f, mst1 = -1e30f, lst0 = 0.f, lst1 = 0.f;

    const uint32_t aQhB = sb + SQH + (uint32_t)(w*16 + (lane & 15))*400 + (uint32_t)((lane >> 4) & 1)*16;
    const uint32_t aQlB = aQhB + (SQL - SQH);
    const uint32_t bKhB = sb + SKH + (uint32_t)((lane & 7) + ((lane & 16) >> 1))*400 + (uint32_t)(lane & 8)*2;
    const uint32_t bKlB = bKhB + (SKL - SKH);
    const uint32_t vBH  = sb + SVH + (uint32_t)(lane & 15)*272 + (uint32_t)((lane >> 4) << 4);
    const uint32_t vBL  = vBH + (SVL - SVH);

    const int kb_end = 2*qb + 1;
    for (int kb = 0; kb <= kb_end; kb++) {
        const int k0 = kb * 64;
        __syncthreads();   // previous tile's readers done before overwrite
        // ---- stage K [64][192] hi/lo ----
        for (int i = tid; i < 1536; i += 256) {
            int r = i / 24, c = i % 24;
            size_t m = (size_t)(b*Sn + k0 + r);
            const __nv_bfloat16 *ph, *pl;
            if (c < 16) { size_t off = m*(Hn*DHn) + h*DHn + c*8;      ph = kch + off; pl = kcl + off; }
            else        { size_t off = m*(Hn*DRn) + h*DRn + (c-16)*8; ph = krh + off; pl = krl + off; }
            uint32_t d = (uint32_t)(r*200 + c*8)*2;
            CP16(sb + SKH + d, ph);
            CP16(sb + SKL + d, pl);
        }
        // ---- stage V [64][128] hi/lo ----
        for (int i = tid; i < 1024; i += 256) {
            int r = i >> 4, c = i & 15;
            size_t off = (size_t)(b*Sn + k0 + r)*(Hn*DHn) + h*DHn + c*8;
            uint32_t d = (uint32_t)(r*136 + c*8)*2;
            CP16(sb + SVH + d, vhi + off);
            CP16(sb + SVL + d, vlo + off);
        }
        CP_COMMIT();
        CP_WAIT0();
        __syncthreads();

        // ---- S = Q K^T (3-pass split) ----
        float s[8][4];
#pragma unroll
        for (int nt = 0; nt < 8; nt++)
#pragma unroll
            for (int q = 0; q < 4; q++) s[nt][q] = 0.f;

        for (int kc = 0; kc < 12; kc++) {
            uint32_t qh4[4], ql4[4];
            LDSM4(qh4[0], qh4[1], qh4[2], qh4[3], aQhB + (uint32_t)kc*32);
            LDSM4(ql4[0], ql4[1], ql4[2], ql4[3], aQlB + (uint32_t)kc*32);
#pragma unroll
            for (int np = 0; np < 4; np++) {
                uint32_t kh4[4], kl4[4];
                LDSM4(kh4[0], kh4[1], kh4[2], kh4[3], bKhB + (uint32_t)np*6400 + (uint32_t)kc*32);
                LDSM4(kl4[0], kl4[1], kl4[2], kl4[3], bKlB + (uint32_t)np*6400 + (uint32_t)kc*32);
                uint32_t bh0[2] = {kh4[0], kh4[1]}, bh1[2] = {kh4[2], kh4[3]};
                uint32_t bl0[2] = {kl4[0], kl4[1]}, bl1[2] = {kl4[2], kl4[3]};
                MMA16816(s[2*np],   qh4, bh0); MMA16816(s[2*np],   qh4, bl0); MMA16816(s[2*np],   ql4, bh0);
                MMA16816(s[2*np+1], qh4, bh1); MMA16816(s[2*np+1], qh4, bl1); MMA16816(s[2*np+1], ql4, bh1);
            }
        }

#pragma unroll
        for (int nt = 0; nt < 8; nt++)
#pragma unroll
            for (int q = 0; q < 4; q++) s[nt][q] *= scale;
        if (k0 + 63 > q0) {
            int rg = q0 + w*16 + g;
#pragma unroll
            for (int nt = 0; nt < 8; nt++)
#pragma unroll
                for (int q = 0; q < 2; q++) {
                    int col = k0 + nt*8 + tg*2 + q;
                    if (col > rg)     s[nt][q]     = -1e9f;
                    if (col > rg + 8) s[nt][q + 2] = -1e9f;
                }
        }

        // ---- online softmax ----
        float mg = -1e30f, mh = -1e30f;
#pragma unroll
        for (int nt = 0; nt < 8; nt++) {
            mg = fmaxf(mg, fmaxf(s[nt][0], s[nt][1]));
            mh = fmaxf(mh, fmaxf(s[nt][2], s[nt][3]));
        }
        mg = fmaxf(mg, __shfl_xor_sync(0xffffffffu, mg, 1));
        mg = fmaxf(mg, __shfl_xor_sync(0xffffffffu, mg, 2));
        mh = fmaxf(mh, __shfl_xor_sync(0xffffffffu, mh, 1));
        mh = fmaxf(mh, __shfl_xor_sync(0xffffffffu, mh, 2));
        float mng = fmaxf(mst0, mg), mnh = fmaxf(mst1, mh);
        float alg = __expf(mst0 - mng), alh = __expf(mst1 - mnh);
        float rsg = 0.f, rsh = 0.f;
#pragma unroll
        for (int nt = 0; nt < 8; nt++) {
            s[nt][0] = __expf(s[nt][0] - mng); rsg += s[nt][0];
            s[nt][1] = __expf(s[nt][1] - mng); rsg += s[nt][1];
            s[nt][2] = __expf(s[nt][2] - mnh); rsh += s[nt][2];
            s[nt][3] = __expf(s[nt][3] - mnh); rsh += s[nt][3];
        }
        rsg += __shfl_xor_sync(0xffffffffu, rsg, 1);
        rsg += __shfl_xor_sync(0xffffffffu, rsg, 2);
        rsh += __shfl_xor_sync(0xffffffffu, rsh, 1);
        rsh += __shfl_xor_sync(0xffffffffu, rsh, 2);
        lst0 = lst0 * alg + rsg; mst0 = mng;
        lst1 = lst1 * alh + rsh; mst1 = mnh;
#pragma unroll
        for (int nf = 0; nf < 16; nf++) {
            o[nf][0] *= alg; o[nf][1] *= alg;
            o[nf][2] *= alh; o[nf][3] *= alh;
        }

        // ---- pack P into A-frags (hi/lo) ----
        uint32_t pah[4][4], pal[4][4];
#pragma unroll
        for (int kcp = 0; kcp < 4; kcp++) {
            float r0, r1, r2, r3, r4, r5, r6, r7;
            pah[kcp][0] = pk2hi(s[2*kcp][0],   s[2*kcp][1],   r0, r1);
            pah[kcp][1] = pk2hi(s[2*kcp][2],   s[2*kcp][3],   r2, r3);
            pah[kcp][2] = pk2hi(s[2*kcp+1][0], s[2*kcp+1][1], r4, r5);
            pah[kcp][3] = pk2hi(s[2*kcp+1][2], s[2*kcp+1][3], r6, r7);
            pal[kcp][0] = pk2(r0, r1);
            pal[kcp][1] = pk2(r2, r3);
            pal[kcp][2] = pk2(r4, r5);
            pal[kcp][3] = pk2(r6, r7);
        }

        // ---- O += P V (3-pass split) ----
#pragma unroll
        for (int kcp = 0; kcp < 4; kcp++) {
            uint32_t koff = (uint32_t)kcp * 4352;
#pragma unroll
            for (int nq = 0; nq < 8; nq++) {
                uint32_t vh4[4], vl4[4];
                LDSM4T(vh4[0], vh4[1], vh4[2], vh4[3], vBH + koff + (uint32_t)nq*32);
                LDSM4T(vl4[0], vl4[1], vl4[2], vl4[3], vBL + koff + (uint32_t)nq*32);
                uint32_t bh0[2] = {vh4[0], vh4[1]}, bh1[2] = {vh4[2], vh4[3]};
                uint32_t bl0[2] = {vl4[0], vl4[1]}, bl1[2] = {vl4[2], vl4[3]};
                MMA16816(o[2*nq],   pah[kcp], bh0); MMA16816(o[2*nq],   pah[kcp], bl0); MMA16816(o[2*nq],   pal[kcp], bh0);
                MMA16816(o[2*nq+1], pah[kcp], bh1); MMA16816(o[2*nq+1], pah[kcp], bl1); MMA16816(o[2*nq+1], pal[kcp], bh1);
            }
        }
    }

    // ---- epilogue: write split hi/lo directly ----
    float ig = 1.f / lst0, ih = 1.f / lst1;
    int rgl = q0 + w*16 + g;
    size_t offg = (size_t)(b*Sn + rgl    )*(Hn*DHn) + h*DHn + tg*2;
    size_t offh = (size_t)(b*Sn + rgl + 8)*(Hn*DHn) + h*DHn + tg*2;
#pragma unroll
    for (int nf = 0; nf < 16; nf++) {
        float f0 = o[nf][0]*ig, f1 = o[nf][1]*ig;
        float f2 = o[nf][2]*ih, f3 = o[nf][3]*ih;
        float r0, r1, r2, r3;
        uint32_t hv0 = pk2hi(f0, f1, r0, r1);
        uint32_t hv1 = pk2hi(f2, f3, r2, r3);
        *(uint32_t*)(ohi + offg + nf*8) = hv0;
        *(uint32_t*)(olo + offg + nf*8) = pk2(r0, r1);
        *(uint32_t*)(ohi + offh + nf*8) = hv1;
        *(uint32_t*)(olo + offh + nf*8) = pk2(r2, r3);
    }
}

// ---------------- launch ----------------
static void run_split(const float* in, __nv_bfloat16* hi, __nv_bfloat16* lo, size_t n) {
    int n4 = (int)(n >> 2);
    split_kernel<<<(n4 + 255) / 256, 256>>>(in, hi, lo, n4);
}

extern "C" void kernel_launch(void* const* d_in, const int* in_sizes, int n_in,
                              void* d_out, int out_size)
{
    const float* x   = (const float*)d_in[0];
    const float* Wkd = (const float*)d_in[1];
    const float* bkd = (const float*)d_in[2];
    const float* Wqd = (const float*)d_in[3];
    const float* bqd = (const float*)d_in[4];
    const float* Wku = (const float*)d_in[5];
    const float* bku = (const float*)d_in[6];
    const float* Wvu = (const float*)d_in[7];
    const float* bvu = (const float*)d_in[8];
    const float* Wqu = (const float*)d_in[9];
    const float* bqu = (const float*)d_in[10];
    const float* Wkr = (const float*)d_in[11];
    const float* bkr = (const float*)d_in[12];
    const float* Wqr = (const float*)d_in[13];
    const float* bqr = (const float*)d_in[14];
    const float* Wo  = (const float*)d_in[15];
    const float* bo  = (const float*)d_in[16];

    float *kr, *qr;
    cudaGetSymbolAddress((void**)&kr, g_kr);
    cudaGetSymbolAddress((void**)&qr, g_qr);

    __nv_bfloat16 *x_hi, *x_lo, *kvc_hi, *kvc_lo, *qc_hi, *qc_lo, *at_hi, *at_lo;
    __nv_bfloat16 *qu_hi, *qu_lo, *kc_hi, *kc_lo, *v_hi, *v_lo, *krs_hi, *krs_lo, *qrs_hi, *qrs_lo;
    cudaGetSymbolAddress((void**)&x_hi,   g_x_hi);   cudaGetSymbolAddress((void**)&x_lo,   g_x_lo);
    cudaGetSymbolAddress((void**)&kvc_hi, g_kvc_hi); cudaGetSymbolAddress((void**)&kvc_lo, g_kvc_lo);
    cudaGetSymbolAddress((void**)&qc_hi,  g_qc_hi);  cudaGetSymbolAddress((void**)&qc_lo,  g_qc_lo);
    cudaGetSymbolAddress((void**)&at_hi,  g_at_hi);  cudaGetSymbolAddress((void**)&at_lo,  g_at_lo);
    cudaGetSymbolAddress((void**)&qu_hi,  g_qu_hi);  cudaGetSymbolAddress((void**)&qu_lo,  g_qu_lo);
    cudaGetSymbolAddress((void**)&kc_hi,  g_kc_hi);  cudaGetSymbolAddress((void**)&kc_lo,  g_kc_lo);
    cudaGetSymbolAddress((void**)&v_hi,   g_v_hi);   cudaGetSymbolAddress((void**)&v_lo,   g_v_lo);
    cudaGetSymbolAddress((void**)&krs_hi, g_krs_hi); cudaGetSymbolAddress((void**)&krs_lo, g_krs_lo);
    cudaGetSymbolAddress((void**)&qrs_hi, g_qrs_hi); cudaGetSymbolAddress((void**)&qrs_lo, g_qrs_lo);

    __nv_bfloat16 *Wkd_hi,*Wkd_lo,*Wqd_hi,*Wqd_lo,*Wku_hi,*Wku_lo,*Wvu_hi,*Wvu_lo;
    __nv_bfloat16 *Wqu_hi,*Wqu_lo,*Wkr_hi,*Wkr_lo,*Wqr_hi,*Wqr_lo,*Wo_hi,*Wo_lo;
    cudaGetSymbolAddress((void**)&Wkd_hi, g_Wkd_hi); cudaGetSymbolAddress((void**)&Wkd_lo, g_Wkd_lo);
    cudaGetSymbolAddress((void**)&Wqd_hi, g_Wqd_hi); cudaGetSymbolAddress((void**)&Wqd_lo, g_Wqd_lo);
    cudaGetSymbolAddress((void**)&Wku_hi, g_Wku_hi); cudaGetSymbolAddress((void**)&Wku_lo, g_Wku_lo);
    cudaGetSymbolAddress((void**)&Wvu_hi, g_Wvu_hi); cudaGetSymbolAddress((void**)&Wvu_lo, g_Wvu_lo);
    cudaGetSymbolAddress((void**)&Wqu_hi, g_Wqu_hi); cudaGetSymbolAddress((void**)&Wqu_lo, g_Wqu_lo);
    cudaGetSymbolAddress((void**)&Wkr_hi, g_Wkr_hi); cudaGetSymbolAddress((void**)&Wkr_lo, g_Wkr_lo);
    cudaGetSymbolAddress((void**)&Wqr_hi, g_Wqr_hi); cudaGetSymbolAddress((void**)&Wqr_lo, g_Wqr_lo);
    cudaGetSymbolAddress((void**)&Wo_hi,  g_Wo_hi);  cudaGetSymbolAddress((void**)&Wo_lo,  g_Wo_lo);

    // ---- split inputs ----
    run_split(x,   x_hi,   x_lo,   (size_t)Mn*Dn);
    run_split(Wkd, Wkd_hi, Wkd_lo, (size_t)DCKVn*Dn);
    run_split(Wqd, Wqd_hi, Wqd_lo, (size_t)DCQn*Dn);
    run_split(Wku, Wku_hi, Wku_lo, (size_t)Hn*DHn*DCKVn);
    run_split(Wvu, Wvu_hi, Wvu_lo, (size_t)Hn*DHn*DCKVn);
    run_split(Wqu, Wqu_hi, Wqu_lo, (size_t)Hn*DHn*DCQn);
    run_split(Wkr, Wkr_hi, Wkr_lo, (size_t)Hn*DRn*Dn);
    run_split(Wqr, Wqr_hi, Wqr_lo, (size_t)Hn*DRn*DCQn);
    run_split(Wo,  Wo_hi,  Wo_lo,  (size_t)Dn*Hn*DHn);

    cudaFuncSetAttribute(gemm_mma_kernel, cudaFuncAttributeMaxDynamicSharedMemorySize, GM_SMEM);
    dim3 thr(256);

    // ---- compress ----
    gemm_mma_kernel<<<dim3(DCKVn/128, Mn/128), thr, GM_SMEM>>>(
        x_hi, x_lo, Wkd_hi, Wkd_lo, bkd, nullptr, kvc_hi, kvc_lo, DCKVn, Dn);
    gemm_mma_kernel<<<dim3(DCQn/128, Mn/128), thr, GM_SMEM>>>(
        x_hi, x_lo, Wqd_hi, Wqd_lo, bqd, nullptr, qc_hi, qc_lo, DCQn, Dn);
    // ---- up-project ----
    gemm_mma_kernel<<<dim3((Hn*DHn)/128, Mn/128), thr, GM_SMEM>>>(
        kvc_hi, kvc_lo, Wku_hi, Wku_lo, bku, nullptr, kc_hi, kc_lo, Hn*DHn, DCKVn);
    gemm_mma_kernel<<<dim3((Hn*DHn)/128, Mn/128), thr, GM_SMEM>>>(
        kvc_hi, kvc_lo, Wvu_hi, Wvu_lo, bvu, nullptr, v_hi, v_lo, Hn*DHn, DCKVn);
    gemm_mma_kernel<<<dim3((Hn*DHn)/128, Mn/128), thr, GM_SMEM>>>(
        qc_hi, qc_lo, Wqu_hi, Wqu_lo, bqu, nullptr, qu_hi, qu_lo, Hn*DHn, DCQn);
    gemm_mma_kernel<<<dim3((Hn*DRn)/128, Mn/128), thr, GM_SMEM>>>(
        x_hi, x_lo, Wkr_hi, Wkr_lo, bkr, kr, nullptr, nullptr, Hn*DRn, Dn);
    gemm_mma_kernel<<<dim3((Hn*DRn)/128, Mn/128), thr, GM_SMEM>>>(
        qc_hi, qc_lo, Wqr_hi, Wqr_lo, bqr, qr, nullptr, nullptr, Hn*DRn, DCQn);

    // ---- rope + split (fused) ----
    int rope_total = Mn * Hn * (DRn / 2);
    rope_split_kernel<<<(rope_total + 255) / 256, 256>>>(kr, krs_hi, krs_lo, rope_total);
    rope_split_kernel<<<(rope_total + 255) / 256, 256>>>(qr, qrs_hi, qrs_lo, rope_total);

    // ---- attention (tensor cores, split output) ----
    cudaFuncSetAttribute(attn_mma_kernel, cudaFuncAttributeMaxDynamicSharedMemorySize, ATTN_SMEM);
    attn_mma_kernel<<<dim3(Bn*Hn, Sn/128), thr, ATTN_SMEM>>>(
        qu_hi, qu_lo, qrs_hi, qrs_lo, kc_hi, kc_lo, krs_hi, krs_lo, v_hi, v_lo, at_hi, at_lo);

    // ---- output projection ----
    gemm_mma_kernel<<<dim3(Dn/128, Mn/128), thr, GM_SMEM>>>(
        at_hi, at_lo, Wo_hi, Wo_lo, bo, (float*)d_out, nullptr, nullptr, Dn, Hn*DHn);
}

// round 16
// speedup vs baseline: 5.3117x; 1.0223x over previous
#include <cuda_runtime.h>
#include <cuda_bf16.h>
#include <math.h>
#include <stdint.h>

#define Bn 2
#define Sn 2048
#define Dn 2048
#define Hn 16
#define DHn 128
#define DRn 64
#define DCKVn 512
#define DCQn 1536
#define Mn (Bn*Sn)

// ---------------- scratch (device globals; no allocation allowed) ----------------
__device__ float g_kr  [(size_t)Mn*Hn*DRn];
__device__ float g_qr  [(size_t)Mn*Hn*DRn];
__device__ __nv_bfloat16 g_x_hi  [(size_t)Mn*Dn],      g_x_lo  [(size_t)Mn*Dn];
__device__ __nv_bfloat16 g_kvc_hi[(size_t)Mn*DCKVn],   g_kvc_lo[(size_t)Mn*DCKVn];
__device__ __nv_bfloat16 g_qc_hi [(size_t)Mn*DCQn],    g_qc_lo [(size_t)Mn*DCQn];
__device__ __nv_bfloat16 g_at_hi [(size_t)Mn*Hn*DHn],  g_at_lo [(size_t)Mn*Hn*DHn];
__device__ __nv_bfloat16 g_qu_hi [(size_t)Mn*Hn*DHn],  g_qu_lo [(size_t)Mn*Hn*DHn];
__device__ __nv_bfloat16 g_kc_hi [(size_t)Mn*Hn*DHn],  g_kc_lo [(size_t)Mn*Hn*DHn];
__device__ __nv_bfloat16 g_v_hi  [(size_t)Mn*Hn*DHn],  g_v_lo  [(size_t)Mn*Hn*DHn];
__device__ __nv_bfloat16 g_krs_hi[(size_t)Mn*Hn*DRn],  g_krs_lo[(size_t)Mn*Hn*DRn];
__device__ __nv_bfloat16 g_qrs_hi[(size_t)Mn*Hn*DRn],  g_qrs_lo[(size_t)Mn*Hn*DRn];
__device__ __nv_bfloat16 g_Wkd_hi[(size_t)DCKVn*Dn],     g_Wkd_lo[(size_t)DCKVn*Dn];
__device__ __nv_bfloat16 g_Wqd_hi[(size_t)DCQn*Dn],      g_Wqd_lo[(size_t)DCQn*Dn];
__device__ __nv_bfloat16 g_Wku_hi[(size_t)Hn*DHn*DCKVn], g_Wku_lo[(size_t)Hn*DHn*DCKVn];
__device__ __nv_bfloat16 g_Wvu_hi[(size_t)Hn*DHn*DCKVn], g_Wvu_lo[(size_t)Hn*DHn*DCKVn];
__device__ __nv_bfloat16 g_Wqu_hi[(size_t)Hn*DHn*DCQn],  g_Wqu_lo[(size_t)Hn*DHn*DCQn];
__device__ __nv_bfloat16 g_Wkr_hi[(size_t)Hn*DRn*Dn],    g_Wkr_lo[(size_t)Hn*DRn*Dn];
__device__ __nv_bfloat16 g_Wqr_hi[(size_t)Hn*DRn*DCQn],  g_Wqr_lo[(size_t)Hn*DRn*DCQn];
__device__ __nv_bfloat16 g_Wo_hi [(size_t)Dn*Hn*DHn],    g_Wo_lo [(size_t)Dn*Hn*DHn];

// ================= helpers =================
static __device__ __forceinline__ uint32_t smem_u32(const void* p) {
    uint32_t a;
    asm("{ .reg .u64 t; cvta.to.shared.u64 t, %1; cvt.u32.u64 %0, t; }" : "=r"(a) : "l"(p));
    return a;
}
#define LDSM4(r0,r1,r2,r3,addr) \
    asm volatile("ldmatrix.sync.aligned.m8n8.x4.shared.b16 {%0,%1,%2,%3}, [%4];" \
        : "=r"(r0),"=r"(r1),"=r"(r2),"=r"(r3) : "r"(addr))
#define LDSM4T(r0,r1,r2,r3,addr) \
    asm volatile("ldmatrix.sync.aligned.m8n8.x4.trans.shared.b16 {%0,%1,%2,%3}, [%4];" \
        : "=r"(r0),"=r"(r1),"=r"(r2),"=r"(r3) : "r"(addr))
#define LDSM2(r0,r1,addr) \
    asm volatile("ldmatrix.sync.aligned.m8n8.x2.shared.b16 {%0,%1}, [%2];" \
        : "=r"(r0),"=r"(r1) : "r"(addr))
#define MMA16816(d,a,b) \
    asm volatile("mma.sync.aligned.m16n8k16.row.col.f32.bf16.bf16.f32 " \
        "{%0,%1,%2,%3}, {%4,%5,%6,%7}, {%8,%9}, {%0,%1,%2,%3};" \
        : "+f"((d)[0]),"+f"((d)[1]),"+f"((d)[2]),"+f"((d)[3]) \
        : "r"((a)[0]),"r"((a)[1]),"r"((a)[2]),"r"((a)[3]), "r"((b)[0]),"r"((b)[1]))
#define CP16(dst, src) \
    asm volatile("cp.async.cg.shared.global [%0], [%1], 16;" :: "r"(dst), "l"(src))
#define CP_COMMIT() asm volatile("cp.async.commit_group;" ::: "memory")
#define CP_WAIT0()  asm volatile("cp.async.wait_group 0;" ::: "memory")
#define CP_WAIT1()  asm volatile("cp.async.wait_group 1;" ::: "memory")
#define CP_WAIT2()  asm volatile("cp.async.wait_group 2;" ::: "memory")

static __device__ __forceinline__ uint32_t pk2hi(float a, float b, float& ra, float& rb) {
    __nv_bfloat16 h0 = __float2bfloat16(a), h1 = __float2bfloat16(b);
    ra = a - __bfloat162float(h0);
    rb = b - __bfloat162float(h1);
    return (uint32_t)__bfloat16_as_ushort(h0) | ((uint32_t)__bfloat16_as_ushort(h1) << 16);
}
static __device__ __forceinline__ uint32_t pk2(float a, float b) {
    __nv_bfloat16 h0 = __float2bfloat16(a), h1 = __float2bfloat16(b);
    return (uint32_t)__bfloat16_as_ushort(h0) | ((uint32_t)__bfloat16_as_ushort(h1) << 16);
}

// ---------------- fp32 -> bf16 hi/lo split ----------------
__global__ void split_kernel(const float* __restrict__ in, __nv_bfloat16* __restrict__ hi,
                             __nv_bfloat16* __restrict__ lo, int n4)
{
    int i = blockIdx.x * blockDim.x + threadIdx.x;
    if (i >= n4) return;
    float4 a = ((const float4*)in)[i];
    float r0, r1, r2, r3;
    uint2 hv, lv;
    hv.x = pk2hi(a.x, a.y, r0, r1);
    hv.y = pk2hi(a.z, a.w, r2, r3);
    lv.x = pk2(r0, r1);
    lv.y = pk2(r2, r3);
    ((uint2*)hi)[i] = hv;
    ((uint2*)lo)[i] = lv;
}

// ---------------- mma.sync GEMM with 3-stage cp.async pipeline ----------------
#define GM_STRIDE 72
#define GM_ARRB   (128*GM_STRIDE*2)           // 18432 B per array
#define GM_STAGE  (4*GM_ARRB)                 // 73728 B per stage
#define GM_SMEM   (3*GM_STAGE)                // 221184 B

__global__ __launch_bounds__(256) void gemm_mma_kernel(
    const __nv_bfloat16* __restrict__ Ahi, const __nv_bfloat16* __restrict__ Alo,
    const __nv_bfloat16* __restrict__ Whi, const __nv_bfloat16* __restrict__ Wlo,
    const float* __restrict__ bias,
    float* __restrict__ Cf,
    __nv_bfloat16* __restrict__ Chi, __nv_bfloat16* __restrict__ Clo,
    int N, int K)
{
    extern __shared__ char smem[];
    const uint32_t sb = smem_u32(smem);

    const int tid  = threadIdx.x;
    const int lane = tid & 31, wid = tid >> 5;
    const int wm = wid & 1, wn = wid >> 1;
    const int n0 = blockIdx.x << 7, m0 = blockIdx.y << 7;

    float acc[4][4][4];
#pragma unroll
    for (int mt = 0; mt < 4; mt++)
#pragma unroll
        for (int nt = 0; nt < 4; nt++)
#pragma unroll
            for (int q = 0; q < 4; q++) acc[mt][nt][q] = 0.f;

    const int sr = tid >> 3, sc = (tid & 7) << 3;
    const int lrow = lane & 15;
    const int lk8  = (lane >> 4) << 3;
    const int brow = lane & 7;
    const int bk8  = ((lane >> 3) & 1) << 3;

    const uint32_t aOffH = (uint32_t)(wm*64 + lrow)*144 + (uint32_t)lk8*2;
    const uint32_t bOffH = 2u*GM_ARRB + (uint32_t)(wn*32 + brow)*144 + (uint32_t)bk8*2;

    const int nch = K >> 6;

    // ---- prologue: stage chunks 0,1 into stages 0,1 ----
#pragma unroll
    for (int pc = 0; pc < 2; pc++) {
        if (pc < nch) {
            const int kk = pc << 6;
            const uint32_t st = sb + (uint32_t)pc*GM_STAGE;
#pragma unroll
            for (int i = 0; i < 4; i++) {
                int r = sr + i*32;
                uint32_t d = st + (uint32_t)(r*GM_STRIDE + sc)*2;
                size_t ga = (size_t)(m0 + r) * K + kk + sc;
                size_t gb = (size_t)(n0 + r) * K + kk + sc;
                CP16(d,              Ahi + ga);
                CP16(d + GM_ARRB,    Alo + ga);
                CP16(d + 2u*GM_ARRB, Whi + gb);
                CP16(d + 3u*GM_ARRB, Wlo + gb);
            }
            CP_COMMIT();
        }
    }

    int s = 0, s2 = 2;   // s = stage of current chunk, s2 = stage to refill (ch+2)
    for (int ch = 0; ch < nch; ch++) {
        if (ch + 2 < nch) {
            const int kk = (ch + 2) << 6;
            const uint32_t st = sb + (uint32_t)s2*GM_STAGE;
#pragma unroll
            for (int i = 0; i < 4; i++) {
                int r = sr + i*32;
                uint32_t d = st + (uint32_t)(r*GM_STRIDE + sc)*2;
                size_t ga = (size_t)(m0 + r) * K + kk + sc;
                size_t gb = (size_t)(n0 + r) * K + kk + sc;
                CP16(d,              Ahi + ga);
                CP16(d + GM_ARRB,    Alo + ga);
                CP16(d + 2u*GM_ARRB, Whi + gb);
                CP16(d + 3u*GM_ARRB, Wlo + gb);
            }
            CP_COMMIT();
            CP_WAIT2();
        } else if (ch + 1 < nch) {
            CP_WAIT1();
        } else {
            CP_WAIT0();
        }
        __syncthreads();

        const uint32_t aBaseH = sb + (uint32_t)s*GM_STAGE + aOffH;
        const uint32_t aBaseL = aBaseH + GM_ARRB;
        const uint32_t bBaseH = sb + (uint32_t)s*GM_STAGE + bOffH;
        const uint32_t bBaseL = bBaseH + GM_ARRB;

#pragma unroll
        for (int ks = 0; ks < 4; ks++) {
            const uint32_t koff = (uint32_t)ks * 32;
            uint32_t bhf[4][2], blf[4][2];
#pragma unroll
            for (int nt = 0; nt < 4; nt++) {
                LDSM2(bhf[nt][0], bhf[nt][1], bBaseH + (uint32_t)nt*1152 + koff);
                LDSM2(blf[nt][0], blf[nt][1], bBaseL + (uint32_t)nt*1152 + koff);
            }
#pragma unroll
            for (int mt = 0; mt < 4; mt++) {
                uint32_t ahf[4], alf[4];
                LDSM4(ahf[0], ahf[1], ahf[2], ahf[3], aBaseH + (uint32_t)mt*2304 + koff);
                LDSM4(alf[0], alf[1], alf[2], alf[3], aBaseL + (uint32_t)mt*2304 + koff);
#pragma unroll
                for (int nt = 0; nt < 4; nt++) {
                    MMA16816(acc[mt][nt], ahf, bhf[nt]);
                    MMA16816(acc[mt][nt], ahf, blf[nt]);
                    MMA16816(acc[mt][nt], alf, bhf[nt]);
                }
            }
        }
        __syncthreads();   // stage s reads done before refill
        s  = (s  == 2) ? 0 : s  + 1;
        s2 = (s2 == 2) ? 0 : s2 + 1;
    }

    const int g = lane >> 2, tg = lane & 3;
#pragma unroll
    for (int mt = 0; mt < 4; mt++) {
#pragma unroll
        for (int nt = 0; nt < 4; nt++) {
            int n   = n0 + wn*32 + nt*8 + tg*2;
            int mA  = m0 + wm*64 + mt*16 + g;
            int mB  = mA + 8;
            float b0v = bias[n], b1v = bias[n+1];
            float f0 = acc[mt][nt][0] + b0v, f1 = acc[mt][nt][1] + b1v;
            float f2 = acc[mt][nt][2] + b0v, f3 = acc[mt][nt][3] + b1v;
            if (Cf) {
                *(float2*)(Cf + (size_t)mA * N + n) = make_float2(f0, f1);
                *(float2*)(Cf + (size_t)mB * N + n) = make_float2(f2, f3);
            } else {
                float r0, r1, r2, r3;
                uint32_t hv0 = pk2hi(f0, f1, r0, r1);
                uint32_t hv1 = pk2hi(f2, f3, r2, r3);
                *(uint32_t*)(Chi + (size_t)mA * N + n) = hv0;
                *(uint32_t*)(Chi + (size_t)mB * N + n) = hv1;
                *(uint32_t*)(Clo + (size_t)mA * N + n) = pk2(r0, r1);
                *(uint32_t*)(Clo + (size_t)mB * N + n) = pk2(r2, r3);
            }
        }
    }
}

// ---------------- RoPE fused with hi/lo split ----------------
__global__ void rope_split_kernel(const float* __restrict__ t,
                                  __nv_bfloat16* __restrict__ hi,
                                  __nv_bfloat16* __restrict__ lo, int total)
{
    int idx = blockIdx.x * blockDim.x + threadIdx.x;
    if (idx >= total) return;
    int j   = idx & 31;
    int rem = idx >> 5;
    int bs  = rem >> 4;
    int s   = bs & (Sn - 1);
    float inv_freq = 1.0f / powf(10000.0f, (float)(2 * j) / (float)DRn);
    float ang = (float)s * inv_freq;
    float sv, cv;
    sincosf(ang, &sv, &cv);
    const float* p = t + (size_t)rem * DRn;
    float t1 = p[j], t2 = p[j + 32];
    float o1 = t1 * cv - t2 * sv;
    float o2 = t2 * cv + t1 * sv;
    __nv_bfloat16 h1 = __float2bfloat16(o1), h2 = __float2bfloat16(o2);
    __nv_bfloat16 l1 = __float2bfloat16(o1 - __bfloat162float(h1));
    __nv_bfloat16 l2 = __float2bfloat16(o2 - __bfloat162float(h2));
    size_t base = (size_t)rem * DRn;
    hi[base + j] = h1; hi[base + j + 32] = h2;
    lo[base + j] = l1; lo[base + j + 32] = l2;
}

// ---------------- tensor-core causal flash attention, V double-buffered ----------------
#define SQH 0
#define SQL 51200
#define SKH 102400
#define SKL 128000
#define SV0H 153600
#define SV0L 171008
#define SV1H 188416
#define SV1L 205824
#define ATTN_SMEM 223232

__global__ __launch_bounds__(256) void attn_mma_kernel(
    const __nv_bfloat16* __restrict__ quh, const __nv_bfloat16* __restrict__ qul,
    const __nv_bfloat16* __restrict__ qrh, const __nv_bfloat16* __restrict__ qrl,
    const __nv_bfloat16* __restrict__ kch, const __nv_bfloat16* __restrict__ kcl,
    const __nv_bfloat16* __restrict__ krh, const __nv_bfloat16* __restrict__ krl,
    const __nv_bfloat16* __restrict__ vhi, const __nv_bfloat16* __restrict__ vlo,
    __nv_bfloat16* __restrict__ ohi, __nv_bfloat16* __restrict__ olo)
{
    extern __shared__ char smraw[];
    const uint32_t sb = smem_u32(smraw);

    const int tid  = threadIdx.x;
    const int lane = tid & 31, w = tid >> 5;
    const int b  = blockIdx.x >> 4;
    const int h  = blockIdx.x & 15;
    const int qb = (gridDim.y - 1) - blockIdx.y;
    const int q0 = qb * 128;
    const float scale = rsqrtf((float)(DHn + DRn));
    const int g = lane >> 2, tg = lane & 3;

    // ---- stage Q [128][192] hi/lo ----
    for (int i = tid; i < 3072; i += 256) {
        int r = i / 24, c = i % 24;
        size_t m = (size_t)(b*Sn + q0 + r);
        const __nv_bfloat16 *ph, *pl;
        if (c < 16) { size_t off = m*(Hn*DHn) + h*DHn + c*8;       ph = quh + off; pl = qul + off; }
        else        { size_t off = m*(Hn*DRn) + h*DRn + (c-16)*8;  ph = qrh + off; pl = qrl + off; }
        uint32_t d = (uint32_t)(r*200 + c*8)*2;
        CP16(sb + SQH + d, ph);
        CP16(sb + SQL + d, pl);
    }
    CP_COMMIT();

    // ---- stage K(0) + V(0) (buffer 0) ----
    {
        for (int i = tid; i < 1536; i += 256) {
            int r = i / 24, c = i % 24;
            size_t m = (size_t)(b*Sn + r);
            const __nv_bfloat16 *ph, *pl;
            if (c < 16) { size_t off = m*(Hn*DHn) + h*DHn + c*8;      ph = kch + off; pl = kcl + off; }
            else        { size_t off = m*(Hn*DRn) + h*DRn + (c-16)*8; ph = krh + off; pl = krl + off; }
            uint32_t d = (uint32_t)(r*200 + c*8)*2;
            CP16(sb + SKH + d, ph);
            CP16(sb + SKL + d, pl);
        }
        for (int i = tid; i < 1024; i += 256) {
            int r = i >> 4, c = i & 15;
            size_t off = (size_t)(b*Sn + r)*(Hn*DHn) + h*DHn + c*8;
            uint32_t d = (uint32_t)(r*136 + c*8)*2;
            CP16(sb + SV0H + d, vhi + off);
            CP16(sb + SV0L + d, vlo + off);
        }
        CP_COMMIT();
    }

    float o[16][4];
#pragma unroll
    for (int nf = 0; nf < 16; nf++)
#pragma unroll
        for (int q = 0; q < 4; q++) o[nf][q] = 0.f;
    float mst0 = -1e30f, mst1 = -1e30f, lst0 = 0.f, lst1 = 0.f;

    const uint32_t aQhB = sb + SQH + (uint32_t)(w*16 + (lane & 15))*400 + (uint32_t)((lane >> 4) & 1)*16;
    const uint32_t aQlB = aQhB + (SQL - SQH);
    const uint32_t bKhB = sb + SKH + (uint32_t)((lane & 7) + ((lane & 16) >> 1))*400 + (uint32_t)(lane & 8)*2;
    const uint32_t bKlB = bKhB + (SKL - SKH);
    const uint32_t vLaneOff = (uint32_t)(lane & 15)*272 + (uint32_t)((lane >> 4) << 4);

    const int kb_end = 2*qb + 1;
    for (int kb = 0; kb <= kb_end; kb++) {
        const int k0 = kb * 64;
        CP_WAIT0();          // K(kb) + V(kb) (and Q on kb=0) complete
        __syncthreads();

        // ---- S = Q K^T (3-pass split) ----
        float s[8][4];
#pragma unroll
        for (int nt = 0; nt < 8; nt++)
#pragma unroll
            for (int q = 0; q < 4; q++) s[nt][q] = 0.f;

        for (int kc = 0; kc < 12; kc++) {
            uint32_t qh4[4], ql4[4];
            LDSM4(qh4[0], qh4[1], qh4[2], qh4[3], aQhB + (uint32_t)kc*32);
            LDSM4(ql4[0], ql4[1], ql4[2], ql4[3], aQlB + (uint32_t)kc*32);
#pragma unroll
            for (int np = 0; np < 4; np++) {
                uint32_t kh4[4], kl4[4];
                LDSM4(kh4[0], kh4[1], kh4[2], kh4[3], bKhB + (uint32_t)np*6400 + (uint32_t)kc*32);
                LDSM4(kl4[0], kl4[1], kl4[2], kl4[3], bKlB + (uint32_t)np*6400 + (uint32_t)kc*32);
                uint32_t bh0[2] = {kh4[0], kh4[1]}, bh1[2] = {kh4[2], kh4[3]};
                uint32_t bl0[2] = {kl4[0], kl4[1]}, bl1[2] = {kl4[2], kl4[3]};
                MMA16816(s[2*np],   qh4, bh0); MMA16816(s[2*np],   qh4, bl0); MMA16816(s[2*np],   ql4, bh0);
                MMA16816(s[2*np+1], qh4, bh1); MMA16816(s[2*np+1], qh4, bl1); MMA16816(s[2*np+1], ql4, bh1);
            }
        }
        __syncthreads();     // all warps done reading K buffer

        // ---- prefetch K(kb+1) + V(kb+1) while softmax/PV run ----
        if (kb + 1 <= kb_end) {
            const int k1 = (kb + 1) * 64;
            const uint32_t svh = ((kb + 1) & 1) ? SV1H : SV0H;
            const uint32_t svl = ((kb + 1) & 1) ? SV1L : SV0L;
            for (int i = tid; i < 1536; i += 256) {
                int r = i / 24, c = i % 24;
                size_t m = (size_t)(b*Sn + k1 + r);
                const __nv_bfloat16 *ph, *pl;
                if (c < 16) { size_t off = m*(Hn*DHn) + h*DHn + c*8;      ph = kch + off; pl = kcl + off; }
                else        { size_t off = m*(Hn*DRn) + h*DRn + (c-16)*8; ph = krh + off; pl = krl + off; }
                uint32_t d = (uint32_t)(r*200 + c*8)*2;
                CP16(sb + SKH + d, ph);
                CP16(sb + SKL + d, pl);
            }
            for (int i = tid; i < 1024; i += 256) {
                int r = i >> 4, c = i & 15;
                size_t off = (size_t)(b*Sn + k1 + r)*(Hn*DHn) + h*DHn + c*8;
                uint32_t d = (uint32_t)(r*136 + c*8)*2;
                CP16(sb + svh + d, vhi + off);
                CP16(sb + svl + d, vlo + off);
            }
            CP_COMMIT();
        }

        // ---- scale + causal mask ----
#pragma unroll
        for (int nt = 0; nt < 8; nt++)
#pragma unroll
            for (int q = 0; q < 4; q++) s[nt][q] *= scale;
        if (k0 + 63 > q0) {
            int rg = q0 + w*16 + g;
#pragma unroll
            for (int nt = 0; nt < 8; nt++)
#pragma unroll
                for (int q = 0; q < 2; q++) {
                    int col = k0 + nt*8 + tg*2 + q;
                    if (col > rg)     s[nt][q]     = -1e9f;
                    if (col > rg + 8) s[nt][q + 2] = -1e9f;
                }
        }

        // ---- online softmax ----
        float mg = -1e30f, mh = -1e30f;
#pragma unroll
        for (int nt = 0; nt < 8; nt++) {
            mg = fmaxf(mg, fmaxf(s[nt][0], s[nt][1]));
            mh = fmaxf(mh, fmaxf(s[nt][2], s[nt][3]));
        }
        mg = fmaxf(mg, __shfl_xor_sync(0xffffffffu, mg, 1));
        mg = fmaxf(mg, __shfl_xor_sync(0xffffffffu, mg, 2));
        mh = fmaxf(mh, __shfl_xor_sync(0xffffffffu, mh, 1));
        mh = fmaxf(mh, __shfl_xor_sync(0xffffffffu, mh, 2));
        float mng = fmaxf(mst0, mg), mnh = fmaxf(mst1, mh);
        float alg = __expf(mst0 - mng), alh = __expf(mst1 - mnh);
        float rsg = 0.f, rsh = 0.f;
#pragma unroll
        for (int nt = 0; nt < 8; nt++) {
            s[nt][0] = __expf(s[nt][0] - mng); rsg += s[nt][0];
            s[nt][1] = __expf(s[nt][1] - mng); rsg += s[nt][1];
            s[nt][2] = __expf(s[nt][2] - mnh); rsh += s[nt][2];
            s[nt][3] = __expf(s[nt][3] - mnh); rsh += s[nt][3];
        }
        rsg += __shfl_xor_sync(0xffffffffu, rsg, 1);
        rsg += __shfl_xor_sync(0xffffffffu, rsg, 2);
        rsh += __shfl_xor_sync(0xffffffffu, rsh, 1);
        rsh += __shfl_xor_sync(0xffffffffu, rsh, 2);
        lst0 = lst0 * alg + rsg; mst0 = mng;
        lst1 = lst1 * alh + rsh; mst1 = mnh;
#pragma unroll
        for (int nf = 0; nf < 16; nf++) {
            o[nf][0] *= alg; o[nf][1] *= alg;
            o[nf][2] *= alh; o[nf][3] *= alh;
        }

        // ---- pack P into A-frags (hi/lo) ----
        uint32_t pah[4][4], pal[4][4];
#pragma unroll
        for (int kcp = 0; kcp < 4; kcp++) {
            float r0, r1, r2, r3, r4, r5, r6, r7;
            pah[kcp][0] = pk2hi(s[2*kcp][0],   s[2*kcp][1],   r0, r1);
            pah[kcp][1] = pk2hi(s[2*kcp][2],   s[2*kcp][3],   r2, r3);
            pah[kcp][2] = pk2hi(s[2*kcp+1][0], s[2*kcp+1][1], r4, r5);
            pah[kcp][3] = pk2hi(s[2*kcp+1][2], s[2*kcp+1][3], r6, r7);
            pal[kcp][0] = pk2(r0, r1);
            pal[kcp][1] = pk2(r2, r3);
            pal[kcp][2] = pk2(r4, r5);
            pal[kcp][3] = pk2(r6, r7);
        }

        // ---- O += P V (3-pass split), V buffer kb&1 ----
        const uint32_t vBH = sb + ((kb & 1) ? SV1H : SV0H) + vLaneOff;
        const uint32_t vBL = sb + ((kb & 1) ? SV1L : SV0L) + vLaneOff;
#pragma unroll
        for (int kcp = 0; kcp < 4; kcp++) {
            uint32_t koff = (uint32_t)kcp * 4352;
#pragma unroll
            for (int nq = 0; nq < 8; nq++) {
                uint32_t vh4[4], vl4[4];
                LDSM4T(vh4[0], vh4[1], vh4[2], vh4[3], vBH + koff + (uint32_t)nq*32);
                LDSM4T(vl4[0], vl4[1], vl4[2], vl4[3], vBL + koff + (uint32_t)nq*32);
                uint32_t bh0[2] = {vh4[0], vh4[1]}, bh1[2] = {vh4[2], vh4[3]};
                uint32_t bl0[2] = {vl4[0], vl4[1]}, bl1[2] = {vl4[2], vl4[3]};
                MMA16816(o[2*nq],   pah[kcp], bh0); MMA16816(o[2*nq],   pah[kcp], bl0); MMA16816(o[2*nq],   pal[kcp], bh0);
                MMA16816(o[2*nq+1], pah[kcp], bh1); MMA16816(o[2*nq+1], pah[kcp], bl1); MMA16816(o[2*nq+1], pal[kcp], bh1);
            }
        }
    }

    // ---- epilogue: write split hi/lo directly ----
    float ig = 1.f / lst0, ih = 1.f / lst1;
    int rgl = q0 + w*16 + g;
    size_t offg = (size_t)(b*Sn + rgl    )*(Hn*DHn) + h*DHn + tg*2;
    size_t offh = (size_t)(b*Sn + rgl + 8)*(Hn*DHn) + h*DHn + tg*2;
#pragma unroll
    for (int nf = 0; nf < 16; nf++) {
        float f0 = o[nf][0]*ig, f1 = o[nf][1]*ig;
        float f2 = o[nf][2]*ih, f3 = o[nf][3]*ih;
        float r0, r1, r2, r3;
        uint32_t hv0 = pk2hi(f0, f1, r0, r1);
        uint32_t hv1 = pk2hi(f2, f3, r2, r3);
        *(uint32_t*)(ohi + offg + nf*8) = hv0;
        *(uint32_t*)(olo + offg + nf*8) = pk2(r0, r1);
        *(uint32_t*)(ohi + offh + nf*8) = hv1;
        *(uint32_t*)(olo + offh + nf*8) = pk2(r2, r3);
    }
}

// ---------------- launch ----------------
static void run_split(const float* in, __nv_bfloat16* hi, __nv_bfloat16* lo, size_t n) {
    int n4 = (int)(n >> 2);
    split_kernel<<<(n4 + 255) / 256, 256>>>(in, hi, lo, n4);
}

extern "C" void kernel_launch(void* const* d_in, const int* in_sizes, int n_in,
                              void* d_out, int out_size)
{
    const float* x   = (const float*)d_in[0];
    const float* Wkd = (const float*)d_in[1];
    const float* bkd = (const float*)d_in[2];
    const float* Wqd = (const float*)d_in[3];
    const float* bqd = (const float*)d_in[4];
    const float* Wku = (const float*)d_in[5];
    const float* bku = (const float*)d_in[6];
    const float* Wvu = (const float*)d_in[7];
    const float* bvu = (const float*)d_in[8];
    const float* Wqu = (const float*)d_in[9];
    const float* bqu = (const float*)d_in[10];
    const float* Wkr = (const float*)d_in[11];
    const float* bkr = (const float*)d_in[12];
    const float* Wqr = (const float*)d_in[13];
    const float* bqr = (const float*)d_in[14];
    const float* Wo  = (const float*)d_in[15];
    const float* bo  = (const float*)d_in[16];

    float *kr, *qr;
    cudaGetSymbolAddress((void**)&kr, g_kr);
    cudaGetSymbolAddress((void**)&qr, g_qr);

    __nv_bfloat16 *x_hi, *x_lo, *kvc_hi, *kvc_lo, *qc_hi, *qc_lo, *at_hi, *at_lo;
    __nv_bfloat16 *qu_hi, *qu_lo, *kc_hi, *kc_lo, *v_hi, *v_lo, *krs_hi, *krs_lo, *qrs_hi, *qrs_lo;
    cudaGetSymbolAddress((void**)&x_hi,   g_x_hi);   cudaGetSymbolAddress((void**)&x_lo,   g_x_lo);
    cudaGetSymbolAddress((void**)&kvc_hi, g_kvc_hi); cudaGetSymbolAddress((void**)&kvc_lo, g_kvc_lo);
    cudaGetSymbolAddress((void**)&qc_hi,  g_qc_hi);  cudaGetSymbolAddress((void**)&qc_lo,  g_qc_lo);
    cudaGetSymbolAddress((void**)&at_hi,  g_at_hi);  cudaGetSymbolAddress((void**)&at_lo,  g_at_lo);
    cudaGetSymbolAddress((void**)&qu_hi,  g_qu_hi);  cudaGetSymbolAddress((void**)&qu_lo,  g_qu_lo);
    cudaGetSymbolAddress((void**)&kc_hi,  g_kc_hi);  cudaGetSymbolAddress((void**)&kc_lo,  g_kc_lo);
    cudaGetSymbolAddress((void**)&v_hi,   g_v_hi);   cudaGetSymbolAddress((void**)&v_lo,   g_v_lo);
    cudaGetSymbolAddress((void**)&krs_hi, g_krs_hi); cudaGetSymbolAddress((void**)&krs_lo, g_krs_lo);
    cudaGetSymbolAddress((void**)&qrs_hi, g_qrs_hi); cudaGetSymbolAddress((void**)&qrs_lo, g_qrs_lo);

    __nv_bfloat16 *Wkd_hi,*Wkd_lo,*Wqd_hi,*Wqd_lo,*Wku_hi,*Wku_lo,*Wvu_hi,*Wvu_lo;
    __nv_bfloat16 *Wqu_hi,*Wqu_lo,*Wkr_hi,*Wkr_lo,*Wqr_hi,*Wqr_lo,*Wo_hi,*Wo_lo;
    cudaGetSymbolAddress((void**)&Wkd_hi, g_Wkd_hi); cudaGetSymbolAddress((void**)&Wkd_lo, g_Wkd_lo);
    cudaGetSymbolAddress((void**)&Wqd_hi, g_Wqd_hi); cudaGetSymbolAddress((void**)&Wqd_lo, g_Wqd_lo);
    cudaGetSymbolAddress((void**)&Wku_hi, g_Wku_hi); cudaGetSymbolAddress((void**)&Wku_lo, g_Wku_lo);
    cudaGetSymbolAddress((void**)&Wvu_hi, g_Wvu_hi); cudaGetSymbolAddress((void**)&Wvu_lo, g_Wvu_lo);
    cudaGetSymbolAddress((void**)&Wqu_hi, g_Wqu_hi); cudaGetSymbolAddress((void**)&Wqu_lo, g_Wqu_lo);
    cudaGetSymbolAddress((void**)&Wkr_hi, g_Wkr_hi); cudaGetSymbolAddress((void**)&Wkr_lo, g_Wkr_lo);
    cudaGetSymbolAddress((void**)&Wqr_hi, g_Wqr_hi); cudaGetSymbolAddress((void**)&Wqr_lo, g_Wqr_lo);
    cudaGetSymbolAddress((void**)&Wo_hi,  g_Wo_hi);  cudaGetSymbolAddress((void**)&Wo_lo,  g_Wo_lo);

    // ---- split inputs ----
    run_split(x,   x_hi,   x_lo,   (size_t)Mn*Dn);
    run_split(Wkd, Wkd_hi, Wkd_lo, (size_t)DCKVn*Dn);
    run_split(Wqd, Wqd_hi, Wqd_lo, (size_t)DCQn*Dn);
    run_split(Wku, Wku_hi, Wku_lo, (size_t)Hn*DHn*DCKVn);
    run_split(Wvu, Wvu_hi, Wvu_lo, (size_t)Hn*DHn*DCKVn);
    run_split(Wqu, Wqu_hi, Wqu_lo, (size_t)Hn*DHn*DCQn);
    run_split(Wkr, Wkr_hi, Wkr_lo, (size_t)Hn*DRn*Dn);
    run_split(Wqr, Wqr_hi, Wqr_lo, (size_t)Hn*DRn*DCQn);
    run_split(Wo,  Wo_hi,  Wo_lo,  (size_t)Dn*Hn*DHn);

    cudaFuncSetAttribute(gemm_mma_kernel, cudaFuncAttributeMaxDynamicSharedMemorySize, GM_SMEM);
    dim3 thr(256);

    // ---- compress ----
    gemm_mma_kernel<<<dim3(DCKVn/128, Mn/128), thr, GM_SMEM>>>(
        x_hi, x_lo, Wkd_hi, Wkd_lo, bkd, nullptr, kvc_hi, kvc_lo, DCKVn, Dn);
    gemm_mma_kernel<<<dim3(DCQn/128, Mn/128), thr, GM_SMEM>>>(
        x_hi, x_lo, Wqd_hi, Wqd_lo, bqd, nullptr, qc_hi, qc_lo, DCQn, Dn);
    // ---- up-project ----
    gemm_mma_kernel<<<dim3((Hn*DHn)/128, Mn/128), thr, GM_SMEM>>>(
        kvc_hi, kvc_lo, Wku_hi, Wku_lo, bku, nullptr, kc_hi, kc_lo, Hn*DHn, DCKVn);
    gemm_mma_kernel<<<dim3((Hn*DHn)/128, Mn/128), thr, GM_SMEM>>>(
        kvc_hi, kvc_lo, Wvu_hi, Wvu_lo, bvu, nullptr, v_hi, v_lo, Hn*DHn, DCKVn);
    gemm_mma_kernel<<<dim3((Hn*DHn)/128, Mn/128), thr, GM_SMEM>>>(
        qc_hi, qc_lo, Wqu_hi, Wqu_lo, bqu, nullptr, qu_hi, qu_lo, Hn*DHn, DCQn);
    gemm_mma_kernel<<<dim3((Hn*DRn)/128, Mn/128), thr, GM_SMEM>>>(
        x_hi, x_lo, Wkr_hi, Wkr_lo, bkr, kr, nullptr, nullptr, Hn*DRn, Dn);
    gemm_mma_kernel<<<dim3((Hn*DRn)/128, Mn/128), thr, GM_SMEM>>>(
        qc_hi, qc_lo, Wqr_hi, Wqr_lo, bqr, qr, nullptr, nullptr, Hn*DRn, DCQn);

    // ---- rope + split (fused) ----
    int rope_total = Mn * Hn * (DRn / 2);
    rope_split_kernel<<<(rope_total + 255) / 256, 256>>>(kr, krs_hi, krs_lo, rope_total);
    rope_split_kernel<<<(rope_total + 255) / 256, 256>>>(qr, qrs_hi, qrs_lo, rope_total);

    // ---- attention (tensor cores, pipelined) ----
    cudaFuncSetAttribute(attn_mma_kernel, cudaFuncAttributeMaxDynamicSharedMemorySize, ATTN_SMEM);
    attn_mma_kernel<<<dim3(Bn*Hn, Sn/128), thr, ATTN_SMEM>>>(
        qu_hi, qu_lo, qrs_hi, qrs_lo, kc_hi, kc_lo, krs_hi, krs_lo, v_hi, v_lo, at_hi, at_lo);

    // ---- output projection ----
    gemm_mma_kernel<<<dim3(Dn/128, Mn/128), thr, GM_SMEM>>>(
        at_hi, at_lo, Wo_hi, Wo_lo, bo, (float*)d_out, nullptr, nullptr, Dn, Hn*DHn);
}

// round 17
// speedup vs baseline: 6.9920x; 1.3163x over previous
#include <cuda_runtime.h>
#include <cuda_fp16.h>
#include <math.h>
#include <stdint.h>

#define Bn 2
#define Sn 2048
#define Dn 2048
#define Hn 16
#define DHn 128
#define DRn 64
#define DCKVn 512
#define DCQn 1536
#define Mn (Bn*Sn)

// ---------------- scratch (device globals; no allocation allowed) ----------------
__device__ float g_kr  [(size_t)Mn*Hn*DRn];
__device__ float g_qr  [(size_t)Mn*Hn*DRn];
// fp16 hi/lo split A-operands
__device__ __half g_x_hi  [(size_t)Mn*Dn],      g_x_lo  [(size_t)Mn*Dn];
__device__ __half g_kvc_hi[(size_t)Mn*DCKVn],   g_kvc_lo[(size_t)Mn*DCKVn];
__device__ __half g_qc_hi [(size_t)Mn*DCQn],    g_qc_lo [(size_t)Mn*DCQn];
__device__ __half g_at_hi [(size_t)Mn*Hn*DHn],  g_at_lo [(size_t)Mn*Hn*DHn];
__device__ __half g_qu_hi [(size_t)Mn*Hn*DHn],  g_qu_lo [(size_t)Mn*Hn*DHn];
__device__ __half g_qrs_hi[(size_t)Mn*Hn*DRn],  g_qrs_lo[(size_t)Mn*Hn*DRn];
// fp16 single B-operands
__device__ __half g_kc_h  [(size_t)Mn*Hn*DHn];
__device__ __half g_v_h   [(size_t)Mn*Hn*DHn];
__device__ __half g_krs_h [(size_t)Mn*Hn*DRn];
// fp16 weights (single)
__device__ __half g_Wkd_h[(size_t)DCKVn*Dn];
__device__ __half g_Wqd_h[(size_t)DCQn*Dn];
__device__ __half g_Wku_h[(size_t)Hn*DHn*DCKVn];
__device__ __half g_Wvu_h[(size_t)Hn*DHn*DCKVn];
__device__ __half g_Wqu_h[(size_t)Hn*DHn*DCQn];
__device__ __half g_Wkr_h[(size_t)Hn*DRn*Dn];
__device__ __half g_Wqr_h[(size_t)Hn*DRn*DCQn];
__device__ __half g_Wo_h [(size_t)Dn*Hn*DHn];

// ================= helpers =================
static __device__ __forceinline__ uint32_t smem_u32(const void* p) {
    uint32_t a;
    asm("{ .reg .u64 t; cvta.to.shared.u64 t, %1; cvt.u32.u64 %0, t; }" : "=r"(a) : "l"(p));
    return a;
}
#define LDSM4(r0,r1,r2,r3,addr) \
    asm volatile("ldmatrix.sync.aligned.m8n8.x4.shared.b16 {%0,%1,%2,%3}, [%4];" \
        : "=r"(r0),"=r"(r1),"=r"(r2),"=r"(r3) : "r"(addr))
#define LDSM4T(r0,r1,r2,r3,addr) \
    asm volatile("ldmatrix.sync.aligned.m8n8.x4.trans.shared.b16 {%0,%1,%2,%3}, [%4];" \
        : "=r"(r0),"=r"(r1),"=r"(r2),"=r"(r3) : "r"(addr))
#define LDSM2(r0,r1,addr) \
    asm volatile("ldmatrix.sync.aligned.m8n8.x2.shared.b16 {%0,%1}, [%2];" \
        : "=r"(r0),"=r"(r1) : "r"(addr))
#define MMA16816(d,a,b) \
    asm volatile("mma.sync.aligned.m16n8k16.row.col.f32.f16.f16.f32 " \
        "{%0,%1,%2,%3}, {%4,%5,%6,%7}, {%8,%9}, {%0,%1,%2,%3};" \
        : "+f"((d)[0]),"+f"((d)[1]),"+f"((d)[2]),"+f"((d)[3]) \
        : "r"((a)[0]),"r"((a)[1]),"r"((a)[2]),"r"((a)[3]), "r"((b)[0]),"r"((b)[1]))
#define CP16(dst, src) \
    asm volatile("cp.async.cg.shared.global [%0], [%1], 16;" :: "r"(dst), "l"(src))
#define CP_COMMIT() asm volatile("cp.async.commit_group;" ::: "memory")
#define CP_WAIT0()  asm volatile("cp.async.wait_group 0;" ::: "memory")
#define CP_WAIT1()  asm volatile("cp.async.wait_group 1;" ::: "memory")
#define CP_WAIT2()  asm volatile("cp.async.wait_group 2;" ::: "memory")

static __device__ __forceinline__ uint32_t hpk2hi(float a, float b, float& ra, float& rb) {
    __half h0 = __float2half_rn(a), h1 = __float2half_rn(b);
    ra = a - __half2float(h0);
    rb = b - __half2float(h1);
    return (uint32_t)__half_as_ushort(h0) | ((uint32_t)__half_as_ushort(h1) << 16);
}
static __device__ __forceinline__ uint32_t hpk2(float a, float b) {
    __half h0 = __float2half_rn(a), h1 = __float2half_rn(b);
    return (uint32_t)__half_as_ushort(h0) | ((uint32_t)__half_as_ushort(h1) << 16);
}

// ---------------- fp32 -> fp16 hi/lo split ----------------
__global__ void split_kernel(const float* __restrict__ in, __half* __restrict__ hi,
                             __half* __restrict__ lo, int n4)
{
    int i = blockIdx.x * blockDim.x + threadIdx.x;
    if (i >= n4) return;
    float4 a = ((const float4*)in)[i];
    float r0, r1, r2, r3;
    uint2 hv, lv;
    hv.x = hpk2hi(a.x, a.y, r0, r1);
    hv.y = hpk2hi(a.z, a.w, r2, r3);
    lv.x = hpk2(r0, r1);
    lv.y = hpk2(r2, r3);
    ((uint2*)hi)[i] = hv;
    ((uint2*)lo)[i] = lv;
}

// ---------------- fp32 -> fp16 convert (weights) ----------------
__global__ void conv_kernel(const float* __restrict__ in, __half* __restrict__ out, int n4)
{
    int i = blockIdx.x * blockDim.x + threadIdx.x;
    if (i >= n4) return;
    float4 a = ((const float4*)in)[i];
    uint2 hv;
    hv.x = hpk2(a.x, a.y);
    hv.y = hpk2(a.z, a.w);
    ((uint2*)out)[i] = hv;
}

// ---------------- mma.sync GEMM: fp16 2-pass (A split, W single), 3-stage cp.async ----------------
#define GM_STRIDE 72
#define GM_ARRB   (128*GM_STRIDE*2)           // 18432 B per array
#define GM_STAGE  (3*GM_ARRB)                 // 55296 B per stage (Ah, Al, Wh)
#define GM_SMEM   (3*GM_STAGE)                // 165888 B

__global__ __launch_bounds__(256) void gemm_mma_kernel(
    const __half* __restrict__ Ahi, const __half* __restrict__ Alo,
    const __half* __restrict__ Wh,
    const float* __restrict__ bias,
    float* __restrict__ Cf,
    __half* __restrict__ Chi, __half* __restrict__ Clo,
    int N, int K)
{
    extern __shared__ char smem[];
    const uint32_t sb = smem_u32(smem);

    const int tid  = threadIdx.x;
    const int lane = tid & 31, wid = tid >> 5;
    const int wm = wid & 1, wn = wid >> 1;
    const int n0 = blockIdx.x << 7, m0 = blockIdx.y << 7;

    float acc[4][4][4];
#pragma unroll
    for (int mt = 0; mt < 4; mt++)
#pragma unroll
        for (int nt = 0; nt < 4; nt++)
#pragma unroll
            for (int q = 0; q < 4; q++) acc[mt][nt][q] = 0.f;

    const int sr = tid >> 3, sc = (tid & 7) << 3;
    const int lrow = lane & 15;
    const int lk8  = (lane >> 4) << 3;
    const int brow = lane & 7;
    const int bk8  = ((lane >> 3) & 1) << 3;

    const uint32_t aOffH = (uint32_t)(wm*64 + lrow)*144 + (uint32_t)lk8*2;
    const uint32_t bOffH = 2u*GM_ARRB + (uint32_t)(wn*32 + brow)*144 + (uint32_t)bk8*2;

    const int nch = K >> 6;

    // ---- prologue: stage chunks 0,1 ----
#pragma unroll
    for (int pc = 0; pc < 2; pc++) {
        if (pc < nch) {
            const int kk = pc << 6;
            const uint32_t st = sb + (uint32_t)pc*GM_STAGE;
#pragma unroll
            for (int i = 0; i < 4; i++) {
                int r = sr + i*32;
                uint32_t d = st + (uint32_t)(r*GM_STRIDE + sc)*2;
                size_t ga = (size_t)(m0 + r) * K + kk + sc;
                size_t gb = (size_t)(n0 + r) * K + kk + sc;
                CP16(d,              Ahi + ga);
                CP16(d + GM_ARRB,    Alo + ga);
                CP16(d + 2u*GM_ARRB, Wh  + gb);
            }
            CP_COMMIT();
        }
    }

    int s = 0, s2 = 2;
    for (int ch = 0; ch < nch; ch++) {
        if (ch + 2 < nch) {
            const int kk = (ch + 2) << 6;
            const uint32_t st = sb + (uint32_t)s2*GM_STAGE;
#pragma unroll
            for (int i = 0; i < 4; i++) {
                int r = sr + i*32;
                uint32_t d = st + (uint32_t)(r*GM_STRIDE + sc)*2;
                size_t ga = (size_t)(m0 + r) * K + kk + sc;
                size_t gb = (size_t)(n0 + r) * K + kk + sc;
                CP16(d,              Ahi + ga);
                CP16(d + GM_ARRB,    Alo + ga);
                CP16(d + 2u*GM_ARRB, Wh  + gb);
            }
            CP_COMMIT();
            CP_WAIT2();
        } else if (ch + 1 < nch) {
            CP_WAIT1();
        } else {
            CP_WAIT0();
        }
        __syncthreads();

        const uint32_t aBaseH = sb + (uint32_t)s*GM_STAGE + aOffH;
        const uint32_t aBaseL = aBaseH + GM_ARRB;
        const uint32_t bBaseH = sb + (uint32_t)s*GM_STAGE + bOffH;

#pragma unroll
        for (int ks = 0; ks < 4; ks++) {
            const uint32_t koff = (uint32_t)ks * 32;
            uint32_t bhf[4][2];
#pragma unroll
            for (int nt = 0; nt < 4; nt++)
                LDSM2(bhf[nt][0], bhf[nt][1], bBaseH + (uint32_t)nt*1152 + koff);
#pragma unroll
            for (int mt = 0; mt < 4; mt++) {
                uint32_t ahf[4], alf[4];
                LDSM4(ahf[0], ahf[1], ahf[2], ahf[3], aBaseH + (uint32_t)mt*2304 + koff);
                LDSM4(alf[0], alf[1], alf[2], alf[3], aBaseL + (uint32_t)mt*2304 + koff);
#pragma unroll
                for (int nt = 0; nt < 4; nt++) {
                    MMA16816(acc[mt][nt], ahf, bhf[nt]);
                    MMA16816(acc[mt][nt], alf, bhf[nt]);
                }
            }
        }
        __syncthreads();
        s  = (s  == 2) ? 0 : s  + 1;
        s2 = (s2 == 2) ? 0 : s2 + 1;
    }

    const int g = lane >> 2, tg = lane & 3;
#pragma unroll
    for (int mt = 0; mt < 4; mt++) {
#pragma unroll
        for (int nt = 0; nt < 4; nt++) {
            int n   = n0 + wn*32 + nt*8 + tg*2;
            int mA  = m0 + wm*64 + mt*16 + g;
            int mB  = mA + 8;
            float b0v = bias[n], b1v = bias[n+1];
            float f0 = acc[mt][nt][0] + b0v, f1 = acc[mt][nt][1] + b1v;
            float f2 = acc[mt][nt][2] + b0v, f3 = acc[mt][nt][3] + b1v;
            if (Cf) {
                *(float2*)(Cf + (size_t)mA * N + n) = make_float2(f0, f1);
                *(float2*)(Cf + (size_t)mB * N + n) = make_float2(f2, f3);
            } else if (Clo) {
                float r0, r1, r2, r3;
                uint32_t hv0 = hpk2hi(f0, f1, r0, r1);
                uint32_t hv1 = hpk2hi(f2, f3, r2, r3);
                *(uint32_t*)(Chi + (size_t)mA * N + n) = hv0;
                *(uint32_t*)(Chi + (size_t)mB * N + n) = hv1;
                *(uint32_t*)(Clo + (size_t)mA * N + n) = hpk2(r0, r1);
                *(uint32_t*)(Clo + (size_t)mB * N + n) = hpk2(r2, r3);
            } else {
                *(uint32_t*)(Chi + (size_t)mA * N + n) = hpk2(f0, f1);
                *(uint32_t*)(Chi + (size_t)mB * N + n) = hpk2(f2, f3);
            }
        }
    }
}

// ---------------- RoPE fused with fp16 hi/lo split (lo optional) ----------------
__global__ void rope_split_kernel(const float* __restrict__ t,
                                  __half* __restrict__ hi,
                                  __half* __restrict__ lo, int total)
{
    int idx = blockIdx.x * blockDim.x + threadIdx.x;
    if (idx >= total) return;
    int j   = idx & 31;
    int rem = idx >> 5;
    int bs  = rem >> 4;
    int s   = bs & (Sn - 1);
    float inv_freq = 1.0f / powf(10000.0f, (float)(2 * j) / (float)DRn);
    float ang = (float)s * inv_freq;
    float sv, cv;
    sincosf(ang, &sv, &cv);
    const float* p = t + (size_t)rem * DRn;
    float t1 = p[j], t2 = p[j + 32];
    float o1 = t1 * cv - t2 * sv;
    float o2 = t2 * cv + t1 * sv;
    __half h1 = __float2half_rn(o1), h2 = __float2half_rn(o2);
    size_t base = (size_t)rem * DRn;
    hi[base + j] = h1; hi[base + j + 32] = h2;
    if (lo) {
        lo[base + j]      = __float2half_rn(o1 - __half2float(h1));
        lo[base + j + 32] = __float2half_rn(o2 - __half2float(h2));
    }
}

// ---------------- tensor-core causal flash attention (fp16, Q split, K/V single, dbl-buffered) ----------------
#define SQH 0
#define SQL 51200
#define SK0 102400
#define SK1 128000
#define SV0 153600
#define SV1 171008
#define ATTN_SMEM 188416

__global__ __launch_bounds__(256) void attn_mma_kernel(
    const __half* __restrict__ quh, const __half* __restrict__ qul,
    const __half* __restrict__ qrh, const __half* __restrict__ qrl,
    const __half* __restrict__ kch, const __half* __restrict__ krh,
    const __half* __restrict__ vh,
    __half* __restrict__ ohi, __half* __restrict__ olo)
{
    extern __shared__ char smraw[];
    const uint32_t sb = smem_u32(smraw);

    const int tid  = threadIdx.x;
    const int lane = tid & 31, w = tid >> 5;
    const int b  = blockIdx.x >> 4;
    const int h  = blockIdx.x & 15;
    const int qb = (gridDim.y - 1) - blockIdx.y;
    const int q0 = qb * 128;
    const float scale = rsqrtf((float)(DHn + DRn));
    const int g = lane >> 2, tg = lane & 3;

    // ---- stage Q hi/lo + K(0) + V(0) (one group) ----
    for (int i = tid; i < 3072; i += 256) {
        int r = i / 24, c = i % 24;
        size_t m = (size_t)(b*Sn + q0 + r);
        const __half *ph, *pl;
        if (c < 16) { size_t off = m*(Hn*DHn) + h*DHn + c*8;       ph = quh + off; pl = qul + off; }
        else        { size_t off = m*(Hn*DRn) + h*DRn + (c-16)*8;  ph = qrh + off; pl = qrl + off; }
        uint32_t d = (uint32_t)(r*200 + c*8)*2;
        CP16(sb + SQH + d, ph);
        CP16(sb + SQL + d, pl);
    }
    for (int i = tid; i < 1536; i += 256) {
        int r = i / 24, c = i % 24;
        size_t m = (size_t)(b*Sn + r);
        const __half* ph;
        if (c < 16) ph = kch + m*(Hn*DHn) + h*DHn + c*8;
        else        ph = krh + m*(Hn*DRn) + h*DRn + (c-16)*8;
        CP16(sb + SK0 + (uint32_t)(r*200 + c*8)*2, ph);
    }
    for (int i = tid; i < 1024; i += 256) {
        int r = i >> 4, c = i & 15;
        CP16(sb + SV0 + (uint32_t)(r*136 + c*8)*2,
             vh + (size_t)(b*Sn + r)*(Hn*DHn) + h*DHn + c*8);
    }
    CP_COMMIT();

    float o[16][4];
#pragma unroll
    for (int nf = 0; nf < 16; nf++)
#pragma unroll
        for (int q = 0; q < 4; q++) o[nf][q] = 0.f;
    float mst0 = -1e30f, mst1 = -1e30f, lst0 = 0.f, lst1 = 0.f;

    const uint32_t aQhB = sb + SQH + (uint32_t)(w*16 + (lane & 15))*400 + (uint32_t)((lane >> 4) & 1)*16;
    const uint32_t aQlB = aQhB + (SQL - SQH);
    const uint32_t kLaneOff = (uint32_t)((lane & 7) + ((lane & 16) >> 1))*400 + (uint32_t)(lane & 8)*2;
    const uint32_t vLaneOff = (uint32_t)(lane & 15)*272 + (uint32_t)((lane >> 4) << 4);

    const int kb_end = 2*qb + 1;
    for (int kb = 0; kb <= kb_end; kb++) {
        const int k0 = kb * 64;
        CP_WAIT0();          // data for tile kb (and Q on kb=0) complete
        __syncthreads();     // all threads finished reading previous tile's buffers

        // ---- prefetch K(kb+1) + V(kb+1) into other buffers; overlaps whole tile ----
        if (kb + 1 <= kb_end) {
            const int k1 = (kb + 1) * 64;
            const uint32_t sk = ((kb + 1) & 1) ? SK1 : SK0;
            const uint32_t sv = ((kb + 1) & 1) ? SV1 : SV0;
            for (int i = tid; i < 1536; i += 256) {
                int r = i / 24, c = i % 24;
                size_t m = (size_t)(b*Sn + k1 + r);
                const __half* ph;
                if (c < 16) ph = kch + m*(Hn*DHn) + h*DHn + c*8;
                else        ph = krh + m*(Hn*DRn) + h*DRn + (c-16)*8;
                CP16(sb + sk + (uint32_t)(r*200 + c*8)*2, ph);
            }
            for (int i = tid; i < 1024; i += 256) {
                int r = i >> 4, c = i & 15;
                CP16(sb + sv + (uint32_t)(r*136 + c*8)*2,
                     vh + (size_t)(b*Sn + k1 + r)*(Hn*DHn) + h*DHn + c*8);
            }
            CP_COMMIT();
        }

        const uint32_t bKB = sb + ((kb & 1) ? SK1 : SK0) + kLaneOff;
        const uint32_t vB  = sb + ((kb & 1) ? SV1 : SV0) + vLaneOff;

        // ---- S = Q K^T (2-pass: Qhi K + Qlo K) ----
        float s[8][4];
#pragma unroll
        for (int nt = 0; nt < 8; nt++)
#pragma unroll
            for (int q = 0; q < 4; q++) s[nt][q] = 0.f;

        for (int kc = 0; kc < 12; kc++) {
            uint32_t qh4[4], ql4[4];
            LDSM4(qh4[0], qh4[1], qh4[2], qh4[3], aQhB + (uint32_t)kc*32);
            LDSM4(ql4[0], ql4[1], ql4[2], ql4[3], aQlB + (uint32_t)kc*32);
#pragma unroll
            for (int np = 0; np < 4; np++) {
                uint32_t kh4[4];
                LDSM4(kh4[0], kh4[1], kh4[2], kh4[3], bKB + (uint32_t)np*6400 + (uint32_t)kc*32);
                uint32_t bh0[2] = {kh4[0], kh4[1]}, bh1[2] = {kh4[2], kh4[3]};
                MMA16816(s[2*np],   qh4, bh0); MMA16816(s[2*np],   ql4, bh0);
                MMA16816(s[2*np+1], qh4, bh1); MMA16816(s[2*np+1], ql4, bh1);
            }
        }

        // ---- scale + causal mask ----
#pragma unroll
        for (int nt = 0; nt < 8; nt++)
#pragma unroll
            for (int q = 0; q < 4; q++) s[nt][q] *= scale;
        if (k0 + 63 > q0) {
            int rg = q0 + w*16 + g;
#pragma unroll
            for (int nt = 0; nt < 8; nt++)
#pragma unroll
                for (int q = 0; q < 2; q++) {
                    int col = k0 + nt*8 + tg*2 + q;
                    if (col > rg)     s[nt][q]     = -1e9f;
                    if (col > rg + 8) s[nt][q + 2] = -1e9f;
                }
        }

        // ---- online softmax ----
        float mg = -1e30f, mh = -1e30f;
#pragma unroll
        for (int nt = 0; nt < 8; nt++) {
            mg = fmaxf(mg, fmaxf(s[nt][0], s[nt][1]));
            mh = fmaxf(mh, fmaxf(s[nt][2], s[nt][3]));
        }
        mg = fmaxf(mg, __shfl_xor_sync(0xffffffffu, mg, 1));
        mg = fmaxf(mg, __shfl_xor_sync(0xffffffffu, mg, 2));
        mh = fmaxf(mh, __shfl_xor_sync(0xffffffffu, mh, 1));
        mh = fmaxf(mh, __shfl_xor_sync(0xffffffffu, mh, 2));
        float mng = fmaxf(mst0, mg), mnh = fmaxf(mst1, mh);
        float alg = __expf(mst0 - mng), alh = __expf(mst1 - mnh);
        float rsg = 0.f, rsh = 0.f;
#pragma unroll
        for (int nt = 0; nt < 8; nt++) {
            s[nt][0] = __expf(s[nt][0] - mng); rsg += s[nt][0];
            s[nt][1] = __expf(s[nt][1] - mng); rsg += s[nt][1];
            s[nt][2] = __expf(s[nt][2] - mnh); rsh += s[nt][2];
            s[nt][3] = __expf(s[nt][3] - mnh); rsh += s[nt][3];
        }
        rsg += __shfl_xor_sync(0xffffffffu, rsg, 1);
        rsg += __shfl_xor_sync(0xffffffffu, rsg, 2);
        rsh += __shfl_xor_sync(0xffffffffu, rsh, 1);
        rsh += __shfl_xor_sync(0xffffffffu, rsh, 2);
        lst0 = lst0 * alg + rsg; mst0 = mng;
        lst1 = lst1 * alh + rsh; mst1 = mnh;
#pragma unroll
        for (int nf = 0; nf < 16; nf++) {
            o[nf][0] *= alg; o[nf][1] *= alg;
            o[nf][2] *= alh; o[nf][3] *= alh;
        }

        // ---- pack P into A-frags (fp16 hi/lo) ----
        uint32_t pah[4][4], pal[4][4];
#pragma unroll
        for (int kcp = 0; kcp < 4; kcp++) {
            float r0, r1, r2, r3, r4, r5, r6, r7;
            pah[kcp][0] = hpk2hi(s[2*kcp][0],   s[2*kcp][1],   r0, r1);
            pah[kcp][1] = hpk2hi(s[2*kcp][2],   s[2*kcp][3],   r2, r3);
            pah[kcp][2] = hpk2hi(s[2*kcp+1][0], s[2*kcp+1][1], r4, r5);
            pah[kcp][3] = hpk2hi(s[2*kcp+1][2], s[2*kcp+1][3], r6, r7);
            pal[kcp][0] = hpk2(r0, r1);
            pal[kcp][1] = hpk2(r2, r3);
            pal[kcp][2] = hpk2(r4, r5);
            pal[kcp][3] = hpk2(r6, r7);
        }

        // ---- O += P V (2-pass: Phi V + Plo V) ----
#pragma unroll
        for (int kcp = 0; kcp < 4; kcp++) {
            uint32_t koff = (uint32_t)kcp * 4352;
#pragma unroll
            for (int nq = 0; nq < 8; nq++) {
                uint32_t vh4[4];
                LDSM4T(vh4[0], vh4[1], vh4[2], vh4[3], vB + koff + (uint32_t)nq*32);
                uint32_t bh0[2] = {vh4[0], vh4[1]}, bh1[2] = {vh4[2], vh4[3]};
                MMA16816(o[2*nq],   pah[kcp], bh0); MMA16816(o[2*nq],   pal[kcp], bh0);
                MMA16816(o[2*nq+1], pah[kcp], bh1); MMA16816(o[2*nq+1], pal[kcp], bh1);
            }
        }
    }

    // ---- epilogue: write split hi/lo directly ----
    float ig = 1.f / lst0, ih = 1.f / lst1;
    int rgl = q0 + w*16 + g;
    size_t offg = (size_t)(b*Sn + rgl    )*(Hn*DHn) + h*DHn + tg*2;
    size_t offh = (size_t)(b*Sn + rgl + 8)*(Hn*DHn) + h*DHn + tg*2;
#pragma unroll
    for (int nf = 0; nf < 16; nf++) {
        float f0 = o[nf][0]*ig, f1 = o[nf][1]*ig;
        float f2 = o[nf][2]*ih, f3 = o[nf][3]*ih;
        float r0, r1, r2, r3;
        uint32_t hv0 = hpk2hi(f0, f1, r0, r1);
        uint32_t hv1 = hpk2hi(f2, f3, r2, r3);
        *(uint32_t*)(ohi + offg + nf*8) = hv0;
        *(uint32_t*)(olo + offg + nf*8) = hpk2(r0, r1);
        *(uint32_t*)(ohi + offh + nf*8) = hv1;
        *(uint32_t*)(olo + offh + nf*8) = hpk2(r2, r3);
    }
}

// ---------------- launch ----------------
static void run_split(const float* in, __half* hi, __half* lo, size_t n) {
    int n4 = (int)(n >> 2);
    split_kernel<<<(n4 + 255) / 256, 256>>>(in, hi, lo, n4);
}
static void run_conv(const float* in, __half* out, size_t n) {
    int n4 = (int)(n >> 2);
    conv_kernel<<<(n4 + 255) / 256, 256>>>(in, out, n4);
}

extern "C" void kernel_launch(void* const* d_in, const int* in_sizes, int n_in,
                              void* d_out, int out_size)
{
    const float* x   = (const float*)d_in[0];
    const float* Wkd = (const float*)d_in[1];
    const float* bkd = (const float*)d_in[2];
    const float* Wqd = (const float*)d_in[3];
    const float* bqd = (const float*)d_in[4];
    const float* Wku = (const float*)d_in[5];
    const float* bku = (const float*)d_in[6];
    const float* Wvu = (const float*)d_in[7];
    const float* bvu = (const float*)d_in[8];
    const float* Wqu = (const float*)d_in[9];
    const float* bqu = (const float*)d_in[10];
    const float* Wkr = (const float*)d_in[11];
    const float* bkr = (const float*)d_in[12];
    const float* Wqr = (const float*)d_in[13];
    const float* bqr = (const float*)d_in[14];
    const float* Wo  = (const float*)d_in[15];
    const float* bo  = (const float*)d_in[16];

    float *kr, *qr;
    cudaGetSymbolAddress((void**)&kr, g_kr);
    cudaGetSymbolAddress((void**)&qr, g_qr);

    __half *x_hi, *x_lo, *kvc_hi, *kvc_lo, *qc_hi, *qc_lo, *at_hi, *at_lo;
    __half *qu_hi, *qu_lo, *qrs_hi, *qrs_lo, *kc_h, *v_h, *krs_h;
    cudaGetSymbolAddress((void**)&x_hi,   g_x_hi);   cudaGetSymbolAddress((void**)&x_lo,   g_x_lo);
    cudaGetSymbolAddress((void**)&kvc_hi, g_kvc_hi); cudaGetSymbolAddress((void**)&kvc_lo, g_kvc_lo);
    cudaGetSymbolAddress((void**)&qc_hi,  g_qc_hi);  cudaGetSymbolAddress((void**)&qc_lo,  g_qc_lo);
    cudaGetSymbolAddress((void**)&at_hi,  g_at_hi);  cudaGetSymbolAddress((void**)&at_lo,  g_at_lo);
    cudaGetSymbolAddress((void**)&qu_hi,  g_qu_hi);  cudaGetSymbolAddress((void**)&qu_lo,  g_qu_lo);
    cudaGetSymbolAddress((void**)&qrs_hi, g_qrs_hi); cudaGetSymbolAddress((void**)&qrs_lo, g_qrs_lo);
    cudaGetSymbolAddress((void**)&kc_h,   g_kc_h);
    cudaGetSymbolAddress((void**)&v_h,    g_v_h);
    cudaGetSymbolAddress((void**)&krs_h,  g_krs_h);

    __half *Wkd_h,*Wqd_h,*Wku_h,*Wvu_h,*Wqu_h,*Wkr_h,*Wqr_h,*Wo_h;
    cudaGetSymbolAddress((void**)&Wkd_h, g_Wkd_h);
    cudaGetSymbolAddress((void**)&Wqd_h, g_Wqd_h);
    cudaGetSymbolAddress((void**)&Wku_h, g_Wku_h);
    cudaGetSymbolAddress((void**)&Wvu_h, g_Wvu_h);
    cudaGetSymbolAddress((void**)&Wqu_h, g_Wqu_h);
    cudaGetSymbolAddress((void**)&Wkr_h, g_Wkr_h);
    cudaGetSymbolAddress((void**)&Wqr_h, g_Wqr_h);
    cudaGetSymbolAddress((void**)&Wo_h,  g_Wo_h);

    // ---- convert inputs ----
    run_split(x, x_hi, x_lo, (size_t)Mn*Dn);
    run_conv(Wkd, Wkd_h, (size_t)DCKVn*Dn);
    run_conv(Wqd, Wqd_h, (size_t)DCQn*Dn);
    run_conv(Wku, Wku_h, (size_t)Hn*DHn*DCKVn);
    run_conv(Wvu, Wvu_h, (size_t)Hn*DHn*DCKVn);
    run_conv(Wqu, Wqu_h, (size_t)Hn*DHn*DCQn);
    run_conv(Wkr, Wkr_h, (size_t)Hn*DRn*Dn);
    run_conv(Wqr, Wqr_h, (size_t)Hn*DRn*DCQn);
    run_conv(Wo,  Wo_h,  (size_t)Dn*Hn*DHn);

    cudaFuncSetAttribute(gemm_mma_kernel, cudaFuncAttributeMaxDynamicSharedMemorySize, GM_SMEM);
    dim3 thr(256);

    // ---- compress (A-split outputs) ----
    gemm_mma_kernel<<<dim3(DCKVn/128, Mn/128), thr, GM_SMEM>>>(
        x_hi, x_lo, Wkd_h, bkd, nullptr, kvc_hi, kvc_lo, DCKVn, Dn);
    gemm_mma_kernel<<<dim3(DCQn/128, Mn/128), thr, GM_SMEM>>>(
        x_hi, x_lo, Wqd_h, bqd, nullptr, qc_hi, qc_lo, DCQn, Dn);
    // ---- up-project ----
    gemm_mma_kernel<<<dim3((Hn*DHn)/128, Mn/128), thr, GM_SMEM>>>(
        kvc_hi, kvc_lo, Wku_h, bku, nullptr, kc_h, nullptr, Hn*DHn, DCKVn);   // K content: hi only
    gemm_mma_kernel<<<dim3((Hn*DHn)/128, Mn/128), thr, GM_SMEM>>>(
        kvc_hi, kvc_lo, Wvu_h, bvu, nullptr, v_h, nullptr, Hn*DHn, DCKVn);    // V: hi only
    gemm_mma_kernel<<<dim3((Hn*DHn)/128, Mn/128), thr, GM_SMEM>>>(
        qc_hi, qc_lo, Wqu_h, bqu, nullptr, qu_hi, qu_lo, Hn*DHn, DCQn);       // Q content: split
    gemm_mma_kernel<<<dim3((Hn*DRn)/128, Mn/128), thr, GM_SMEM>>>(
        x_hi, x_lo, Wkr_h, bkr, kr, nullptr, nullptr, Hn*DRn, Dn);            // K rope: fp32 (pre-rope)
    gemm_mma_kernel<<<dim3((Hn*DRn)/128, Mn/128), thr, GM_SMEM>>>(
        qc_hi, qc_lo, Wqr_h, bqr, qr, nullptr, nullptr, Hn*DRn, DCQn);        // Q rope: fp32 (pre-rope)

    // ---- rope + split (fused; K rope hi-only) ----
    int rope_total = Mn * Hn * (DRn / 2);
    rope_split_kernel<<<(rope_total + 255) / 256, 256>>>(kr, krs_h, nullptr, rope_total);
    rope_split_kernel<<<(rope_total + 255) / 256, 256>>>(qr, qrs_hi, qrs_lo, rope_total);

    // ---- attention ----
    cudaFuncSetAttribute(attn_mma_kernel, cudaFuncAttributeMaxDynamicSharedMemorySize, ATTN_SMEM);
    attn_mma_kernel<<<dim3(Bn*Hn, Sn/128), thr, ATTN_SMEM>>>(
        qu_hi, qu_lo, qrs_hi, qrs_lo, kc_h, krs_h, v_h, at_hi, at_lo);

    // ---- output projection ----
    gemm_mma_kernel<<<dim3(Dn/128, Mn/128), thr, GM_SMEM>>>(
        at_hi, at_lo, Wo_h, bo, (float*)d_out, nullptr, nullptr, Dn, Hn*DHn);
}